// round 2
// baseline (speedup 1.0000x reference)
#include <cuda_runtime.h>
#include <math.h>

#define Nn 32
#define Cc 96
#define Tt 256
#define Vv 25
#define Ss 3
#define RELr 12
#define OUTo 96
#define BCc 24
#define TV (Tt*Vv)   // 6400

// ---------------- scratch (static device globals; no runtime alloc) ----------
__device__ float g_xm[Nn*Cc*Vv];                        // [n][c][v]
__device__ float g_A [(size_t)Nn*Ss*OUTo*Vv*Vv];        // [(n*3+s)*96+o][u*25+v]
__device__ float g_x3[(size_t)Nn*Ss*OUTo*TV];           // [(n*3+s)*96+o][t*25+v]
__device__ float g_y [(size_t)Nn*OUTo*TV];              // [n][o][t][v]
__device__ float g_H0[(size_t)Nn*BCc*TV];
__device__ float g_H1[(size_t)Nn*BCc*TV];
__device__ float g_H2[(size_t)Nn*BCc*TV];

// ---------------- K1: mean over T --------------------------------------------
__global__ void k_xm(const float* __restrict__ x) {
    int nc = blockIdx.x;                       // 0..N*C-1
    const float* xp = x + (size_t)nc * TV;
    float acc[Vv];
#pragma unroll
    for (int v = 0; v < Vv; v++) acc[v] = 0.f;
    for (int t = threadIdx.x; t < Tt; t += 128) {
        const float* row = xp + t * Vv;
#pragma unroll
        for (int v = 0; v < Vv; v++) acc[v] += row[v];
    }
    __shared__ float s[Vv][128];
#pragma unroll
    for (int v = 0; v < Vv; v++) s[v][threadIdx.x] = acc[v];
    __syncthreads();
    if (threadIdx.x < Vv) {
        float r = 0.f;
#pragma unroll 8
        for (int i = 0; i < 128; i++) r += s[threadIdx.x][i];
        g_xm[nc * Vv + threadIdx.x] = r * (1.f / Tt);
    }
}

// ---------------- K2: CTRGC relation -> A_at ---------------------------------
__global__ void k_rel(const float* __restrict__ spd, const float* __restrict__ A3,
                      const float* __restrict__ A6,
                      const float* __restrict__ alpha, const float* __restrict__ beta,
                      const float* __restrict__ gamma,
                      const float* __restrict__ c1w, const float* __restrict__ c1b,
                      const float* __restrict__ c2w, const float* __restrict__ c2b,
                      const float* __restrict__ c4w, const float* __restrict__ c4b) {
    int n = blockIdx.x / Ss, s = blockIdx.x % Ss;
    int tid = threadIdx.x;
    __shared__ float xm_s[Cc * Vv];           // 2400
    __shared__ float x1s[RELr * Vv];          // 300
    __shared__ float x2s[RELr * Vv];          // 300
    __shared__ float Rs[RELr * Vv * Vv];      // 7500
    __shared__ float base_s[Vv * Vv];         // 625

    for (int i = tid; i < Cc * Vv; i += 256) xm_s[i] = g_xm[n * Cc * Vv + i];
    __syncthreads();

    for (int i = tid; i < 2 * RELr * Vv; i += 256) {
        int which = i / (RELr * Vv);
        int rv = i % (RELr * Vv);
        int r = rv / Vv, v = rv % Vv;
        const float* w = (which ? c2w : c1w) + (s * RELr + r) * Cc;
        float acc = (which ? c2b : c1b)[s * RELr + r];
#pragma unroll 8
        for (int c = 0; c < Cc; c++) acc += w[c] * xm_s[c * Vv + v];
        (which ? x2s : x1s)[rv] = acc;
    }
    __syncthreads();

    float ga = __ldg(gamma);
    for (int i = tid; i < RELr * Vv * Vv; i += 256) {
        int r = i / (Vv * Vv);
        int uv = i % (Vv * Vv);
        int u = uv / Vv, v = uv % Vv;
        Rs[i] = tanhf(x1s[r * Vv + u] - x2s[r * Vv + v]);
    }
    for (int i = tid; i < Vv * Vv; i += 256)
        base_s[i] = __ldg(&A3[s * 625 + i]) + __ldg(&spd[i]) * ga;
    __syncthreads();

    float al = __ldg(alpha), be = __ldg(beta);
    float* Aout = g_A + (size_t)(n * Ss + s) * OUTo * 625;
    for (int o = 0; o < OUTo; o++) {
        float w4[RELr];
#pragma unroll
        for (int r = 0; r < RELr; r++) w4[r] = __ldg(&c4w[(s * OUTo + o) * RELr + r]);
        float b4 = __ldg(&c4b[s * OUTo + o]);
        const float* A6o = A6 + (o % 6) * 625;
        for (int i = tid; i < 625; i += 256) {
            float m = b4;
#pragma unroll
            for (int r = 0; r < RELr; r++) m += w4[r] * Rs[r * 625 + i];
            Aout[(size_t)o * 625 + i] = m * al + base_s[i] + __ldg(&A6o[i]) * be;
        }
    }
}

// ---------------- GEMM core: 96 rows x 128 cols, K=96, chunked 32 ------------
// thread tile 6 rows x 8 cols; blockDim 256 (ty=tid>>4 in [0,16), tx=tid&15)
// EPI==0: X = xglob (harness input x), write x3 to g_x3.
// EPI==1: X = g_y (device scratch, referenced from device code!), epilogue
//         does the 4 pointwise branches.
template <int EPI>
__global__ void k_gemm96(const float* __restrict__ Wfull,   // [rows][96]
                         const float* __restrict__ xglob,   // x (EPI==0) / residual x (EPI==1)
                         const float* __restrict__ bias,
                         const float* __restrict__ bn_s, const float* __restrict__ bn_b,
                         float* __restrict__ outbuf)        // d_out (EPI==1)
{
    int ct = blockIdx.x;                 // col tile (0..49)
    int s  = blockIdx.y;                 // s index (EPI==0) else 0
    int n  = blockIdx.z;
    int tid = threadIdx.x;
    int tx = tid & 15, ty = tid >> 4;

    const float* W = Wfull + (size_t)s * 96 * 96;
    const float* Xin = (EPI == 0) ? xglob : (const float*)g_y;
    const float* X = Xin + (size_t)n * Cc * TV + (size_t)ct * 128;

    __shared__ float Ws[32 * 97];
    __shared__ float Xs[32 * 128];

    float acc[6][8];
#pragma unroll
    for (int i = 0; i < 6; i++)
#pragma unroll
        for (int j = 0; j < 8; j++) acc[i][j] = 0.f;

    for (int k0 = 0; k0 < 96; k0 += 32) {
        __syncthreads();
        for (int i = tid; i < 96 * 32; i += 256) {
            int r = i >> 5, kk = i & 31;
            Ws[kk * 97 + r] = W[r * 96 + k0 + kk];
        }
        for (int i4 = tid; i4 < 1024; i4 += 256) {
            int kk = i4 >> 5;
            int c4 = (i4 & 31) << 2;
            *(float4*)&Xs[kk * 128 + c4] =
                *(const float4*)&X[(size_t)(k0 + kk) * TV + c4];
        }
        __syncthreads();
#pragma unroll
        for (int kk = 0; kk < 32; kk++) {
            float a[6];
#pragma unroll
            for (int i = 0; i < 6; i++) a[i] = Ws[kk * 97 + ty * 6 + i];
            float4 b0 = *(float4*)&Xs[kk * 128 + tx * 8];
            float4 b1 = *(float4*)&Xs[kk * 128 + tx * 8 + 4];
            float bb[8] = {b0.x, b0.y, b0.z, b0.w, b1.x, b1.y, b1.z, b1.w};
#pragma unroll
            for (int i = 0; i < 6; i++)
#pragma unroll
                for (int j = 0; j < 8; j++) acc[i][j] += a[i] * bb[j];
        }
    }

    if (EPI == 0) {
        // x3 = W@x + c3_b  -> g_x3
        float* O = g_x3 + (size_t)(n * Ss + s) * 96 * TV + (size_t)ct * 128;
#pragma unroll
        for (int i = 0; i < 6; i++) {
            int r = ty * 6 + i;
            float bv = __ldg(&bias[s * 96 + r]);
            float4 o0 = {acc[i][0] + bv, acc[i][1] + bv, acc[i][2] + bv, acc[i][3] + bv};
            float4 o1 = {acc[i][4] + bv, acc[i][5] + bv, acc[i][6] + bv, acc[i][7] + bv};
            *(float4*)&O[(size_t)r * TV + tx * 8]     = o0;
            *(float4*)&O[(size_t)r * TV + tx * 8 + 4] = o1;
        }
    } else {
        // pointwise convs: rows = 4 branches * 24 channels
#pragma unroll
        for (int i = 0; i < 6; i++) {
            int r = ty * 6 + i;
            int br = r / 24, bc = r % 24;
            float bv = __ldg(&bias[r]);
            float sc = __ldg(&bn_s[r]), sh = __ldg(&bn_b[r]);
            int colg = ct * 128 + tx * 8;
#pragma unroll
            for (int j = 0; j < 8; j++) {
                float v = acc[i][j] + bv;
                v = v * sc + sh;
                if (br < 3) v = fmaxf(v, 0.f);
                size_t hidx = (size_t)(n * BCc + bc) * TV + colg + j;
                if (br == 0)      g_H0[hidx] = v;
                else if (br == 1) g_H1[hidx] = v;
                else if (br == 2) g_H2[hidx] = v;
                else {
                    size_t oi = ((size_t)n * OUTo + 72 + bc) * TV + colg + j;
                    outbuf[oi] = fmaxf(v + __ldg(&xglob[oi]), 0.f);
                }
            }
        }
    }
}

// ---------------- K4: y = relu(bn(sum_s A_s @ x3_s) + x) ----------------------
__global__ void k_y(const float* __restrict__ x, const float* __restrict__ gbn_s,
                    const float* __restrict__ gbn_b) {
    int no = blockIdx.x;
    int n = no / OUTo, o = no % OUTo;
    int t = threadIdx.x;       // 256 threads = T
    __shared__ float As[Ss * 625];
    for (int i = t; i < Ss * 625; i += 256) {
        int s = i / 625;
        As[i] = g_A[((size_t)(n * Ss + s) * OUTo + o) * 625 + (i % 625)];
    }
    __syncthreads();

    float acc[Vv];
#pragma unroll
    for (int u = 0; u < Vv; u++) acc[u] = 0.f;

#pragma unroll
    for (int s = 0; s < Ss; s++) {
        const float* xr = g_x3 + ((size_t)(n * Ss + s) * OUTo + o) * TV + t * Vv;
        float xv[Vv];
#pragma unroll
        for (int v = 0; v < Vv; v++) xv[v] = xr[v];
        const float* Ar = As + s * 625;
#pragma unroll
        for (int u = 0; u < Vv; u++) {
            float a = acc[u];
#pragma unroll
            for (int v = 0; v < Vv; v++) a += Ar[u * Vv + v] * xv[v];
            acc[u] = a;
        }
    }
    float gs = __ldg(&gbn_s[o]), gb = __ldg(&gbn_b[o]);
    float* yo = g_y + ((size_t)n * OUTo + o) * TV + t * Vv;
    const float* xo = x + ((size_t)n * OUTo + o) * TV + t * Vv;
#pragma unroll
    for (int u = 0; u < Vv; u++) yo[u] = fmaxf(acc[u] * gs + gb + xo[u], 0.f);
}

// ---------------- K6: dilated temporal conv (branches 0/1) -------------------
template <int D>
__global__ void k_tc(const float* __restrict__ tcw, const float* __restrict__ tcb,
                     const float* __restrict__ tcbn_s, const float* __restrict__ tcbn_b,
                     const float* __restrict__ x, float* __restrict__ out) {
    const int b = (D == 1) ? 0 : 1;
    int tile = blockIdx.x;       // 0..7, 32 t each
    int n = blockIdx.y;
    int tid = threadIdx.x;
    __shared__ float ws[BCc * BCc * 5];      // 2880
    for (int i = tid; i < BCc * BCc * 5; i += 640)
        ws[i] = tcw[b * BCc * BCc * 5 + i];
    __syncthreads();
    if (tid >= BCc * Vv) return;
    int oc = tid / Vv, v = tid % Vv;
    float bias = __ldg(&tcb[b * BCc + oc]);
    float sc = __ldg(&tcbn_s[b * BCc + oc]), sh = __ldg(&tcbn_b[b * BCc + oc]);
    const float* H = (b == 0 ? g_H0 : g_H1) + (size_t)n * BCc * TV;
    int t0 = tile * 32;
    const int NL = 8 + 4 * D;
    for (int chunk = 0; chunk < 4; chunk++) {
        int tc0 = t0 + chunk * 8;
        float acc[8];
#pragma unroll
        for (int j = 0; j < 8; j++) acc[j] = bias;
        for (int ic = 0; ic < BCc; ic++) {
            float h[NL];
#pragma unroll
            for (int i = 0; i < NL; i++) {
                int tg = tc0 + i - 2 * D;
                h[i] = ((unsigned)tg < 256u) ? H[(size_t)ic * TV + tg * Vv + v] : 0.f;
            }
            const float* wp = ws + (oc * BCc + ic) * 5;
#pragma unroll
            for (int k = 0; k < 5; k++) {
                float wv = wp[k];
#pragma unroll
                for (int j = 0; j < 8; j++) acc[j] += wv * h[j + k * D];
            }
        }
#pragma unroll
        for (int j = 0; j < 8; j++) {
            int tg = tc0 + j;
            size_t oi = ((size_t)n * OUTo + b * BCc + oc) * TV + (size_t)tg * Vv + v;
            out[oi] = fmaxf(acc[j] * sc + sh + __ldg(&x[oi]), 0.f);
        }
    }
}

// ---------------- K7: maxpool branch -----------------------------------------
__global__ void k_mp(const float* __restrict__ mpbn_s, const float* __restrict__ mpbn_b,
                     const float* __restrict__ x, float* __restrict__ out) {
    int idx = blockIdx.x * 256 + threadIdx.x;
    if (idx >= Nn * BCc * TV) return;
    int v = idx % Vv;
    int t = (idx / Vv) % Tt;
    int bc = (idx / TV) % BCc;
    int n = idx / (TV * BCc);
    const float* H = g_H2 + (size_t)(n * BCc + bc) * TV;
    float m = H[t * Vv + v];
    if (t > 0)   m = fmaxf(m, H[(t - 1) * Vv + v]);
    if (t < 255) m = fmaxf(m, H[(t + 1) * Vv + v]);
    float val = m * __ldg(&mpbn_s[bc]) + __ldg(&mpbn_b[bc]);
    size_t oi = ((size_t)n * OUTo + 48 + bc) * TV + (size_t)t * Vv + v;
    out[oi] = fmaxf(val + __ldg(&x[oi]), 0.f);
}

// ---------------- driver ------------------------------------------------------
extern "C" void kernel_launch(void* const* d_in, const int* in_sizes, int n_in,
                              void* d_out, int out_size) {
    const float* x      = (const float*)d_in[0];
    const float* spd_A  = (const float*)d_in[1];
    const float* A3     = (const float*)d_in[2];
    const float* A6     = (const float*)d_in[3];
    const float* alpha  = (const float*)d_in[4];
    const float* beta   = (const float*)d_in[5];
    const float* gamma  = (const float*)d_in[6];
    const float* c1_w   = (const float*)d_in[7];
    const float* c1_b   = (const float*)d_in[8];
    const float* c2_w   = (const float*)d_in[9];
    const float* c2_b   = (const float*)d_in[10];
    const float* c4_w   = (const float*)d_in[11];
    const float* c4_b   = (const float*)d_in[12];
    const float* c3_w   = (const float*)d_in[13];
    const float* c3_b   = (const float*)d_in[14];
    const float* gbn_s  = (const float*)d_in[15];
    const float* gbn_b  = (const float*)d_in[16];
    const float* pw_w   = (const float*)d_in[17];
    const float* pw_b   = (const float*)d_in[18];
    const float* pwbn_s = (const float*)d_in[19];
    const float* pwbn_b = (const float*)d_in[20];
    const float* tc_w   = (const float*)d_in[21];
    const float* tc_b   = (const float*)d_in[22];
    const float* tcbn_s = (const float*)d_in[23];
    const float* tcbn_b = (const float*)d_in[24];
    const float* mpbn_s = (const float*)d_in[25];
    const float* mpbn_b = (const float*)d_in[26];
    float* out = (float*)d_out;

    // K1: T-mean
    k_xm<<<Nn * Cc, 128>>>(x);
    // K2: A_at
    k_rel<<<Nn * Ss, 256>>>(spd_A, A3, A6, alpha, beta, gamma,
                            c1_w, c1_b, c2_w, c2_b, c4_w, c4_b);
    // K3: x3 = c3_w[s] @ x[n] + c3_b
    k_gemm96<0><<<dim3(50, Ss, Nn), 256>>>(c3_w, x, c3_b, nullptr, nullptr, nullptr);
    // K4: y
    k_y<<<Nn * OUTo, 256>>>(x, gbn_s, gbn_b);
    // K5: pointwise convs (all 4 branches stacked), branch3 fused to out
    k_gemm96<1><<<dim3(50, 1, Nn), 256>>>(pw_w, x, pw_b, pwbn_s, pwbn_b, out);
    // K6: temporal convs
    k_tc<1><<<dim3(8, Nn), 640>>>(tc_w, tc_b, tcbn_s, tcbn_b, x, out);
    k_tc<2><<<dim3(8, Nn), 640>>>(tc_w, tc_b, tcbn_s, tcbn_b, x, out);
    // K7: maxpool branch
    k_mp<<<(Nn * BCc * TV + 255) / 256, 256>>>(mpbn_s, mpbn_b, x, out);
}

// round 3
// speedup vs baseline: 1.0119x; 1.0119x over previous
#include <cuda_runtime.h>
#include <math.h>

#define Nn 32
#define Cc 96
#define Tt 256
#define Vv 25
#define Ss 3
#define RELr 12
#define OUTo 96
#define BCc 24
#define TV (Tt*Vv)   // 6400

typedef unsigned long long u64;

__device__ __forceinline__ u64 splat2(float x) {
    u64 r;
    asm("mov.b64 %0, {%1, %1};" : "=l"(r) : "f"(x));
    return r;
}
__device__ __forceinline__ void ffma2(u64& d, u64 a, u64 b) {
    asm("fma.rn.f32x2 %0, %1, %2, %0;" : "+l"(d) : "l"(a), "l"(b));
}
__device__ __forceinline__ void unpack2(float& lo, float& hi, u64 v) {
    asm("mov.b64 {%0, %1}, %2;" : "=f"(lo), "=f"(hi) : "l"(v));
}

// ---------------- scratch ----------------------------------------------------
__device__ float g_xm[Nn*Cc*Vv];
__device__ float g_A [(size_t)Nn*Ss*OUTo*Vv*Vv];
__device__ float g_x3[(size_t)Nn*Ss*OUTo*TV];
__device__ float g_y [(size_t)Nn*OUTo*TV];
__device__ float g_H0[(size_t)Nn*BCc*TV];
__device__ float g_H1[(size_t)Nn*BCc*TV];
__device__ float g_H2[(size_t)Nn*BCc*TV];

// ---------------- K1: mean over T --------------------------------------------
__global__ void k_xm(const float* __restrict__ x) {
    int nc = blockIdx.x;
    const float* xp = x + (size_t)nc * TV;
    float acc[Vv];
#pragma unroll
    for (int v = 0; v < Vv; v++) acc[v] = 0.f;
    for (int t = threadIdx.x; t < Tt; t += 128) {
        const float* row = xp + t * Vv;
#pragma unroll
        for (int v = 0; v < Vv; v++) acc[v] += row[v];
    }
    __shared__ float s[Vv][128];
#pragma unroll
    for (int v = 0; v < Vv; v++) s[v][threadIdx.x] = acc[v];
    __syncthreads();
    if (threadIdx.x < Vv) {
        float r = 0.f;
#pragma unroll 8
        for (int i = 0; i < 128; i++) r += s[threadIdx.x][i];
        g_xm[nc * Vv + threadIdx.x] = r * (1.f / Tt);
    }
}

// ---------------- K2: CTRGC relation -> A_at ---------------------------------
__global__ void k_rel(const float* __restrict__ spd, const float* __restrict__ A3,
                      const float* __restrict__ A6,
                      const float* __restrict__ alpha, const float* __restrict__ beta,
                      const float* __restrict__ gamma,
                      const float* __restrict__ c1w, const float* __restrict__ c1b,
                      const float* __restrict__ c2w, const float* __restrict__ c2b,
                      const float* __restrict__ c4w, const float* __restrict__ c4b) {
    int n = blockIdx.x / Ss, s = blockIdx.x % Ss;
    int tid = threadIdx.x;
    __shared__ float xm_s[Cc * Vv];
    __shared__ float x1s[RELr * Vv];
    __shared__ float x2s[RELr * Vv];
    __shared__ float Rs[RELr * Vv * Vv];
    __shared__ float base_s[Vv * Vv];

    for (int i = tid; i < Cc * Vv; i += 256) xm_s[i] = g_xm[n * Cc * Vv + i];
    __syncthreads();

    for (int i = tid; i < 2 * RELr * Vv; i += 256) {
        int which = i / (RELr * Vv);
        int rv = i % (RELr * Vv);
        int r = rv / Vv, v = rv % Vv;
        const float* w = (which ? c2w : c1w) + (s * RELr + r) * Cc;
        float acc = (which ? c2b : c1b)[s * RELr + r];
#pragma unroll 8
        for (int c = 0; c < Cc; c++) acc += w[c] * xm_s[c * Vv + v];
        (which ? x2s : x1s)[rv] = acc;
    }
    __syncthreads();

    float ga = __ldg(gamma);
    for (int i = tid; i < RELr * Vv * Vv; i += 256) {
        int r = i / (Vv * Vv);
        int uv = i % (Vv * Vv);
        int u = uv / Vv, v = uv % Vv;
        Rs[i] = tanhf(x1s[r * Vv + u] - x2s[r * Vv + v]);
    }
    for (int i = tid; i < Vv * Vv; i += 256)
        base_s[i] = __ldg(&A3[s * 625 + i]) + __ldg(&spd[i]) * ga;
    __syncthreads();

    float al = __ldg(alpha), be = __ldg(beta);
    float* Aout = g_A + (size_t)(n * Ss + s) * OUTo * 625;
    for (int o = 0; o < OUTo; o++) {
        float w4[RELr];
#pragma unroll
        for (int r = 0; r < RELr; r++) w4[r] = __ldg(&c4w[(s * OUTo + o) * RELr + r]);
        float b4 = __ldg(&c4b[s * OUTo + o]);
        const float* A6o = A6 + (o % 6) * 625;
        for (int i = tid; i < 625; i += 256) {
            float m = b4;
#pragma unroll
            for (int r = 0; r < RELr; r++) m += w4[r] * Rs[r * 625 + i];
            Aout[(size_t)o * 625 + i] = m * al + base_s[i] + __ldg(&A6o[i]) * be;
        }
    }
}

// ---------------- GEMM core: 96 rows x 128 cols, K=96, f32x2 ------------------
// thread tile 6 rows x 8 cols; pairs along rows. blockDim 256.
template <int EPI>
__global__ void k_gemm96(const float* __restrict__ Wfull,
                         const float* __restrict__ xglob,   // x (EPI0) / residual x (EPI1)
                         const float* __restrict__ bias,
                         const float* __restrict__ bn_s, const float* __restrict__ bn_b,
                         float* __restrict__ outbuf)
{
    int ct = blockIdx.x;
    int s  = blockIdx.y;
    int n  = blockIdx.z;
    int tid = threadIdx.x;
    int tx = tid & 15, ty = tid >> 4;

    const float* W = Wfull + (size_t)s * 96 * 96;
    const float* Xin = (EPI == 0) ? xglob : (const float*)g_y;
    const float* X = Xin + (size_t)n * Cc * TV + (size_t)ct * 128;

    __shared__ float Ws[32 * 98];    // [kk][row], row padded to 98 (even)
    __shared__ float Xs[32 * 128];

    u64 acc2[3][8];
#pragma unroll
    for (int p = 0; p < 3; p++)
#pragma unroll
        for (int j = 0; j < 8; j++) acc2[p][j] = 0ull;

    for (int k0 = 0; k0 < 96; k0 += 32) {
        __syncthreads();
        for (int i = tid; i < 96 * 32; i += 256) {
            int r = i >> 5, kk = i & 31;
            Ws[kk * 98 + r] = W[r * 96 + k0 + kk];
        }
        for (int i4 = tid; i4 < 1024; i4 += 256) {
            int kk = i4 >> 5;
            int c4 = (i4 & 31) << 2;
            *(float4*)&Xs[kk * 128 + c4] =
                *(const float4*)&X[(size_t)(k0 + kk) * TV + c4];
        }
        __syncthreads();
#pragma unroll
        for (int kk = 0; kk < 32; kk++) {
            u64 ap[3];
#pragma unroll
            for (int p = 0; p < 3; p++)
                ap[p] = *(const u64*)&Ws[kk * 98 + ty * 6 + 2 * p];
            float4 b0 = *(float4*)&Xs[kk * 128 + tx * 8];
            float4 b1 = *(float4*)&Xs[kk * 128 + tx * 8 + 4];
            u64 bs[8];
            bs[0] = splat2(b0.x); bs[1] = splat2(b0.y);
            bs[2] = splat2(b0.z); bs[3] = splat2(b0.w);
            bs[4] = splat2(b1.x); bs[5] = splat2(b1.y);
            bs[6] = splat2(b1.z); bs[7] = splat2(b1.w);
#pragma unroll
            for (int p = 0; p < 3; p++)
#pragma unroll
                for (int j = 0; j < 8; j++) ffma2(acc2[p][j], ap[p], bs[j]);
        }
    }

    if (EPI == 0) {
        float* O = g_x3 + (size_t)(n * Ss + s) * 96 * TV + (size_t)ct * 128;
#pragma unroll
        for (int p = 0; p < 3; p++) {
            float v0[8], v1[8];
#pragma unroll
            for (int j = 0; j < 8; j++) unpack2(v0[j], v1[j], acc2[p][j]);
#pragma unroll
            for (int e = 0; e < 2; e++) {
                int r = ty * 6 + 2 * p + e;
                float bv = __ldg(&bias[s * 96 + r]);
                float* vv = e ? v1 : v0;
                float4 o0 = {vv[0] + bv, vv[1] + bv, vv[2] + bv, vv[3] + bv};
                float4 o1 = {vv[4] + bv, vv[5] + bv, vv[6] + bv, vv[7] + bv};
                *(float4*)&O[(size_t)r * TV + tx * 8]     = o0;
                *(float4*)&O[(size_t)r * TV + tx * 8 + 4] = o1;
            }
        }
    } else {
#pragma unroll
        for (int p = 0; p < 3; p++) {
            float v0[8], v1[8];
#pragma unroll
            for (int j = 0; j < 8; j++) unpack2(v0[j], v1[j], acc2[p][j]);
#pragma unroll
            for (int e = 0; e < 2; e++) {
                int r = ty * 6 + 2 * p + e;
                int br = r / 24, bc = r % 24;
                float bv = __ldg(&bias[r]);
                float sc = __ldg(&bn_s[r]), sh = __ldg(&bn_b[r]);
                float* vv = e ? v1 : v0;
                int colg = ct * 128 + tx * 8;
#pragma unroll
                for (int j = 0; j < 8; j++) {
                    float v = vv[j] + bv;
                    v = v * sc + sh;
                    if (br < 3) v = fmaxf(v, 0.f);
                    size_t hidx = (size_t)(n * BCc + bc) * TV + colg + j;
                    if (br == 0)      g_H0[hidx] = v;
                    else if (br == 1) g_H1[hidx] = v;
                    else if (br == 2) g_H2[hidx] = v;
                    else {
                        size_t oi = ((size_t)n * OUTo + 72 + bc) * TV + colg + j;
                        outbuf[oi] = fmaxf(v + __ldg(&xglob[oi]), 0.f);
                    }
                }
            }
        }
    }
}

// ---------------- K4: y = relu(bn(sum_s A_s @ x3_s) + x) ----------------------
// block = (n,o), 256 threads = one per t. A staged transposed [s][v][u(pad26)],
// x3 staged transposed [v][t(pad257)], accumulate 13 u-pairs via f32x2.
__global__ void k_y(const float* __restrict__ x, const float* __restrict__ gbn_s,
                    const float* __restrict__ gbn_b) {
    int no = blockIdx.x;
    int n = no / OUTo, o = no % OUTo;
    int tid = threadIdx.x;

    __shared__ float As[Ss * Vv * 26];   // 1950 floats
    __shared__ float Xs[Vv * 257];       // 6425 floats

    // stage A transposed: As[(s*25+v)*26 + u] = A[s][u][v]
    for (int i = tid; i < Ss * 625; i += 256) {
        int s = i / 625;
        int rem = i - s * 625;
        int u = rem / 25, v = rem - u * 25;
        As[(s * 25 + v) * 26 + u] =
            g_A[(((size_t)(n * Ss + s)) * OUTo + o) * 625 + rem];
    }
    for (int i = tid; i < Ss * Vv; i += 256) As[i * 26 + 25] = 0.f;

    u64 acc2[13];
#pragma unroll
    for (int p = 0; p < 13; p++) acc2[p] = 0ull;

    int t = tid;
#pragma unroll
    for (int s = 0; s < Ss; s++) {
        __syncthreads();
        // stage x3 slab (contiguous 6400 floats) transposed into Xs[v][t]
        const float* base = g_x3 + (((size_t)(n * Ss + s)) * OUTo + o) * TV;
        for (int l = tid * 4; l < TV; l += 1024) {
            float4 w = *(const float4*)&base[l];
            float e[4] = {w.x, w.y, w.z, w.w};
#pragma unroll
            for (int k = 0; k < 4; k++) {
                int idx = l + k;
                int tt = (int)(((unsigned)idx * 5243u) >> 17);   // idx/25
                int vv = idx - tt * 25;
                Xs[vv * 257 + tt] = e[k];
            }
        }
        __syncthreads();
        const float* Asv = As + s * Vv * 26;
#pragma unroll
        for (int v = 0; v < Vv; v++) {
            u64 xs2 = splat2(Xs[v * 257 + t]);
            const float* ar = Asv + v * 26;
#pragma unroll
            for (int p = 0; p < 13; p++) {
                u64 ap = *(const u64*)&ar[2 * p];
                ffma2(acc2[p], ap, xs2);
            }
        }
    }

    float gs = __ldg(&gbn_s[o]), gb = __ldg(&gbn_b[o]);
    size_t obase = ((size_t)n * OUTo + o) * TV + (size_t)t * Vv;
    float* yo = g_y + obase;
    const float* xo = x + obase;
#pragma unroll
    for (int p = 0; p < 13; p++) {
        float lo, hi;
        unpack2(lo, hi, acc2[p]);
        int u = 2 * p;
        yo[u] = fmaxf(lo * gs + gb + xo[u], 0.f);
        if (u + 1 < Vv) yo[u + 1] = fmaxf(hi * gs + gb + xo[u + 1], 0.f);
    }
}

// ---------------- K6: dilated temporal conv ----------------------------------
template <int D>
__global__ void k_tc(const float* __restrict__ tcw, const float* __restrict__ tcb,
                     const float* __restrict__ tcbn_s, const float* __restrict__ tcbn_b,
                     const float* __restrict__ x, float* __restrict__ out) {
    const int b = (D == 1) ? 0 : 1;
    int tile = blockIdx.x;
    int n = blockIdx.y;
    int tid = threadIdx.x;
    __shared__ float ws[BCc * BCc * 5];
    for (int i = tid; i < BCc * BCc * 5; i += 640)
        ws[i] = tcw[b * BCc * BCc * 5 + i];
    __syncthreads();
    if (tid >= BCc * Vv) return;
    int oc = tid / Vv, v = tid % Vv;
    float bias = __ldg(&tcb[b * BCc + oc]);
    float sc = __ldg(&tcbn_s[b * BCc + oc]), sh = __ldg(&tcbn_b[b * BCc + oc]);
    const float* H = (b == 0 ? g_H0 : g_H1) + (size_t)n * BCc * TV;
    int t0 = tile * 32;
    const int NL = 8 + 4 * D;
    for (int chunk = 0; chunk < 4; chunk++) {
        int tc0 = t0 + chunk * 8;
        float acc[8];
#pragma unroll
        for (int j = 0; j < 8; j++) acc[j] = bias;
        for (int ic = 0; ic < BCc; ic++) {
            float h[NL];
#pragma unroll
            for (int i = 0; i < NL; i++) {
                int tg = tc0 + i - 2 * D;
                h[i] = ((unsigned)tg < 256u) ? H[(size_t)ic * TV + tg * Vv + v] : 0.f;
            }
            const float* wp = ws + (oc * BCc + ic) * 5;
#pragma unroll
            for (int k = 0; k < 5; k++) {
                float wv = wp[k];
#pragma unroll
                for (int j = 0; j < 8; j++) acc[j] += wv * h[j + k * D];
            }
        }
#pragma unroll
        for (int j = 0; j < 8; j++) {
            int tg = tc0 + j;
            size_t oi = ((size_t)n * OUTo + b * BCc + oc) * TV + (size_t)tg * Vv + v;
            out[oi] = fmaxf(acc[j] * sc + sh + __ldg(&x[oi]), 0.f);
        }
    }
}

// ---------------- K7: maxpool branch -----------------------------------------
__global__ void k_mp(const float* __restrict__ mpbn_s, const float* __restrict__ mpbn_b,
                     const float* __restrict__ x, float* __restrict__ out) {
    int idx = blockIdx.x * 256 + threadIdx.x;
    if (idx >= Nn * BCc * TV) return;
    int v = idx % Vv;
    int t = (idx / Vv) % Tt;
    int bc = (idx / TV) % BCc;
    int n = idx / (TV * BCc);
    const float* H = g_H2 + (size_t)(n * BCc + bc) * TV;
    float m = H[t * Vv + v];
    if (t > 0)   m = fmaxf(m, H[(t - 1) * Vv + v]);
    if (t < 255) m = fmaxf(m, H[(t + 1) * Vv + v]);
    float val = m * __ldg(&mpbn_s[bc]) + __ldg(&mpbn_b[bc]);
    size_t oi = ((size_t)n * OUTo + 48 + bc) * TV + (size_t)t * Vv + v;
    out[oi] = fmaxf(val + __ldg(&x[oi]), 0.f);
}

// ---------------- driver ------------------------------------------------------
extern "C" void kernel_launch(void* const* d_in, const int* in_sizes, int n_in,
                              void* d_out, int out_size) {
    const float* x      = (const float*)d_in[0];
    const float* spd_A  = (const float*)d_in[1];
    const float* A3     = (const float*)d_in[2];
    const float* A6     = (const float*)d_in[3];
    const float* alpha  = (const float*)d_in[4];
    const float* beta   = (const float*)d_in[5];
    const float* gamma  = (const float*)d_in[6];
    const float* c1_w   = (const float*)d_in[7];
    const float* c1_b   = (const float*)d_in[8];
    const float* c2_w   = (const float*)d_in[9];
    const float* c2_b   = (const float*)d_in[10];
    const float* c4_w   = (const float*)d_in[11];
    const float* c4_b   = (const float*)d_in[12];
    const float* c3_w   = (const float*)d_in[13];
    const float* c3_b   = (const float*)d_in[14];
    const float* gbn_s  = (const float*)d_in[15];
    const float* gbn_b  = (const float*)d_in[16];
    const float* pw_w   = (const float*)d_in[17];
    const float* pw_b   = (const float*)d_in[18];
    const float* pwbn_s = (const float*)d_in[19];
    const float* pwbn_b = (const float*)d_in[20];
    const float* tc_w   = (const float*)d_in[21];
    const float* tc_b   = (const float*)d_in[22];
    const float* tcbn_s = (const float*)d_in[23];
    const float* tcbn_b = (const float*)d_in[24];
    const float* mpbn_s = (const float*)d_in[25];
    const float* mpbn_b = (const float*)d_in[26];
    float* out = (float*)d_out;

    k_xm<<<Nn * Cc, 128>>>(x);
    k_rel<<<Nn * Ss, 256>>>(spd_A, A3, A6, alpha, beta, gamma,
                            c1_w, c1_b, c2_w, c2_b, c4_w, c4_b);
    k_gemm96<0><<<dim3(50, Ss, Nn), 256>>>(c3_w, x, c3_b, nullptr, nullptr, nullptr);
    k_y<<<Nn * OUTo, 256>>>(x, gbn_s, gbn_b);
    k_gemm96<1><<<dim3(50, 1, Nn), 256>>>(pw_w, x, pw_b, pwbn_s, pwbn_b, out);
    k_tc<1><<<dim3(8, Nn), 640>>>(tc_w, tc_b, tcbn_s, tcbn_b, x, out);
    k_tc<2><<<dim3(8, Nn), 640>>>(tc_w, tc_b, tcbn_s, tcbn_b, x, out);
    k_mp<<<(Nn * BCc * TV + 255) / 256, 256>>>(mpbn_s, mpbn_b, x, out);
}

// round 4
// speedup vs baseline: 1.1529x; 1.1393x over previous
#include <cuda_runtime.h>
#include <math.h>

#define Nn 32
#define Cc 96
#define Tt 256
#define Vv 25
#define Ss 3
#define RELr 12
#define OUTo 96
#define BCc 24
#define TV (Tt*Vv)   // 6400

typedef unsigned long long u64;

__device__ __forceinline__ u64 splat2(float x) {
    u64 r;
    asm("mov.b64 %0, {%1, %1};" : "=l"(r) : "f"(x));
    return r;
}
__device__ __forceinline__ void ffma2(u64& d, u64 a, u64 b) {
    asm("fma.rn.f32x2 %0, %1, %2, %0;" : "+l"(d) : "l"(a), "l"(b));
}
__device__ __forceinline__ void unpack2(float& lo, float& hi, u64 v) {
    asm("mov.b64 {%0, %1}, %2;" : "=f"(lo), "=f"(hi) : "l"(v));
}

// ---------------- scratch ----------------------------------------------------
__device__ float g_xm[Nn*Cc*Vv];
__device__ float g_A [(size_t)Nn*Ss*OUTo*Vv*Vv];
__device__ float g_x3[(size_t)Nn*Ss*OUTo*TV];
__device__ float g_y [(size_t)Nn*OUTo*TV];
__device__ float g_H0[(size_t)Nn*BCc*TV];
__device__ float g_H1[(size_t)Nn*BCc*TV];
__device__ float g_H2[(size_t)Nn*BCc*TV];

// ---------------- K1: mean over T --------------------------------------------
__global__ void k_xm(const float* __restrict__ x) {
    int nc = blockIdx.x;
    const float* xp = x + (size_t)nc * TV;
    float acc[Vv];
#pragma unroll
    for (int v = 0; v < Vv; v++) acc[v] = 0.f;
    for (int t = threadIdx.x; t < Tt; t += 128) {
        const float* row = xp + t * Vv;
#pragma unroll
        for (int v = 0; v < Vv; v++) acc[v] += row[v];
    }
    __shared__ float s[Vv][128];
#pragma unroll
    for (int v = 0; v < Vv; v++) s[v][threadIdx.x] = acc[v];
    __syncthreads();
    if (threadIdx.x < Vv) {
        float r = 0.f;
#pragma unroll 8
        for (int i = 0; i < 128; i++) r += s[threadIdx.x][i];
        g_xm[nc * Vv + threadIdx.x] = r * (1.f / Tt);
    }
}

// ---------------- K2: CTRGC relation -> A_at ---------------------------------
__global__ void k_rel(const float* __restrict__ spd, const float* __restrict__ A3,
                      const float* __restrict__ A6,
                      const float* __restrict__ alpha, const float* __restrict__ beta,
                      const float* __restrict__ gamma,
                      const float* __restrict__ c1w, const float* __restrict__ c1b,
                      const float* __restrict__ c2w, const float* __restrict__ c2b,
                      const float* __restrict__ c4w, const float* __restrict__ c4b) {
    int n = blockIdx.x / Ss, s = blockIdx.x % Ss;
    int tid = threadIdx.x;
    __shared__ float xm_s[Cc * Vv];
    __shared__ float x1s[RELr * Vv];
    __shared__ float x2s[RELr * Vv];
    __shared__ float Rs[RELr * Vv * Vv];
    __shared__ float base_s[Vv * Vv];

    for (int i = tid; i < Cc * Vv; i += 256) xm_s[i] = g_xm[n * Cc * Vv + i];
    __syncthreads();

    for (int i = tid; i < 2 * RELr * Vv; i += 256) {
        int which = i / (RELr * Vv);
        int rv = i % (RELr * Vv);
        int r = rv / Vv, v = rv % Vv;
        const float* w = (which ? c2w : c1w) + (s * RELr + r) * Cc;
        float acc = (which ? c2b : c1b)[s * RELr + r];
#pragma unroll 8
        for (int c = 0; c < Cc; c++) acc += w[c] * xm_s[c * Vv + v];
        (which ? x2s : x1s)[rv] = acc;
    }
    __syncthreads();

    float ga = __ldg(gamma);
    for (int i = tid; i < RELr * Vv * Vv; i += 256) {
        int r = i / (Vv * Vv);
        int uv = i % (Vv * Vv);
        int u = uv / Vv, v = uv % Vv;
        Rs[i] = tanhf(x1s[r * Vv + u] - x2s[r * Vv + v]);
    }
    for (int i = tid; i < Vv * Vv; i += 256)
        base_s[i] = __ldg(&A3[s * 625 + i]) + __ldg(&spd[i]) * ga;
    __syncthreads();

    float al = __ldg(alpha), be = __ldg(beta);
    float* Aout = g_A + (size_t)(n * Ss + s) * OUTo * 625;
    for (int o = 0; o < OUTo; o++) {
        float w4[RELr];
#pragma unroll
        for (int r = 0; r < RELr; r++) w4[r] = __ldg(&c4w[(s * OUTo + o) * RELr + r]);
        float b4 = __ldg(&c4b[s * OUTo + o]);
        const float* A6o = A6 + (o % 6) * 625;
        for (int i = tid; i < 625; i += 256) {
            float m = b4;
#pragma unroll
            for (int r = 0; r < RELr; r++) m += w4[r] * Rs[r * 625 + i];
            Aout[(size_t)o * 625 + i] = m * al + base_s[i] + __ldg(&A6o[i]) * be;
        }
    }
}

// ---------------- GEMM core: 96 rows x 128 cols, K=96, f32x2 ------------------
template <int EPI>
__global__ void k_gemm96(const float* __restrict__ Wfull,
                         const float* __restrict__ xglob,
                         const float* __restrict__ bias,
                         const float* __restrict__ bn_s, const float* __restrict__ bn_b,
                         float* __restrict__ outbuf)
{
    int ct = blockIdx.x;
    int s  = blockIdx.y;
    int n  = blockIdx.z;
    int tid = threadIdx.x;
    int tx = tid & 15, ty = tid >> 4;

    const float* W = Wfull + (size_t)s * 96 * 96;
    const float* Xin = (EPI == 0) ? xglob : (const float*)g_y;
    const float* X = Xin + (size_t)n * Cc * TV + (size_t)ct * 128;

    __shared__ float Ws[32 * 98];
    __shared__ float Xs[32 * 128];

    u64 acc2[3][8];
#pragma unroll
    for (int p = 0; p < 3; p++)
#pragma unroll
        for (int j = 0; j < 8; j++) acc2[p][j] = 0ull;

    for (int k0 = 0; k0 < 96; k0 += 32) {
        __syncthreads();
        for (int i = tid; i < 96 * 32; i += 256) {
            int r = i >> 5, kk = i & 31;
            Ws[kk * 98 + r] = W[r * 96 + k0 + kk];
        }
        for (int i4 = tid; i4 < 1024; i4 += 256) {
            int kk = i4 >> 5;
            int c4 = (i4 & 31) << 2;
            *(float4*)&Xs[kk * 128 + c4] =
                *(const float4*)&X[(size_t)(k0 + kk) * TV + c4];
        }
        __syncthreads();
#pragma unroll
        for (int kk = 0; kk < 32; kk++) {
            u64 ap[3];
#pragma unroll
            for (int p = 0; p < 3; p++)
                ap[p] = *(const u64*)&Ws[kk * 98 + ty * 6 + 2 * p];
            float4 b0 = *(float4*)&Xs[kk * 128 + tx * 8];
            float4 b1 = *(float4*)&Xs[kk * 128 + tx * 8 + 4];
            u64 bs[8];
            bs[0] = splat2(b0.x); bs[1] = splat2(b0.y);
            bs[2] = splat2(b0.z); bs[3] = splat2(b0.w);
            bs[4] = splat2(b1.x); bs[5] = splat2(b1.y);
            bs[6] = splat2(b1.z); bs[7] = splat2(b1.w);
#pragma unroll
            for (int p = 0; p < 3; p++)
#pragma unroll
                for (int j = 0; j < 8; j++) ffma2(acc2[p][j], ap[p], bs[j]);
        }
    }

    if (EPI == 0) {
        float* O = g_x3 + (size_t)(n * Ss + s) * 96 * TV + (size_t)ct * 128;
#pragma unroll
        for (int p = 0; p < 3; p++) {
            float v0[8], v1[8];
#pragma unroll
            for (int j = 0; j < 8; j++) unpack2(v0[j], v1[j], acc2[p][j]);
#pragma unroll
            for (int e = 0; e < 2; e++) {
                int r = ty * 6 + 2 * p + e;
                float bv = __ldg(&bias[s * 96 + r]);
                float* vv = e ? v1 : v0;
                float4 o0 = {vv[0] + bv, vv[1] + bv, vv[2] + bv, vv[3] + bv};
                float4 o1 = {vv[4] + bv, vv[5] + bv, vv[6] + bv, vv[7] + bv};
                *(float4*)&O[(size_t)r * TV + tx * 8]     = o0;
                *(float4*)&O[(size_t)r * TV + tx * 8 + 4] = o1;
            }
        }
    } else {
#pragma unroll
        for (int p = 0; p < 3; p++) {
            float v0[8], v1[8];
#pragma unroll
            for (int j = 0; j < 8; j++) unpack2(v0[j], v1[j], acc2[p][j]);
#pragma unroll
            for (int e = 0; e < 2; e++) {
                int r = ty * 6 + 2 * p + e;
                int br = r / 24, bc = r % 24;
                float bv = __ldg(&bias[r]);
                float sc = __ldg(&bn_s[r]), sh = __ldg(&bn_b[r]);
                float* vv = e ? v1 : v0;
                int colg = ct * 128 + tx * 8;
                float w[8];
#pragma unroll
                for (int j = 0; j < 8; j++) {
                    float v = vv[j] + bv;
                    v = v * sc + sh;
                    if (br < 3) v = fmaxf(v, 0.f);
                    w[j] = v;
                }
                if (br < 3) {
                    size_t hidx = (size_t)(n * BCc + bc) * TV + colg;
                    float* dst = (br == 0) ? g_H0 : (br == 1) ? g_H1 : g_H2;
                    float4 q0 = {w[0], w[1], w[2], w[3]};
                    float4 q1 = {w[4], w[5], w[6], w[7]};
                    *(float4*)&dst[hidx]     = q0;
                    *(float4*)&dst[hidx + 4] = q1;
                } else {
                    size_t oi = ((size_t)n * OUTo + 72 + bc) * TV + colg;
                    float4 r0 = *(const float4*)&xglob[oi];
                    float4 r1 = *(const float4*)&xglob[oi + 4];
                    float4 q0 = {fmaxf(w[0] + r0.x, 0.f), fmaxf(w[1] + r0.y, 0.f),
                                 fmaxf(w[2] + r0.z, 0.f), fmaxf(w[3] + r0.w, 0.f)};
                    float4 q1 = {fmaxf(w[4] + r1.x, 0.f), fmaxf(w[5] + r1.y, 0.f),
                                 fmaxf(w[6] + r1.z, 0.f), fmaxf(w[7] + r1.w, 0.f)};
                    *(float4*)&outbuf[oi]     = q0;
                    *(float4*)&outbuf[oi + 4] = q1;
                }
            }
        }
    }
}

// ---------------- K4: y = relu(bn(sum_s A_s @ x3_s) + x) ----------------------
// block = (n,o), 128 threads, each owns t0=tid and t1=tid+128.
// x3 slab staged LINEARLY (coalesced); A staged as u-pairs [s][v][u(pad28)].
// Result staged [u][t(257)] then written back as coalesced float4 rows.
__global__ void k_y(const float* __restrict__ x, const float* __restrict__ gbn_s,
                    const float* __restrict__ gbn_b) {
    int no = blockIdx.x;
    int n = no / OUTo, o = no % OUTo;
    int tid = threadIdx.x;        // 128

    __shared__ __align__(16) float As[Ss * Vv * 28];   // 2100 floats
    __shared__ __align__(16) float Xs[Vv * 257 + 7];   // 6432: slab buffer / result buffer

    // stage A transposed into u-pairs: As[(s*25+v)*28 + u] = A[s][u][v]
    for (int i = tid; i < Ss * 625; i += 128) {
        int s = i / 625;
        int rem = i - s * 625;
        int u = rem / 25, v = rem - u * 25;
        As[(s * 25 + v) * 28 + u] =
            g_A[(((size_t)(n * Ss + s)) * OUTo + o) * 625 + rem];
    }
    // zero pads u=25..27
    for (int i = tid; i < Ss * Vv * 3; i += 128) {
        int sv = i / 3, pu = 25 + i % 3;
        As[sv * 28 + pu] = 0.f;
    }

    u64 acc2[13][2];
#pragma unroll
    for (int p = 0; p < 13; p++) { acc2[p][0] = 0ull; acc2[p][1] = 0ull; }

    int t0 = tid, t1 = tid + 128;
#pragma unroll
    for (int s = 0; s < Ss; s++) {
        __syncthreads();
        const float* base = g_x3 + (((size_t)(n * Ss + s)) * OUTo + o) * TV;
        for (int l = tid * 4; l < TV; l += 512)
            *(float4*)&Xs[l] = *(const float4*)&base[l];
        __syncthreads();
        const float* A2 = As + s * Vv * 28;
#pragma unroll
        for (int v = 0; v < Vv; v++) {
            u64 xa = splat2(Xs[t0 * Vv + v]);
            u64 xb = splat2(Xs[t1 * Vv + v]);
            const float* ar = A2 + v * 28;
#pragma unroll
            for (int p = 0; p < 13; p++) {
                u64 ap = *(const u64*)&ar[2 * p];
                ffma2(acc2[p][0], ap, xa);
                ffma2(acc2[p][1], ap, xb);
            }
        }
    }

    float gs = __ldg(&gbn_s[o]), gb = __ldg(&gbn_b[o]);
    __syncthreads();
    // stage results (with BN applied) into Xs as [u][t] with stride 257
#pragma unroll
    for (int p = 0; p < 13; p++) {
        float lo0, hi0, lo1, hi1;
        unpack2(lo0, hi0, acc2[p][0]);
        unpack2(lo1, hi1, acc2[p][1]);
        int u = 2 * p;
        Xs[u * 257 + t0] = lo0 * gs + gb;
        Xs[u * 257 + t1] = lo1 * gs + gb;
        if (u + 1 < Vv) {
            Xs[(u + 1) * 257 + t0] = hi0 * gs + gb;
            Xs[(u + 1) * 257 + t1] = hi1 * gs + gb;
        }
    }
    __syncthreads();

    size_t obase = ((size_t)n * OUTo + o) * TV;
    const float* xo = x + obase;
    float* yo = g_y + obase;
    for (int l = tid * 4; l < TV; l += 512) {
        float4 r = *(const float4*)&xo[l];
        float rr[4] = {r.x, r.y, r.z, r.w};
        float w[4];
#pragma unroll
        for (int k = 0; k < 4; k++) {
            int idx = l + k;
            int tt = (int)(((unsigned)idx * 5243u) >> 17);   // idx/25
            int vv = idx - tt * 25;
            w[k] = fmaxf(Xs[vv * 257 + tt] + rr[k], 0.f);
        }
        float4 q = {w[0], w[1], w[2], w[3]};
        *(float4*)&yo[l] = q;
    }
}

// ---------------- K6: dilated temporal conv ----------------------------------
template <int D>
__global__ void k_tc(const float* __restrict__ tcw, const float* __restrict__ tcb,
                     const float* __restrict__ tcbn_s, const float* __restrict__ tcbn_b,
                     const float* __restrict__ x, float* __restrict__ out) {
    const int b = (D == 1) ? 0 : 1;
    int tile = blockIdx.x;
    int n = blockIdx.y;
    int tid = threadIdx.x;
    __shared__ float ws[BCc * BCc * 5];
    for (int i = tid; i < BCc * BCc * 5; i += 640)
        ws[i] = tcw[b * BCc * BCc * 5 + i];
    __syncthreads();
    if (tid >= BCc * Vv) return;
    int oc = tid / Vv, v = tid % Vv;
    float bias = __ldg(&tcb[b * BCc + oc]);
    float sc = __ldg(&tcbn_s[b * BCc + oc]), sh = __ldg(&tcbn_b[b * BCc + oc]);
    const float* H = (b == 0 ? g_H0 : g_H1) + (size_t)n * BCc * TV;
    int t0 = tile * 32;
    const int NL = 8 + 4 * D;
    for (int chunk = 0; chunk < 4; chunk++) {
        int tc0 = t0 + chunk * 8;
        float acc[8];
#pragma unroll
        for (int j = 0; j < 8; j++) acc[j] = bias;
        for (int ic = 0; ic < BCc; ic++) {
            float h[NL];
#pragma unroll
            for (int i = 0; i < NL; i++) {
                int tg = tc0 + i - 2 * D;
                h[i] = ((unsigned)tg < 256u) ? H[(size_t)ic * TV + tg * Vv + v] : 0.f;
            }
            const float* wp = ws + (oc * BCc + ic) * 5;
#pragma unroll
            for (int k = 0; k < 5; k++) {
                float wv = wp[k];
#pragma unroll
                for (int j = 0; j < 8; j++) acc[j] += wv * h[j + k * D];
            }
        }
#pragma unroll
        for (int j = 0; j < 8; j++) {
            int tg = tc0 + j;
            size_t oi = ((size_t)n * OUTo + b * BCc + oc) * TV + (size_t)tg * Vv + v;
            out[oi] = fmaxf(acc[j] * sc + sh + __ldg(&x[oi]), 0.f);
        }
    }
}

// ---------------- K7: maxpool branch -----------------------------------------
__global__ void k_mp(const float* __restrict__ mpbn_s, const float* __restrict__ mpbn_b,
                     const float* __restrict__ x, float* __restrict__ out) {
    int idx = blockIdx.x * 256 + threadIdx.x;
    if (idx >= Nn * BCc * TV) return;
    int v = idx % Vv;
    int t = (idx / Vv) % Tt;
    int bc = (idx / TV) % BCc;
    int n = idx / (TV * BCc);
    const float* H = g_H2 + (size_t)(n * BCc + bc) * TV;
    float m = H[t * Vv + v];
    if (t > 0)   m = fmaxf(m, H[(t - 1) * Vv + v]);
    if (t < 255) m = fmaxf(m, H[(t + 1) * Vv + v]);
    float val = m * __ldg(&mpbn_s[bc]) + __ldg(&mpbn_b[bc]);
    size_t oi = ((size_t)n * OUTo + 48 + bc) * TV + (size_t)t * Vv + v;
    out[oi] = fmaxf(val + __ldg(&x[oi]), 0.f);
}

// ---------------- driver ------------------------------------------------------
extern "C" void kernel_launch(void* const* d_in, const int* in_sizes, int n_in,
                              void* d_out, int out_size) {
    const float* x      = (const float*)d_in[0];
    const float* spd_A  = (const float*)d_in[1];
    const float* A3     = (const float*)d_in[2];
    const float* A6     = (const float*)d_in[3];
    const float* alpha  = (const float*)d_in[4];
    const float* beta   = (const float*)d_in[5];
    const float* gamma  = (const float*)d_in[6];
    const float* c1_w   = (const float*)d_in[7];
    const float* c1_b   = (const float*)d_in[8];
    const float* c2_w   = (const float*)d_in[9];
    const float* c2_b   = (const float*)d_in[10];
    const float* c4_w   = (const float*)d_in[11];
    const float* c4_b   = (const float*)d_in[12];
    const float* c3_w   = (const float*)d_in[13];
    const float* c3_b   = (const float*)d_in[14];
    const float* gbn_s  = (const float*)d_in[15];
    const float* gbn_b  = (const float*)d_in[16];
    const float* pw_w   = (const float*)d_in[17];
    const float* pw_b   = (const float*)d_in[18];
    const float* pwbn_s = (const float*)d_in[19];
    const float* pwbn_b = (const float*)d_in[20];
    const float* tc_w   = (const float*)d_in[21];
    const float* tc_b   = (const float*)d_in[22];
    const float* tcbn_s = (const float*)d_in[23];
    const float* tcbn_b = (const float*)d_in[24];
    const float* mpbn_s = (const float*)d_in[25];
    const float* mpbn_b = (const float*)d_in[26];
    float* out = (float*)d_out;

    k_xm<<<Nn * Cc, 128>>>(x);
    k_rel<<<Nn * Ss, 256>>>(spd_A, A3, A6, alpha, beta, gamma,
                            c1_w, c1_b, c2_w, c2_b, c4_w, c4_b);
    k_gemm96<0><<<dim3(50, Ss, Nn), 256>>>(c3_w, x, c3_b, nullptr, nullptr, nullptr);
    k_y<<<Nn * OUTo, 128>>>(x, gbn_s, gbn_b);
    k_gemm96<1><<<dim3(50, 1, Nn), 256>>>(pw_w, x, pw_b, pwbn_s, pwbn_b, out);
    k_tc<1><<<dim3(8, Nn), 640>>>(tc_w, tc_b, tcbn_s, tcbn_b, x, out);
    k_tc<2><<<dim3(8, Nn), 640>>>(tc_w, tc_b, tcbn_s, tcbn_b, x, out);
    k_mp<<<(Nn * BCc * TV + 255) / 256, 256>>>(mpbn_s, mpbn_b, x, out);
}

// round 5
// speedup vs baseline: 1.1705x; 1.0152x over previous
#include <cuda_runtime.h>
#include <math.h>

#define Nn 32
#define Cc 96
#define Tt 256
#define Vv 25
#define Ss 3
#define RELr 12
#define OUTo 96
#define BCc 24
#define TV (Tt*Vv)   // 6400

typedef unsigned long long u64;

__device__ __forceinline__ u64 splat2(float x) {
    u64 r;
    asm("mov.b64 %0, {%1, %1};" : "=l"(r) : "f"(x));
    return r;
}
__device__ __forceinline__ void ffma2(u64& d, u64 a, u64 b) {
    asm("fma.rn.f32x2 %0, %1, %2, %0;" : "+l"(d) : "l"(a), "l"(b));
}
__device__ __forceinline__ void unpack2(float& lo, float& hi, u64 v) {
    asm("mov.b64 {%0, %1}, %2;" : "=f"(lo), "=f"(hi) : "l"(v));
}

// ---------------- scratch ----------------------------------------------------
__device__ float g_xm[Nn*Cc*Vv];
__device__ float g_A [(size_t)Nn*Ss*OUTo*Vv*Vv];
__device__ float g_x3[(size_t)Nn*Ss*OUTo*TV];
__device__ float g_y [(size_t)Nn*OUTo*TV];
__device__ float g_H0[(size_t)Nn*BCc*TV];
__device__ float g_H1[(size_t)Nn*BCc*TV];
__device__ float g_H2[(size_t)Nn*BCc*TV];

// ---------------- K1: mean over T --------------------------------------------
__global__ void k_xm(const float* __restrict__ x) {
    int nc = blockIdx.x;
    const float* xp = x + (size_t)nc * TV;
    float acc[Vv];
#pragma unroll
    for (int v = 0; v < Vv; v++) acc[v] = 0.f;
    for (int t = threadIdx.x; t < Tt; t += 128) {
        const float* row = xp + t * Vv;
#pragma unroll
        for (int v = 0; v < Vv; v++) acc[v] += row[v];
    }
    __shared__ float s[Vv][128];
#pragma unroll
    for (int v = 0; v < Vv; v++) s[v][threadIdx.x] = acc[v];
    __syncthreads();
    if (threadIdx.x < Vv) {
        float r = 0.f;
#pragma unroll 8
        for (int i = 0; i < 128; i++) r += s[threadIdx.x][i];
        g_xm[nc * Vv + threadIdx.x] = r * (1.f / Tt);
    }
}

// ---------------- K2: CTRGC relation -> A_at ---------------------------------
__global__ void k_rel(const float* __restrict__ spd, const float* __restrict__ A3,
                      const float* __restrict__ A6,
                      const float* __restrict__ alpha, const float* __restrict__ beta,
                      const float* __restrict__ gamma,
                      const float* __restrict__ c1w, const float* __restrict__ c1b,
                      const float* __restrict__ c2w, const float* __restrict__ c2b,
                      const float* __restrict__ c4w, const float* __restrict__ c4b) {
    int n = blockIdx.x / Ss, s = blockIdx.x % Ss;
    int tid = threadIdx.x;
    __shared__ float xm_s[Cc * Vv];
    __shared__ float x1s[RELr * Vv];
    __shared__ float x2s[RELr * Vv];
    __shared__ float Rs[RELr * Vv * Vv];
    __shared__ float base_s[Vv * Vv];

    for (int i = tid; i < Cc * Vv; i += 256) xm_s[i] = g_xm[n * Cc * Vv + i];
    __syncthreads();

    for (int i = tid; i < 2 * RELr * Vv; i += 256) {
        int which = i / (RELr * Vv);
        int rv = i % (RELr * Vv);
        int r = rv / Vv, v = rv % Vv;
        const float* w = (which ? c2w : c1w) + (s * RELr + r) * Cc;
        float acc = (which ? c2b : c1b)[s * RELr + r];
#pragma unroll 8
        for (int c = 0; c < Cc; c++) acc += w[c] * xm_s[c * Vv + v];
        (which ? x2s : x1s)[rv] = acc;
    }
    __syncthreads();

    float ga = __ldg(gamma);
    for (int i = tid; i < RELr * Vv * Vv; i += 256) {
        int r = i / (Vv * Vv);
        int uv = i % (Vv * Vv);
        int u = uv / Vv, v = uv % Vv;
        Rs[i] = tanhf(x1s[r * Vv + u] - x2s[r * Vv + v]);
    }
    for (int i = tid; i < Vv * Vv; i += 256)
        base_s[i] = __ldg(&A3[s * 625 + i]) + __ldg(&spd[i]) * ga;
    __syncthreads();

    float al = __ldg(alpha), be = __ldg(beta);
    float* Aout = g_A + (size_t)(n * Ss + s) * OUTo * 625;
    for (int o = 0; o < OUTo; o++) {
        float w4[RELr];
#pragma unroll
        for (int r = 0; r < RELr; r++) w4[r] = __ldg(&c4w[(s * OUTo + o) * RELr + r]);
        float b4 = __ldg(&c4b[s * OUTo + o]);
        const float* A6o = A6 + (o % 6) * 625;
        for (int i = tid; i < 625; i += 256) {
            float m = b4;
#pragma unroll
            for (int r = 0; r < RELr; r++) m += w4[r] * Rs[r * 625 + i];
            Aout[(size_t)o * 625 + i] = m * al + base_s[i] + __ldg(&A6o[i]) * be;
        }
    }
}

// ---------------- GEMM: X tile staged ONCE, s-loop inside ---------------------
// Xs[96][128] (48KB) + Ws[96][98] (37.6KB) dynamic smem = 86.8KB.
template <int EPI>
__global__ void k_gemm96(const float* __restrict__ Wfull,
                         const float* __restrict__ xglob,
                         const float* __restrict__ bias,
                         const float* __restrict__ bn_s, const float* __restrict__ bn_b,
                         float* __restrict__ outbuf)
{
    extern __shared__ float sm[];
    float* Xs = sm;              // 96*128
    float* Ws = sm + 96 * 128;   // [kk*98 + r]

    int ct = blockIdx.x;
    int n  = blockIdx.z;
    int tid = threadIdx.x;
    int tx = tid & 15, ty = tid >> 4;

    const float* Xin = (EPI == 0) ? xglob : (const float*)g_y;
    const float* X = Xin + (size_t)n * Cc * TV + (size_t)ct * 128;

    // stage full X tile once
    for (int i4 = tid; i4 < 96 * 32; i4 += 256) {
        int kk = i4 >> 5, c4 = (i4 & 31) << 2;
        *(float4*)&Xs[kk * 128 + c4] = *(const float4*)&X[(size_t)kk * TV + c4];
    }

    const int SC = (EPI == 0) ? Ss : 1;
    for (int s = 0; s < SC; s++) {
        __syncthreads();   // Ws safe to overwrite; (s==0) also fences Xs? no—next sync does
        const float* W = Wfull + (size_t)s * 96 * 96;
        for (int i = tid; i < 96 * 96; i += 256) {
            int r = i / 96, kk = i - r * 96;
            Ws[kk * 98 + r] = W[i];
        }
        __syncthreads();   // Xs + Ws ready

        u64 acc2[3][8];
#pragma unroll
        for (int p = 0; p < 3; p++)
#pragma unroll
            for (int j = 0; j < 8; j++) acc2[p][j] = 0ull;

#pragma unroll 4
        for (int kk = 0; kk < 96; kk++) {
            u64 ap[3];
#pragma unroll
            for (int p = 0; p < 3; p++)
                ap[p] = *(const u64*)&Ws[kk * 98 + ty * 6 + 2 * p];
            float4 b0 = *(float4*)&Xs[kk * 128 + tx * 8];
            float4 b1 = *(float4*)&Xs[kk * 128 + tx * 8 + 4];
            u64 bs[8];
            bs[0] = splat2(b0.x); bs[1] = splat2(b0.y);
            bs[2] = splat2(b0.z); bs[3] = splat2(b0.w);
            bs[4] = splat2(b1.x); bs[5] = splat2(b1.y);
            bs[6] = splat2(b1.z); bs[7] = splat2(b1.w);
#pragma unroll
            for (int p = 0; p < 3; p++)
#pragma unroll
                for (int j = 0; j < 8; j++) ffma2(acc2[p][j], ap[p], bs[j]);
        }

        if (EPI == 0) {
            float* O = g_x3 + (size_t)(n * Ss + s) * 96 * TV + (size_t)ct * 128;
#pragma unroll
            for (int p = 0; p < 3; p++) {
                float v0[8], v1[8];
#pragma unroll
                for (int j = 0; j < 8; j++) unpack2(v0[j], v1[j], acc2[p][j]);
#pragma unroll
                for (int e = 0; e < 2; e++) {
                    int r = ty * 6 + 2 * p + e;
                    float bv = __ldg(&bias[s * 96 + r]);
                    float* vv = e ? v1 : v0;
                    float4 o0 = {vv[0] + bv, vv[1] + bv, vv[2] + bv, vv[3] + bv};
                    float4 o1 = {vv[4] + bv, vv[5] + bv, vv[6] + bv, vv[7] + bv};
                    *(float4*)&O[(size_t)r * TV + tx * 8]     = o0;
                    *(float4*)&O[(size_t)r * TV + tx * 8 + 4] = o1;
                }
            }
        } else {
#pragma unroll
            for (int p = 0; p < 3; p++) {
                float v0[8], v1[8];
#pragma unroll
                for (int j = 0; j < 8; j++) unpack2(v0[j], v1[j], acc2[p][j]);
#pragma unroll
                for (int e = 0; e < 2; e++) {
                    int r = ty * 6 + 2 * p + e;
                    int br = r / 24, bc = r % 24;
                    float bv = __ldg(&bias[r]);
                    float sc = __ldg(&bn_s[r]), sh = __ldg(&bn_b[r]);
                    float* vv = e ? v1 : v0;
                    int colg = ct * 128 + tx * 8;
                    float w[8];
#pragma unroll
                    for (int j = 0; j < 8; j++) {
                        float v = vv[j] + bv;
                        v = v * sc + sh;
                        if (br < 3) v = fmaxf(v, 0.f);
                        w[j] = v;
                    }
                    if (br < 3) {
                        size_t hidx = (size_t)(n * BCc + bc) * TV + colg;
                        float* dst = (br == 0) ? g_H0 : (br == 1) ? g_H1 : g_H2;
                        float4 q0 = {w[0], w[1], w[2], w[3]};
                        float4 q1 = {w[4], w[5], w[6], w[7]};
                        *(float4*)&dst[hidx]     = q0;
                        *(float4*)&dst[hidx + 4] = q1;
                    } else {
                        size_t oi = ((size_t)n * OUTo + 72 + bc) * TV + colg;
                        float4 r0 = *(const float4*)&xglob[oi];
                        float4 r1 = *(const float4*)&xglob[oi + 4];
                        float4 q0 = {fmaxf(w[0] + r0.x, 0.f), fmaxf(w[1] + r0.y, 0.f),
                                     fmaxf(w[2] + r0.z, 0.f), fmaxf(w[3] + r0.w, 0.f)};
                        float4 q1 = {fmaxf(w[4] + r1.x, 0.f), fmaxf(w[5] + r1.y, 0.f),
                                     fmaxf(w[6] + r1.z, 0.f), fmaxf(w[7] + r1.w, 0.f)};
                        *(float4*)&outbuf[oi]     = q0;
                        *(float4*)&outbuf[oi + 4] = q1;
                    }
                }
            }
        }
    }
}

// ---------------- K4: y = relu(bn(sum_s A_s @ x3_s) + x) ----------------------
__global__ void k_y(const float* __restrict__ x, const float* __restrict__ gbn_s,
                    const float* __restrict__ gbn_b) {
    int no = blockIdx.x;
    int n = no / OUTo, o = no % OUTo;
    int tid = threadIdx.x;        // 128

    __shared__ __align__(16) float As[Ss * Vv * 28];
    __shared__ __align__(16) float Xs[Vv * 257 + 7];

    for (int i = tid; i < Ss * 625; i += 128) {
        int s = i / 625;
        int rem = i - s * 625;
        int u = rem / 25, v = rem - u * 25;
        As[(s * 25 + v) * 28 + u] =
            g_A[(((size_t)(n * Ss + s)) * OUTo + o) * 625 + rem];
    }
    for (int i = tid; i < Ss * Vv * 3; i += 128) {
        int sv = i / 3, pu = 25 + i % 3;
        As[sv * 28 + pu] = 0.f;
    }

    u64 acc2[13][2];
#pragma unroll
    for (int p = 0; p < 13; p++) { acc2[p][0] = 0ull; acc2[p][1] = 0ull; }

    int t0 = tid, t1 = tid + 128;
#pragma unroll
    for (int s = 0; s < Ss; s++) {
        __syncthreads();
        const float* base = g_x3 + (((size_t)(n * Ss + s)) * OUTo + o) * TV;
        for (int l = tid * 4; l < TV; l += 512)
            *(float4*)&Xs[l] = *(const float4*)&base[l];
        __syncthreads();
        const float* A2 = As + s * Vv * 28;
#pragma unroll
        for (int v = 0; v < Vv; v++) {
            u64 xa = splat2(Xs[t0 * Vv + v]);
            u64 xb = splat2(Xs[t1 * Vv + v]);
            const float* ar = A2 + v * 28;
#pragma unroll
            for (int p = 0; p < 13; p++) {
                u64 ap = *(const u64*)&ar[2 * p];
                ffma2(acc2[p][0], ap, xa);
                ffma2(acc2[p][1], ap, xb);
            }
        }
    }

    float gs = __ldg(&gbn_s[o]), gb = __ldg(&gbn_b[o]);
    __syncthreads();
#pragma unroll
    for (int p = 0; p < 13; p++) {
        float lo0, hi0, lo1, hi1;
        unpack2(lo0, hi0, acc2[p][0]);
        unpack2(lo1, hi1, acc2[p][1]);
        int u = 2 * p;
        Xs[u * 257 + t0] = lo0 * gs + gb;
        Xs[u * 257 + t1] = lo1 * gs + gb;
        if (u + 1 < Vv) {
            Xs[(u + 1) * 257 + t0] = hi0 * gs + gb;
            Xs[(u + 1) * 257 + t1] = hi1 * gs + gb;
        }
    }
    __syncthreads();

    size_t obase = ((size_t)n * OUTo + o) * TV;
    const float* xo = x + obase;
    float* yo = g_y + obase;
    for (int l = tid * 4; l < TV; l += 512) {
        float4 r = *(const float4*)&xo[l];
        float rr[4] = {r.x, r.y, r.z, r.w};
        float w[4];
#pragma unroll
        for (int k = 0; k < 4; k++) {
            int idx = l + k;
            int tt = (int)(((unsigned)idx * 5243u) >> 17);
            int vv = idx - tt * 25;
            w[k] = fmaxf(Xs[vv * 257 + tt] + rr[k], 0.f);
        }
        float4 q = {w[0], w[1], w[2], w[3]};
        *(float4*)&yo[l] = q;
    }
}

// ---------------- K6: dilated temporal convs, smem-staged, both branches ------
// grid (16, Nn, 2). block 640. smem: Hs[24ic][24t][25v] + ws[24*24*5].
__global__ void k_tc2(const float* __restrict__ tcw, const float* __restrict__ tcb,
                      const float* __restrict__ tcbn_s, const float* __restrict__ tcbn_b,
                      const float* __restrict__ x, float* __restrict__ out) {
    extern __shared__ float sm[];
    float* Hs = sm;              // 24*600 = 14400
    float* ws = sm + 14400;      // 2880

    int br = blockIdx.z;         // 0 -> D=1, 1 -> D=2
    int n  = blockIdx.y;
    int t0 = blockIdx.x * 16;
    int tid = threadIdx.x;

    for (int i = tid; i < BCc * BCc * 5; i += 640)
        ws[i] = tcw[br * BCc * BCc * 5 + i];

    const float* H = (br == 0 ? g_H0 : g_H1) + (size_t)n * BCc * TV;
    int base = (t0 - 4) * 25;
    for (int i = tid; i < 24 * 600; i += 640) {
        int ic = i / 600;
        int rem = i - ic * 600;          // tt*25+v
        int tg25 = base + rem;
        float val = 0.f;
        if (tg25 >= 0 && tg25 < TV) val = H[(size_t)ic * TV + tg25];
        Hs[i] = val;
    }
    __syncthreads();
    if (tid >= BCc * Vv) return;
    int oc = tid / Vv, v = tid - oc * Vv;

    float bias = __ldg(&tcb[br * BCc + oc]);
    float sc = __ldg(&tcbn_s[br * BCc + oc]), sh = __ldg(&tcbn_b[br * BCc + oc]);

    float acc[16];
#pragma unroll
    for (int j = 0; j < 16; j++) acc[j] = bias;

    for (int ic = 0; ic < BCc; ic++) {
        float h[24];
        const float* hp = Hs + ic * 600 + v;
#pragma unroll
        for (int i = 0; i < 24; i++) h[i] = hp[i * 25];
        const float* wp = ws + (oc * BCc + ic) * 5;
        if (br == 0) {   // D=1: input t = t0+j + (k-2) -> h[j+k+2]
#pragma unroll
            for (int k = 0; k < 5; k++) {
                float wv = wp[k];
#pragma unroll
                for (int j = 0; j < 16; j++) acc[j] += wv * h[j + k + 2];
            }
        } else {         // D=2: input t = t0+j + 2(k-2) -> h[j+2k]
#pragma unroll
            for (int k = 0; k < 5; k++) {
                float wv = wp[k];
#pragma unroll
                for (int j = 0; j < 16; j++) acc[j] += wv * h[j + 2 * k];
            }
        }
    }

#pragma unroll
    for (int j = 0; j < 16; j++) {
        int tg = t0 + j;
        size_t oi = ((size_t)n * OUTo + br * BCc + oc) * TV + (size_t)tg * Vv + v;
        out[oi] = fmaxf(acc[j] * sc + sh + __ldg(&x[oi]), 0.f);
    }
}

// ---------------- K7: maxpool branch -----------------------------------------
__global__ void k_mp(const float* __restrict__ mpbn_s, const float* __restrict__ mpbn_b,
                     const float* __restrict__ x, float* __restrict__ out) {
    int idx = blockIdx.x * 256 + threadIdx.x;
    if (idx >= Nn * BCc * TV) return;
    int v = idx % Vv;
    int t = (idx / Vv) % Tt;
    int bc = (idx / TV) % BCc;
    int n = idx / (TV * BCc);
    const float* H = g_H2 + (size_t)(n * BCc + bc) * TV;
    float m = H[t * Vv + v];
    if (t > 0)   m = fmaxf(m, H[(t - 1) * Vv + v]);
    if (t < 255) m = fmaxf(m, H[(t + 1) * Vv + v]);
    float val = m * __ldg(&mpbn_s[bc]) + __ldg(&mpbn_b[bc]);
    size_t oi = ((size_t)n * OUTo + 48 + bc) * TV + (size_t)t * Vv + v;
    out[oi] = fmaxf(val + __ldg(&x[oi]), 0.f);
}

// ---------------- driver ------------------------------------------------------
#define GEMM_SMEM ((96*128 + 96*98) * 4)
#define TC_SMEM   ((24*600 + 24*24*5) * 4)

extern "C" void kernel_launch(void* const* d_in, const int* in_sizes, int n_in,
                              void* d_out, int out_size) {
    const float* x      = (const float*)d_in[0];
    const float* spd_A  = (const float*)d_in[1];
    const float* A3     = (const float*)d_in[2];
    const float* A6     = (const float*)d_in[3];
    const float* alpha  = (const float*)d_in[4];
    const float* beta   = (const float*)d_in[5];
    const float* gamma  = (const float*)d_in[6];
    const float* c1_w   = (const float*)d_in[7];
    const float* c1_b   = (const float*)d_in[8];
    const float* c2_w   = (const float*)d_in[9];
    const float* c2_b   = (const float*)d_in[10];
    const float* c4_w   = (const float*)d_in[11];
    const float* c4_b   = (const float*)d_in[12];
    const float* c3_w   = (const float*)d_in[13];
    const float* c3_b   = (const float*)d_in[14];
    const float* gbn_s  = (const float*)d_in[15];
    const float* gbn_b  = (const float*)d_in[16];
    const float* pw_w   = (const float*)d_in[17];
    const float* pw_b   = (const float*)d_in[18];
    const float* pwbn_s = (const float*)d_in[19];
    const float* pwbn_b = (const float*)d_in[20];
    const float* tc_w   = (const float*)d_in[21];
    const float* tc_b   = (const float*)d_in[22];
    const float* tcbn_s = (const float*)d_in[23];
    const float* tcbn_b = (const float*)d_in[24];
    const float* mpbn_s = (const float*)d_in[25];
    const float* mpbn_b = (const float*)d_in[26];
    float* out = (float*)d_out;

    cudaFuncSetAttribute(k_gemm96<0>, cudaFuncAttributeMaxDynamicSharedMemorySize, GEMM_SMEM);
    cudaFuncSetAttribute(k_gemm96<1>, cudaFuncAttributeMaxDynamicSharedMemorySize, GEMM_SMEM);
    cudaFuncSetAttribute(k_tc2,       cudaFuncAttributeMaxDynamicSharedMemorySize, TC_SMEM);

    k_xm<<<Nn * Cc, 128>>>(x);
    k_rel<<<Nn * Ss, 256>>>(spd_A, A3, A6, alpha, beta, gamma,
                            c1_w, c1_b, c2_w, c2_b, c4_w, c4_b);
    k_gemm96<0><<<dim3(50, 1, Nn), 256, GEMM_SMEM>>>(c3_w, x, c3_b, nullptr, nullptr, nullptr);
    k_y<<<Nn * OUTo, 128>>>(x, gbn_s, gbn_b);
    k_gemm96<1><<<dim3(50, 1, Nn), 256, GEMM_SMEM>>>(pw_w, x, pw_b, pwbn_s, pwbn_b, out);
    k_tc2<<<dim3(16, Nn, 2), 640, TC_SMEM>>>(tc_w, tc_b, tcbn_s, tcbn_b, x, out);
    k_mp<<<(Nn * BCc * TV + 255) / 256, 256>>>(mpbn_s, mpbn_b, x, out);
}

// round 6
// speedup vs baseline: 1.2013x; 1.0264x over previous
#include <cuda_runtime.h>
#include <cuda_fp16.h>
#include <math.h>

#define Nn 32
#define Cc 96
#define Tt 256
#define Vv 25
#define Ss 3
#define RELr 12
#define OUTo 96
#define BCc 24
#define TV (Tt*Vv)   // 6400

typedef unsigned long long u64;

__device__ __forceinline__ u64 splat2(float x) {
    u64 r;
    asm("mov.b64 %0, {%1, %1};" : "=l"(r) : "f"(x));
    return r;
}
__device__ __forceinline__ void ffma2(u64& d, u64 a, u64 b) {
    asm("fma.rn.f32x2 %0, %1, %2, %0;" : "+l"(d) : "l"(a), "l"(b));
}
__device__ __forceinline__ void unpack2(float& lo, float& hi, u64 v) {
    asm("mov.b64 {%0, %1}, %2;" : "=f"(lo), "=f"(hi) : "l"(v));
}

// ---------------- scratch ----------------------------------------------------
__device__ float  g_xm[Nn*Cc*Vv];
__device__ float  g_A [(size_t)Nn*Ss*OUTo*Vv*Vv];
__device__ __half g_x3[(size_t)Nn*Ss*OUTo*TV];      // fp16 intermediate
__device__ float  g_y [(size_t)Nn*OUTo*TV];
__device__ float  g_H0[(size_t)Nn*BCc*TV];
__device__ float  g_H1[(size_t)Nn*BCc*TV];
__device__ float  g_H2[(size_t)Nn*BCc*TV];

// ---------------- K1: mean over T (split into two launches for profiling) ----
__global__ void k_xm(const float* __restrict__ x, int nc0) {
    int nc = nc0 + blockIdx.x;
    const float* xp = x + (size_t)nc * TV;
    float acc[Vv];
#pragma unroll
    for (int v = 0; v < Vv; v++) acc[v] = 0.f;
    for (int t = threadIdx.x; t < Tt; t += 128) {
        const float* row = xp + t * Vv;
#pragma unroll
        for (int v = 0; v < Vv; v++) acc[v] += row[v];
    }
    __shared__ float s[Vv][128];
#pragma unroll
    for (int v = 0; v < Vv; v++) s[v][threadIdx.x] = acc[v];
    __syncthreads();
    if (threadIdx.x < Vv) {
        float r = 0.f;
#pragma unroll 8
        for (int i = 0; i < 128; i++) r += s[threadIdx.x][i];
        g_xm[nc * Vv + threadIdx.x] = r * (1.f / Tt);
    }
}

// ---------------- K2: CTRGC relation -> A_at ---------------------------------
__global__ void k_rel(const float* __restrict__ spd, const float* __restrict__ A3,
                      const float* __restrict__ A6,
                      const float* __restrict__ alpha, const float* __restrict__ beta,
                      const float* __restrict__ gamma,
                      const float* __restrict__ c1w, const float* __restrict__ c1b,
                      const float* __restrict__ c2w, const float* __restrict__ c2b,
                      const float* __restrict__ c4w, const float* __restrict__ c4b) {
    int n = blockIdx.x / Ss, s = blockIdx.x % Ss;
    int tid = threadIdx.x;
    __shared__ float xm_s[Cc * Vv];
    __shared__ float x1s[RELr * Vv];
    __shared__ float x2s[RELr * Vv];
    __shared__ float Rs[RELr * Vv * Vv];
    __shared__ float base_s[Vv * Vv];

    for (int i = tid; i < Cc * Vv; i += 256) xm_s[i] = g_xm[n * Cc * Vv + i];
    __syncthreads();

    for (int i = tid; i < 2 * RELr * Vv; i += 256) {
        int which = i / (RELr * Vv);
        int rv = i % (RELr * Vv);
        int r = rv / Vv, v = rv % Vv;
        const float* w = (which ? c2w : c1w) + (s * RELr + r) * Cc;
        float acc = (which ? c2b : c1b)[s * RELr + r];
#pragma unroll 8
        for (int c = 0; c < Cc; c++) acc += w[c] * xm_s[c * Vv + v];
        (which ? x2s : x1s)[rv] = acc;
    }
    __syncthreads();

    float ga = __ldg(gamma);
    for (int i = tid; i < RELr * Vv * Vv; i += 256) {
        int r = i / (Vv * Vv);
        int uv = i % (Vv * Vv);
        int u = uv / Vv, v = uv % Vv;
        Rs[i] = tanhf(x1s[r * Vv + u] - x2s[r * Vv + v]);
    }
    for (int i = tid; i < Vv * Vv; i += 256)
        base_s[i] = __ldg(&A3[s * 625 + i]) + __ldg(&spd[i]) * ga;
    __syncthreads();

    float al = __ldg(alpha), be = __ldg(beta);
    float* Aout = g_A + (size_t)(n * Ss + s) * OUTo * 625;
    for (int o = 0; o < OUTo; o++) {
        float w4[RELr];
#pragma unroll
        for (int r = 0; r < RELr; r++) w4[r] = __ldg(&c4w[(s * OUTo + o) * RELr + r]);
        float b4 = __ldg(&c4b[s * OUTo + o]);
        const float* A6o = A6 + (o % 6) * 625;
        for (int i = tid; i < 625; i += 256) {
            float m = b4;
#pragma unroll
            for (int r = 0; r < RELr; r++) m += w4[r] * Rs[r * 625 + i];
            Aout[(size_t)o * 625 + i] = m * al + base_s[i] + __ldg(&A6o[i]) * be;
        }
    }
}

// ---------------- GEMM: X tile staged ONCE, s-loop inside ---------------------
template <int EPI>
__global__ void k_gemm96(const float* __restrict__ Wfull,
                         const float* __restrict__ xglob,
                         const float* __restrict__ bias,
                         const float* __restrict__ bn_s, const float* __restrict__ bn_b,
                         float* __restrict__ outbuf)
{
    extern __shared__ float sm[];
    float* Xs = sm;              // 96*128
    float* Ws = sm + 96 * 128;   // [kk*98 + r]

    int ct = blockIdx.x;
    int n  = blockIdx.z;
    int tid = threadIdx.x;
    int tx = tid & 15, ty = tid >> 4;

    const float* Xin = (EPI == 0) ? xglob : (const float*)g_y;
    const float* X = Xin + (size_t)n * Cc * TV + (size_t)ct * 128;

    for (int i4 = tid; i4 < 96 * 32; i4 += 256) {
        int kk = i4 >> 5, c4 = (i4 & 31) << 2;
        *(float4*)&Xs[kk * 128 + c4] = *(const float4*)&X[(size_t)kk * TV + c4];
    }

    const int SC = (EPI == 0) ? Ss : 1;
    for (int s = 0; s < SC; s++) {
        __syncthreads();
        const float* W = Wfull + (size_t)s * 96 * 96;
        for (int i = tid; i < 96 * 96; i += 256) {
            int r = i / 96, kk = i - r * 96;
            Ws[kk * 98 + r] = W[i];
        }
        __syncthreads();

        u64 acc2[3][8];
#pragma unroll
        for (int p = 0; p < 3; p++)
#pragma unroll
            for (int j = 0; j < 8; j++) acc2[p][j] = 0ull;

#pragma unroll 4
        for (int kk = 0; kk < 96; kk++) {
            u64 ap[3];
#pragma unroll
            for (int p = 0; p < 3; p++)
                ap[p] = *(const u64*)&Ws[kk * 98 + ty * 6 + 2 * p];
            float4 b0 = *(float4*)&Xs[kk * 128 + tx * 8];
            float4 b1 = *(float4*)&Xs[kk * 128 + tx * 8 + 4];
            u64 bs[8];
            bs[0] = splat2(b0.x); bs[1] = splat2(b0.y);
            bs[2] = splat2(b0.z); bs[3] = splat2(b0.w);
            bs[4] = splat2(b1.x); bs[5] = splat2(b1.y);
            bs[6] = splat2(b1.z); bs[7] = splat2(b1.w);
#pragma unroll
            for (int p = 0; p < 3; p++)
#pragma unroll
                for (int j = 0; j < 8; j++) ffma2(acc2[p][j], ap[p], bs[j]);
        }

        if (EPI == 0) {
            __half* O = g_x3 + (size_t)(n * Ss + s) * 96 * TV + (size_t)ct * 128;
#pragma unroll
            for (int p = 0; p < 3; p++) {
                float v0[8], v1[8];
#pragma unroll
                for (int j = 0; j < 8; j++) unpack2(v0[j], v1[j], acc2[p][j]);
#pragma unroll
                for (int e = 0; e < 2; e++) {
                    int r = ty * 6 + 2 * p + e;
                    float bv = __ldg(&bias[s * 96 + r]);
                    float* vv = e ? v1 : v0;
                    __half2 h[4];
#pragma unroll
                    for (int q = 0; q < 4; q++)
                        h[q] = __floats2half2_rn(vv[2*q] + bv, vv[2*q+1] + bv);
                    *(uint4*)&O[(size_t)r * TV + tx * 8] = *(uint4*)h;
                }
            }
        } else {
#pragma unroll
            for (int p = 0; p < 3; p++) {
                float v0[8], v1[8];
#pragma unroll
                for (int j = 0; j < 8; j++) unpack2(v0[j], v1[j], acc2[p][j]);
#pragma unroll
                for (int e = 0; e < 2; e++) {
                    int r = ty * 6 + 2 * p + e;
                    int br = r / 24, bc = r % 24;
                    float bv = __ldg(&bias[r]);
                    float sc = __ldg(&bn_s[r]), sh = __ldg(&bn_b[r]);
                    float* vv = e ? v1 : v0;
                    int colg = ct * 128 + tx * 8;
                    float w[8];
#pragma unroll
                    for (int j = 0; j < 8; j++) {
                        float v = vv[j] + bv;
                        v = v * sc + sh;
                        if (br < 3) v = fmaxf(v, 0.f);
                        w[j] = v;
                    }
                    if (br < 3) {
                        size_t hidx = (size_t)(n * BCc + bc) * TV + colg;
                        float* dst = (br == 0) ? g_H0 : (br == 1) ? g_H1 : g_H2;
                        float4 q0 = {w[0], w[1], w[2], w[3]};
                        float4 q1 = {w[4], w[5], w[6], w[7]};
                        *(float4*)&dst[hidx]     = q0;
                        *(float4*)&dst[hidx + 4] = q1;
                    } else {
                        size_t oi = ((size_t)n * OUTo + 72 + bc) * TV + colg;
                        float4 r0 = *(const float4*)&xglob[oi];
                        float4 r1 = *(const float4*)&xglob[oi + 4];
                        float4 q0 = {fmaxf(w[0] + r0.x, 0.f), fmaxf(w[1] + r0.y, 0.f),
                                     fmaxf(w[2] + r0.z, 0.f), fmaxf(w[3] + r0.w, 0.f)};
                        float4 q1 = {fmaxf(w[4] + r1.x, 0.f), fmaxf(w[5] + r1.y, 0.f),
                                     fmaxf(w[6] + r1.z, 0.f), fmaxf(w[7] + r1.w, 0.f)};
                        *(float4*)&outbuf[oi]     = q0;
                        *(float4*)&outbuf[oi + 4] = q1;
                    }
                }
            }
        }
    }
}

// ---------------- K4: y = relu(bn(sum_s A_s @ x3_s) + x) ----------------------
__global__ void k_y(const float* __restrict__ x, const float* __restrict__ gbn_s,
                    const float* __restrict__ gbn_b) {
    int no = blockIdx.x;
    int n = no / OUTo, o = no % OUTo;
    int tid = threadIdx.x;        // 128

    __shared__ __align__(16) float As[Ss * Vv * 28];
    __shared__ __align__(16) float Xs[Vv * 257 + 7];

    for (int i = tid; i < Ss * 625; i += 128) {
        int s = i / 625;
        int rem = i - s * 625;
        int u = rem / 25, v = rem - u * 25;
        As[(s * 25 + v) * 28 + u] =
            g_A[(((size_t)(n * Ss + s)) * OUTo + o) * 625 + rem];
    }
    for (int i = tid; i < Ss * Vv * 3; i += 128) {
        int sv = i / 3, pu = 25 + i % 3;
        As[sv * 28 + pu] = 0.f;
    }

    u64 acc2[13][2];
#pragma unroll
    for (int p = 0; p < 13; p++) { acc2[p][0] = 0ull; acc2[p][1] = 0ull; }

    int t0 = tid, t1 = tid + 128;
#pragma unroll
    for (int s = 0; s < Ss; s++) {
        __syncthreads();
        const __half* base = g_x3 + (((size_t)(n * Ss + s)) * OUTo + o) * TV;
        for (int l = tid * 8; l < TV; l += 1024) {
            uint4 w = *(const uint4*)&base[l];
            const __half2* hp = (const __half2*)&w;
            float2 f0 = __half22float2(hp[0]);
            float2 f1 = __half22float2(hp[1]);
            float2 f2 = __half22float2(hp[2]);
            float2 f3 = __half22float2(hp[3]);
            float4 q0 = {f0.x, f0.y, f1.x, f1.y};
            float4 q1 = {f2.x, f2.y, f3.x, f3.y};
            *(float4*)&Xs[l]     = q0;
            *(float4*)&Xs[l + 4] = q1;
        }
        __syncthreads();
        const float* A2 = As + s * Vv * 28;
#pragma unroll
        for (int v = 0; v < Vv; v++) {
            u64 xa = splat2(Xs[t0 * Vv + v]);
            u64 xb = splat2(Xs[t1 * Vv + v]);
            const float* ar = A2 + v * 28;
#pragma unroll
            for (int p = 0; p < 13; p++) {
                u64 ap = *(const u64*)&ar[2 * p];
                ffma2(acc2[p][0], ap, xa);
                ffma2(acc2[p][1], ap, xb);
            }
        }
    }

    float gs = __ldg(&gbn_s[o]), gb = __ldg(&gbn_b[o]);
    __syncthreads();
#pragma unroll
    for (int p = 0; p < 13; p++) {
        float lo0, hi0, lo1, hi1;
        unpack2(lo0, hi0, acc2[p][0]);
        unpack2(lo1, hi1, acc2[p][1]);
        int u = 2 * p;
        Xs[u * 257 + t0] = lo0 * gs + gb;
        Xs[u * 257 + t1] = lo1 * gs + gb;
        if (u + 1 < Vv) {
            Xs[(u + 1) * 257 + t0] = hi0 * gs + gb;
            Xs[(u + 1) * 257 + t1] = hi1 * gs + gb;
        }
    }
    __syncthreads();

    size_t obase = ((size_t)n * OUTo + o) * TV;
    const float* xo = x + obase;
    float* yo = g_y + obase;
    for (int l = tid * 4; l < TV; l += 512) {
        float4 r = *(const float4*)&xo[l];
        float rr[4] = {r.x, r.y, r.z, r.w};
        float w[4];
#pragma unroll
        for (int k = 0; k < 4; k++) {
            int idx = l + k;
            int tt = (int)(((unsigned)idx * 5243u) >> 17);
            int vv = idx - tt * 25;
            w[k] = fmaxf(Xs[vv * 257 + tt] + rr[k], 0.f);
        }
        float4 q = {w[0], w[1], w[2], w[3]};
        *(float4*)&yo[l] = q;
    }
}

// ---------------- K6: dilated temporal convs ----------------------------------
__global__ void k_tc2(const float* __restrict__ tcw, const float* __restrict__ tcb,
                      const float* __restrict__ tcbn_s, const float* __restrict__ tcbn_b,
                      const float* __restrict__ x, float* __restrict__ out) {
    extern __shared__ float sm[];
    float* Hs = sm;              // 24*600
    float* ws = sm + 14400;      // 2880

    int br = blockIdx.z;
    int n  = blockIdx.y;
    int t0 = blockIdx.x * 16;
    int tid = threadIdx.x;

    for (int i = tid; i < BCc * BCc * 5; i += 640)
        ws[i] = tcw[br * BCc * BCc * 5 + i];

    const float* H = (br == 0 ? g_H0 : g_H1) + (size_t)n * BCc * TV;
    int base = (t0 - 4) * 25;
    for (int i = tid; i < 24 * 600; i += 640) {
        int ic = i / 600;
        int rem = i - ic * 600;
        int tg25 = base + rem;
        float val = 0.f;
        if (tg25 >= 0 && tg25 < TV) val = H[(size_t)ic * TV + tg25];
        Hs[i] = val;
    }
    __syncthreads();
    if (tid >= BCc * Vv) return;
    int oc = tid / Vv, v = tid - oc * Vv;

    float bias = __ldg(&tcb[br * BCc + oc]);
    float sc = __ldg(&tcbn_s[br * BCc + oc]), sh = __ldg(&tcbn_b[br * BCc + oc]);

    float acc[16];
#pragma unroll
    for (int j = 0; j < 16; j++) acc[j] = bias;

    for (int ic = 0; ic < BCc; ic++) {
        float h[24];
        const float* hp = Hs + ic * 600 + v;
#pragma unroll
        for (int i = 0; i < 24; i++) h[i] = hp[i * 25];
        const float* wp = ws + (oc * BCc + ic) * 5;
        if (br == 0) {
#pragma unroll
            for (int k = 0; k < 5; k++) {
                float wv = wp[k];
#pragma unroll
                for (int j = 0; j < 16; j++) acc[j] += wv * h[j + k + 2];
            }
        } else {
#pragma unroll
            for (int k = 0; k < 5; k++) {
                float wv = wp[k];
#pragma unroll
                for (int j = 0; j < 16; j++) acc[j] += wv * h[j + 2 * k];
            }
        }
    }

#pragma unroll
    for (int j = 0; j < 16; j++) {
        int tg = t0 + j;
        size_t oi = ((size_t)n * OUTo + br * BCc + oc) * TV + (size_t)tg * Vv + v;
        out[oi] = fmaxf(acc[j] * sc + sh + __ldg(&x[oi]), 0.f);
    }
}

// ---------------- K7: maxpool branch -----------------------------------------
__global__ void k_mp(const float* __restrict__ mpbn_s, const float* __restrict__ mpbn_b,
                     const float* __restrict__ x, float* __restrict__ out) {
    int idx = blockIdx.x * 256 + threadIdx.x;
    if (idx >= Nn * BCc * TV) return;
    int v = idx % Vv;
    int t = (idx / Vv) % Tt;
    int bc = (idx / TV) % BCc;
    int n = idx / (TV * BCc);
    const float* H = g_H2 + (size_t)(n * BCc + bc) * TV;
    float m = H[t * Vv + v];
    if (t > 0)   m = fmaxf(m, H[(t - 1) * Vv + v]);
    if (t < 255) m = fmaxf(m, H[(t + 1) * Vv + v]);
    float val = m * __ldg(&mpbn_s[bc]) + __ldg(&mpbn_b[bc]);
    size_t oi = ((size_t)n * OUTo + 48 + bc) * TV + (size_t)t * Vv + v;
    out[oi] = fmaxf(val + __ldg(&x[oi]), 0.f);
}

// ---------------- driver ------------------------------------------------------
#define GEMM_SMEM ((96*128 + 96*98) * 4)
#define TC_SMEM   ((24*600 + 24*24*5) * 4)

extern "C" void kernel_launch(void* const* d_in, const int* in_sizes, int n_in,
                              void* d_out, int out_size) {
    const float* x      = (const float*)d_in[0];
    const float* spd_A  = (const float*)d_in[1];
    const float* A3     = (const float*)d_in[2];
    const float* A6     = (const float*)d_in[3];
    const float* alpha  = (const float*)d_in[4];
    const float* beta   = (const float*)d_in[5];
    const float* gamma  = (const float*)d_in[6];
    const float* c1_w   = (const float*)d_in[7];
    const float* c1_b   = (const float*)d_in[8];
    const float* c2_w   = (const float*)d_in[9];
    const float* c2_b   = (const float*)d_in[10];
    const float* c4_w   = (const float*)d_in[11];
    const float* c4_b   = (const float*)d_in[12];
    const float* c3_w   = (const float*)d_in[13];
    const float* c3_b   = (const float*)d_in[14];
    const float* gbn_s  = (const float*)d_in[15];
    const float* gbn_b  = (const float*)d_in[16];
    const float* pw_w   = (const float*)d_in[17];
    const float* pw_b   = (const float*)d_in[18];
    const float* pwbn_s = (const float*)d_in[19];
    const float* pwbn_b = (const float*)d_in[20];
    const float* tc_w   = (const float*)d_in[21];
    const float* tc_b   = (const float*)d_in[22];
    const float* tcbn_s = (const float*)d_in[23];
    const float* tcbn_b = (const float*)d_in[24];
    const float* mpbn_s = (const float*)d_in[25];
    const float* mpbn_b = (const float*)d_in[26];
    float* out = (float*)d_out;

    cudaFuncSetAttribute(k_gemm96<0>, cudaFuncAttributeMaxDynamicSharedMemorySize, GEMM_SMEM);
    cudaFuncSetAttribute(k_gemm96<1>, cudaFuncAttributeMaxDynamicSharedMemorySize, GEMM_SMEM);
    cudaFuncSetAttribute(k_tc2,       cudaFuncAttributeMaxDynamicSharedMemorySize, TC_SMEM);

    // launch order chosen so k_gemm96<0> sits in the ncu capture slot (#4)
    k_xm<<<Nn * Cc / 2, 128>>>(x, 0);                 // 1
    k_xm<<<Nn * Cc / 2, 128>>>(x, Nn * Cc / 2);       // 2
    k_rel<<<Nn * Ss, 256>>>(spd_A, A3, A6, alpha, beta, gamma,
                            c1_w, c1_b, c2_w, c2_b, c4_w, c4_b);   // 3
    k_gemm96<0><<<dim3(50, 1, Nn), 256, GEMM_SMEM>>>(c3_w, x, c3_b,
                                                     nullptr, nullptr, nullptr);  // 4 <- profiled
    k_y<<<Nn * OUTo, 128>>>(x, gbn_s, gbn_b);                                     // 5
    k_gemm96<1><<<dim3(50, 1, Nn), 256, GEMM_SMEM>>>(pw_w, x, pw_b, pwbn_s, pwbn_b, out);
    k_tc2<<<dim3(16, Nn, 2), 640, TC_SMEM>>>(tc_w, tc_b, tcbn_s, tcbn_b, x, out);
    k_mp<<<(Nn * BCc * TV + 255) / 256, 256>>>(mpbn_s, mpbn_b, x, out);
}

// round 7
// speedup vs baseline: 1.3235x; 1.1017x over previous
#include <cuda_runtime.h>
#include <cuda_fp16.h>
#include <math.h>

#define Nn 32
#define Cc 96
#define Tt 256
#define Vv 25
#define Ss 3
#define RELr 12
#define OUTo 96
#define BCc 24
#define TV (Tt*Vv)   // 6400

typedef unsigned long long u64;

__device__ __forceinline__ u64 splat2(float x) {
    u64 r;
    asm("mov.b64 %0, {%1, %1};" : "=l"(r) : "f"(x));
    return r;
}
__device__ __forceinline__ void ffma2(u64& d, u64 a, u64 b) {
    asm("fma.rn.f32x2 %0, %1, %2, %0;" : "+l"(d) : "l"(a), "l"(b));
}
__device__ __forceinline__ void unpack2(float& lo, float& hi, u64 v) {
    asm("mov.b64 {%0, %1}, %2;" : "=f"(lo), "=f"(hi) : "l"(v));
}

// ---------------- scratch ----------------------------------------------------
__device__ float  g_xm[Nn*Cc*Vv];
__device__ float  g_A [(size_t)Nn*Ss*OUTo*Vv*Vv];
__device__ __half g_x3[(size_t)Nn*Ss*OUTo*TV];
__device__ float  g_y [(size_t)Nn*OUTo*TV];
__device__ float  g_H0[(size_t)Nn*BCc*TV];
__device__ float  g_H1[(size_t)Nn*BCc*TV];
__device__ float  g_H2[(size_t)Nn*BCc*TV];

// ---------------- K1: mean over T (split for ncu slot alignment) -------------
__global__ void k_xm(const float* __restrict__ x, int nc0) {
    int nc = nc0 + blockIdx.x;
    const float* xp = x + (size_t)nc * TV;
    float acc[Vv];
#pragma unroll
    for (int v = 0; v < Vv; v++) acc[v] = 0.f;
    for (int t = threadIdx.x; t < Tt; t += 128) {
        const float* row = xp + t * Vv;
#pragma unroll
        for (int v = 0; v < Vv; v++) acc[v] += row[v];
    }
    __shared__ float s[Vv][128];
#pragma unroll
    for (int v = 0; v < Vv; v++) s[v][threadIdx.x] = acc[v];
    __syncthreads();
    if (threadIdx.x < Vv) {
        float r = 0.f;
#pragma unroll 8
        for (int i = 0; i < 128; i++) r += s[threadIdx.x][i];
        g_xm[nc * Vv + threadIdx.x] = r * (1.f / Tt);
    }
}

// ---------------- K2: CTRGC relation -> A_at ---------------------------------
__global__ void k_rel(const float* __restrict__ spd, const float* __restrict__ A3,
                      const float* __restrict__ A6,
                      const float* __restrict__ alpha, const float* __restrict__ beta,
                      const float* __restrict__ gamma,
                      const float* __restrict__ c1w, const float* __restrict__ c1b,
                      const float* __restrict__ c2w, const float* __restrict__ c2b,
                      const float* __restrict__ c4w, const float* __restrict__ c4b) {
    int n = blockIdx.x / Ss, s = blockIdx.x % Ss;
    int tid = threadIdx.x;
    __shared__ float xm_s[Cc * Vv];
    __shared__ float x1s[RELr * Vv];
    __shared__ float x2s[RELr * Vv];
    __shared__ float Rs[RELr * Vv * Vv];
    __shared__ float base_s[Vv * Vv];

    for (int i = tid; i < Cc * Vv; i += 256) xm_s[i] = g_xm[n * Cc * Vv + i];
    __syncthreads();

    for (int i = tid; i < 2 * RELr * Vv; i += 256) {
        int which = i / (RELr * Vv);
        int rv = i % (RELr * Vv);
        int r = rv / Vv, v = rv % Vv;
        const float* w = (which ? c2w : c1w) + (s * RELr + r) * Cc;
        float acc = (which ? c2b : c1b)[s * RELr + r];
#pragma unroll 8
        for (int c = 0; c < Cc; c++) acc += w[c] * xm_s[c * Vv + v];
        (which ? x2s : x1s)[rv] = acc;
    }
    __syncthreads();

    float ga = __ldg(gamma);
    for (int i = tid; i < RELr * Vv * Vv; i += 256) {
        int r = i / (Vv * Vv);
        int uv = i % (Vv * Vv);
        int u = uv / Vv, v = uv % Vv;
        Rs[i] = tanhf(x1s[r * Vv + u] - x2s[r * Vv + v]);
    }
    for (int i = tid; i < Vv * Vv; i += 256)
        base_s[i] = __ldg(&A3[s * 625 + i]) + __ldg(&spd[i]) * ga;
    __syncthreads();

    float al = __ldg(alpha), be = __ldg(beta);
    float* Aout = g_A + (size_t)(n * Ss + s) * OUTo * 625;
    for (int o = 0; o < OUTo; o++) {
        float w4[RELr];
#pragma unroll
        for (int r = 0; r < RELr; r++) w4[r] = __ldg(&c4w[(s * OUTo + o) * RELr + r]);
        float b4 = __ldg(&c4b[s * OUTo + o]);
        const float* A6o = A6 + (o % 6) * 625;
        for (int i = tid; i < 625; i += 256) {
            float m = b4;
#pragma unroll
            for (int r = 0; r < RELr; r++) m += w4[r] * Rs[r * 625 + i];
            Aout[(size_t)o * 625 + i] = m * al + base_s[i] + __ldg(&A6o[i]) * be;
        }
    }
}

// ---------------- GEMM: 96x256 block tile, 12x8 thread tile, f32x2 ------------
// tx = tid&31 -> cols {tx*4..+3} and {128+tx*4..+3} (bank-conflict-free LDS.128)
// ty = tid>>5 -> rows ty*12..ty*12+11 (6 row-pairs)
template <int EPI>
__global__ void __launch_bounds__(256, 1)
k_gemm96(const float* __restrict__ Wfull,
         const float* __restrict__ xglob,
         const float* __restrict__ bias,
         const float* __restrict__ bn_s, const float* __restrict__ bn_b,
         float* __restrict__ outbuf)
{
    extern __shared__ float sm[];
    float* Xs = sm;              // 96*256
    float* Ws = sm + 96 * 256;   // [kk*98 + r]

    int ct = blockIdx.x;         // 0..24 (256-col tiles)
    int n  = blockIdx.z;
    int tid = threadIdx.x;
    int tx = tid & 31, ty = tid >> 5;

    const float* Xin = (EPI == 0) ? xglob : (const float*)g_y;
    const float* X = Xin + (size_t)n * Cc * TV + (size_t)ct * 256;

    // stage X tile once: 96 rows x 256 cols
    for (int i4 = tid; i4 < 96 * 64; i4 += 256) {
        int kk = i4 >> 6, c4 = (i4 & 63) << 2;
        *(float4*)&Xs[kk * 256 + c4] = *(const float4*)&X[(size_t)kk * TV + c4];
    }

    const int SC = (EPI == 0) ? Ss : 1;
    for (int s = 0; s < SC; s++) {
        __syncthreads();
        const float* W = Wfull + (size_t)s * 96 * 96;
        for (int i = tid; i < 96 * 96; i += 256) {
            int r = i / 96, kk = i - r * 96;
            Ws[kk * 98 + r] = W[i];
        }
        __syncthreads();

        u64 acc2[6][8];
#pragma unroll
        for (int p = 0; p < 6; p++)
#pragma unroll
            for (int j = 0; j < 8; j++) acc2[p][j] = 0ull;

#pragma unroll 4
        for (int kk = 0; kk < 96; kk++) {
            u64 ap[6];
#pragma unroll
            for (int p = 0; p < 6; p++)
                ap[p] = *(const u64*)&Ws[kk * 98 + ty * 12 + 2 * p];
            float4 b0 = *(float4*)&Xs[kk * 256 + tx * 4];
            float4 b1 = *(float4*)&Xs[kk * 256 + 128 + tx * 4];
            u64 bs[8];
            bs[0] = splat2(b0.x); bs[1] = splat2(b0.y);
            bs[2] = splat2(b0.z); bs[3] = splat2(b0.w);
            bs[4] = splat2(b1.x); bs[5] = splat2(b1.y);
            bs[6] = splat2(b1.z); bs[7] = splat2(b1.w);
#pragma unroll
            for (int p = 0; p < 6; p++)
#pragma unroll
                for (int j = 0; j < 8; j++) ffma2(acc2[p][j], ap[p], bs[j]);
        }

        if (EPI == 0) {
            __half* O = g_x3 + (size_t)(n * Ss + s) * 96 * TV + (size_t)ct * 256;
#pragma unroll
            for (int p = 0; p < 6; p++) {
                float v0[8], v1[8];
#pragma unroll
                for (int j = 0; j < 8; j++) unpack2(v0[j], v1[j], acc2[p][j]);
#pragma unroll
                for (int e = 0; e < 2; e++) {
                    int r = ty * 12 + 2 * p + e;
                    float bv = __ldg(&bias[s * 96 + r]);
                    float* vv = e ? v1 : v0;
                    __half2 h0[2], h1[2];
                    h0[0] = __floats2half2_rn(vv[0] + bv, vv[1] + bv);
                    h0[1] = __floats2half2_rn(vv[2] + bv, vv[3] + bv);
                    h1[0] = __floats2half2_rn(vv[4] + bv, vv[5] + bv);
                    h1[1] = __floats2half2_rn(vv[6] + bv, vv[7] + bv);
                    *(uint2*)&O[(size_t)r * TV + tx * 4]       = *(uint2*)h0;
                    *(uint2*)&O[(size_t)r * TV + 128 + tx * 4] = *(uint2*)h1;
                }
            }
        } else {
#pragma unroll
            for (int p = 0; p < 6; p++) {
                float v0[8], v1[8];
#pragma unroll
                for (int j = 0; j < 8; j++) unpack2(v0[j], v1[j], acc2[p][j]);
#pragma unroll
                for (int e = 0; e < 2; e++) {
                    int r = ty * 12 + 2 * p + e;
                    int br = r / 24, bc = r % 24;
                    float bv = __ldg(&bias[r]);
                    float sc = __ldg(&bn_s[r]), sh = __ldg(&bn_b[r]);
                    float* vv = e ? v1 : v0;
                    float w[8];
#pragma unroll
                    for (int j = 0; j < 8; j++) {
                        float v = vv[j] + bv;
                        v = v * sc + sh;
                        if (br < 3) v = fmaxf(v, 0.f);
                        w[j] = v;
                    }
                    int c0 = ct * 256 + tx * 4;          // first 4 cols
                    int c1 = c0 + 128;                   // second 4 cols
                    if (br < 3) {
                        size_t hbase = (size_t)(n * BCc + bc) * TV;
                        float* dst = (br == 0) ? g_H0 : (br == 1) ? g_H1 : g_H2;
                        float4 q0 = {w[0], w[1], w[2], w[3]};
                        float4 q1 = {w[4], w[5], w[6], w[7]};
                        *(float4*)&dst[hbase + c0] = q0;
                        *(float4*)&dst[hbase + c1] = q1;
                    } else {
                        size_t ob = ((size_t)n * OUTo + 72 + bc) * TV;
                        float4 r0 = *(const float4*)&xglob[ob + c0];
                        float4 r1 = *(const float4*)&xglob[ob + c1];
                        float4 q0 = {fmaxf(w[0] + r0.x, 0.f), fmaxf(w[1] + r0.y, 0.f),
                                     fmaxf(w[2] + r0.z, 0.f), fmaxf(w[3] + r0.w, 0.f)};
                        float4 q1 = {fmaxf(w[4] + r1.x, 0.f), fmaxf(w[5] + r1.y, 0.f),
                                     fmaxf(w[6] + r1.z, 0.f), fmaxf(w[7] + r1.w, 0.f)};
                        *(float4*)&outbuf[ob + c0] = q0;
                        *(float4*)&outbuf[ob + c1] = q1;
                    }
                }
            }
        }
    }
}

// ---------------- K4: y = relu(bn(sum_s A_s @ x3_s) + x) ----------------------
__global__ void k_y(const float* __restrict__ x, const float* __restrict__ gbn_s,
                    const float* __restrict__ gbn_b) {
    int no = blockIdx.x;
    int n = no / OUTo, o = no % OUTo;
    int tid = threadIdx.x;        // 128

    __shared__ __align__(16) float As[Ss * Vv * 28];
    __shared__ __align__(16) float Xs[Vv * 257 + 7];

    for (int i = tid; i < Ss * 625; i += 128) {
        int s = i / 625;
        int rem = i - s * 625;
        int u = rem / 25, v = rem - u * 25;
        As[(s * 25 + v) * 28 + u] =
            g_A[(((size_t)(n * Ss + s)) * OUTo + o) * 625 + rem];
    }
    for (int i = tid; i < Ss * Vv * 3; i += 128) {
        int sv = i / 3, pu = 25 + i % 3;
        As[sv * 28 + pu] = 0.f;
    }

    u64 acc2[13][2];
#pragma unroll
    for (int p = 0; p < 13; p++) { acc2[p][0] = 0ull; acc2[p][1] = 0ull; }

    int t0 = tid, t1 = tid + 128;
#pragma unroll
    for (int s = 0; s < Ss; s++) {
        __syncthreads();
        const __half* base = g_x3 + (((size_t)(n * Ss + s)) * OUTo + o) * TV;
        for (int l = tid * 8; l < TV; l += 1024) {
            uint4 w = *(const uint4*)&base[l];
            const __half2* hp = (const __half2*)&w;
            float2 f0 = __half22float2(hp[0]);
            float2 f1 = __half22float2(hp[1]);
            float2 f2 = __half22float2(hp[2]);
            float2 f3 = __half22float2(hp[3]);
            float4 q0 = {f0.x, f0.y, f1.x, f1.y};
            float4 q1 = {f2.x, f2.y, f3.x, f3.y};
            *(float4*)&Xs[l]     = q0;
            *(float4*)&Xs[l + 4] = q1;
        }
        __syncthreads();
        const float* A2 = As + s * Vv * 28;
#pragma unroll
        for (int v = 0; v < Vv; v++) {
            u64 xa = splat2(Xs[t0 * Vv + v]);
            u64 xb = splat2(Xs[t1 * Vv + v]);
            const float* ar = A2 + v * 28;
#pragma unroll
            for (int p = 0; p < 13; p++) {
                u64 ap = *(const u64*)&ar[2 * p];
                ffma2(acc2[p][0], ap, xa);
                ffma2(acc2[p][1], ap, xb);
            }
        }
    }

    float gs = __ldg(&gbn_s[o]), gb = __ldg(&gbn_b[o]);
    __syncthreads();
#pragma unroll
    for (int p = 0; p < 13; p++) {
        float lo0, hi0, lo1, hi1;
        unpack2(lo0, hi0, acc2[p][0]);
        unpack2(lo1, hi1, acc2[p][1]);
        int u = 2 * p;
        Xs[u * 257 + t0] = lo0 * gs + gb;
        Xs[u * 257 + t1] = lo1 * gs + gb;
        if (u + 1 < Vv) {
            Xs[(u + 1) * 257 + t0] = hi0 * gs + gb;
            Xs[(u + 1) * 257 + t1] = hi1 * gs + gb;
        }
    }
    __syncthreads();

    size_t obase = ((size_t)n * OUTo + o) * TV;
    const float* xo = x + obase;
    float* yo = g_y + obase;
    for (int l = tid * 4; l < TV; l += 512) {
        float4 r = *(const float4*)&xo[l];
        float rr[4] = {r.x, r.y, r.z, r.w};
        float w[4];
#pragma unroll
        for (int k = 0; k < 4; k++) {
            int idx = l + k;
            int tt = (int)(((unsigned)idx * 5243u) >> 17);
            int vv = idx - tt * 25;
            w[k] = fmaxf(Xs[vv * 257 + tt] + rr[k], 0.f);
        }
        float4 q = {w[0], w[1], w[2], w[3]};
        *(float4*)&yo[l] = q;
    }
}

// ---------------- K6: dilated temporal convs ----------------------------------
__global__ void k_tc2(const float* __restrict__ tcw, const float* __restrict__ tcb,
                      const float* __restrict__ tcbn_s, const float* __restrict__ tcbn_b,
                      const float* __restrict__ x, float* __restrict__ out) {
    extern __shared__ float sm[];
    float* Hs = sm;              // 24*600
    float* ws = sm + 14400;      // 2880

    int br = blockIdx.z;
    int n  = blockIdx.y;
    int t0 = blockIdx.x * 16;
    int tid = threadIdx.x;

    for (int i = tid; i < BCc * BCc * 5; i += 640)
        ws[i] = tcw[br * BCc * BCc * 5 + i];

    const float* H = (br == 0 ? g_H0 : g_H1) + (size_t)n * BCc * TV;
    int base = (t0 - 4) * 25;
    for (int i = tid; i < 24 * 600; i += 640) {
        int ic = i / 600;
        int rem = i - ic * 600;
        int tg25 = base + rem;
        float val = 0.f;
        if (tg25 >= 0 && tg25 < TV) val = H[(size_t)ic * TV + tg25];
        Hs[i] = val;
    }
    __syncthreads();
    if (tid >= BCc * Vv) return;
    int oc = tid / Vv, v = tid - oc * Vv;

    float bias = __ldg(&tcb[br * BCc + oc]);
    float sc = __ldg(&tcbn_s[br * BCc + oc]), sh = __ldg(&tcbn_b[br * BCc + oc]);

    float acc[16];
#pragma unroll
    for (int j = 0; j < 16; j++) acc[j] = bias;

    for (int ic = 0; ic < BCc; ic++) {
        float h[24];
        const float* hp = Hs + ic * 600 + v;
#pragma unroll
        for (int i = 0; i < 24; i++) h[i] = hp[i * 25];
        const float* wp = ws + (oc * BCc + ic) * 5;
        if (br == 0) {
#pragma unroll
            for (int k = 0; k < 5; k++) {
                float wv = wp[k];
#pragma unroll
                for (int j = 0; j < 16; j++) acc[j] += wv * h[j + k + 2];
            }
        } else {
#pragma unroll
            for (int k = 0; k < 5; k++) {
                float wv = wp[k];
#pragma unroll
                for (int j = 0; j < 16; j++) acc[j] += wv * h[j + 2 * k];
            }
        }
    }

#pragma unroll
    for (int j = 0; j < 16; j++) {
        int tg = t0 + j;
        size_t oi = ((size_t)n * OUTo + br * BCc + oc) * TV + (size_t)tg * Vv + v;
        out[oi] = fmaxf(acc[j] * sc + sh + __ldg(&x[oi]), 0.f);
    }
}

// ---------------- K7: maxpool branch -----------------------------------------
__global__ void k_mp(const float* __restrict__ mpbn_s, const float* __restrict__ mpbn_b,
                     const float* __restrict__ x, float* __restrict__ out) {
    int idx = blockIdx.x * 256 + threadIdx.x;
    if (idx >= Nn * BCc * TV) return;
    int v = idx % Vv;
    int t = (idx / Vv) % Tt;
    int bc = (idx / TV) % BCc;
    int n = idx / (TV * BCc);
    const float* H = g_H2 + (size_t)(n * BCc + bc) * TV;
    float m = H[t * Vv + v];
    if (t > 0)   m = fmaxf(m, H[(t - 1) * Vv + v]);
    if (t < 255) m = fmaxf(m, H[(t + 1) * Vv + v]);
    float val = m * __ldg(&mpbn_s[bc]) + __ldg(&mpbn_b[bc]);
    size_t oi = ((size_t)n * OUTo + 48 + bc) * TV + (size_t)t * Vv + v;
    out[oi] = fmaxf(val + __ldg(&x[oi]), 0.f);
}

// ---------------- driver ------------------------------------------------------
#define GEMM_SMEM ((96*256 + 96*98) * 4)
#define TC_SMEM   ((24*600 + 24*24*5) * 4)

extern "C" void kernel_launch(void* const* d_in, const int* in_sizes, int n_in,
                              void* d_out, int out_size) {
    const float* x      = (const float*)d_in[0];
    const float* spd_A  = (const float*)d_in[1];
    const float* A3     = (const float*)d_in[2];
    const float* A6     = (const float*)d_in[3];
    const float* alpha  = (const float*)d_in[4];
    const float* beta   = (const float*)d_in[5];
    const float* gamma  = (const float*)d_in[6];
    const float* c1_w   = (const float*)d_in[7];
    const float* c1_b   = (const float*)d_in[8];
    const float* c2_w   = (const float*)d_in[9];
    const float* c2_b   = (const float*)d_in[10];
    const float* c4_w   = (const float*)d_in[11];
    const float* c4_b   = (const float*)d_in[12];
    const float* c3_w   = (const float*)d_in[13];
    const float* c3_b   = (const float*)d_in[14];
    const float* gbn_s  = (const float*)d_in[15];
    const float* gbn_b  = (const float*)d_in[16];
    const float* pw_w   = (const float*)d_in[17];
    const float* pw_b   = (const float*)d_in[18];
    const float* pwbn_s = (const float*)d_in[19];
    const float* pwbn_b = (const float*)d_in[20];
    const float* tc_w   = (const float*)d_in[21];
    const float* tc_b   = (const float*)d_in[22];
    const float* tcbn_s = (const float*)d_in[23];
    const float* tcbn_b = (const float*)d_in[24];
    const float* mpbn_s = (const float*)d_in[25];
    const float* mpbn_b = (const float*)d_in[26];
    float* out = (float*)d_out;

    cudaFuncSetAttribute(k_gemm96<0>, cudaFuncAttributeMaxDynamicSharedMemorySize, GEMM_SMEM);
    cudaFuncSetAttribute(k_gemm96<1>, cudaFuncAttributeMaxDynamicSharedMemorySize, GEMM_SMEM);
    cudaFuncSetAttribute(k_tc2,       cudaFuncAttributeMaxDynamicSharedMemorySize, TC_SMEM);

    k_xm<<<Nn * Cc / 2, 128>>>(x, 0);                 // 1
    k_xm<<<Nn * Cc / 2, 128>>>(x, Nn * Cc / 2);       // 2
    k_rel<<<Nn * Ss, 256>>>(spd_A, A3, A6, alpha, beta, gamma,
                            c1_w, c1_b, c2_w, c2_b, c4_w, c4_b);   // 3
    k_gemm96<0><<<dim3(25, 1, Nn), 256, GEMM_SMEM>>>(c3_w, x, c3_b,
                                                     nullptr, nullptr, nullptr);  // 4 <- profiled
    k_y<<<Nn * OUTo, 128>>>(x, gbn_s, gbn_b);                                     // 5
    k_gemm96<1><<<dim3(25, 1, Nn), 256, GEMM_SMEM>>>(pw_w, x, pw_b, pwbn_s, pwbn_b, out);
    k_tc2<<<dim3(16, Nn, 2), 640, TC_SMEM>>>(tc_w, tc_b, tcbn_s, tcbn_b, x, out);
    k_mp<<<(Nn * BCc * TV + 255) / 256, 256>>>(mpbn_s, mpbn_b, x, out);
}

// round 9
// speedup vs baseline: 1.3713x; 1.0361x over previous
#include <cuda_runtime.h>
#include <cuda_fp16.h>
#include <math.h>
#include <stdint.h>
#include <mma.h>

using namespace nvcuda;

#define Nn 32
#define Cc 96
#define Tt 256
#define Vv 25
#define Ss 3
#define RELr 12
#define OUTo 96
#define BCc 24
#define TV (Tt*Vv)   // 6400

typedef unsigned long long u64;

__device__ __forceinline__ u64 splat2(float x) {
    u64 r;
    asm("mov.b64 %0, {%1, %1};" : "=l"(r) : "f"(x));
    return r;
}
__device__ __forceinline__ void ffma2(u64& d, u64 a, u64 b) {
    asm("fma.rn.f32x2 %0, %1, %2, %0;" : "+l"(d) : "l"(a), "l"(b));
}
__device__ __forceinline__ void unpack2(float& lo, float& hi, u64 v) {
    asm("mov.b64 {%0, %1}, %2;" : "=f"(lo), "=f"(hi) : "l"(v));
}

// ---------------- scratch ----------------------------------------------------
__device__ float  g_xm[Nn*Cc*Vv];
__device__ float  g_A [(size_t)Nn*Ss*OUTo*Vv*Vv];
__device__ __half g_x3[(size_t)Nn*Ss*OUTo*TV];
__device__ float  g_y [(size_t)Nn*OUTo*TV];
__device__ float  g_H0[(size_t)Nn*BCc*TV];
__device__ float  g_H1[(size_t)Nn*BCc*TV];
__device__ float  g_H2[(size_t)Nn*BCc*TV];

// ---------------- K1: mean over T (split for ncu slot alignment) -------------
__global__ void k_xm(const float* __restrict__ x, int nc0) {
    int nc = nc0 + blockIdx.x;
    const float* xp = x + (size_t)nc * TV;
    float acc[Vv];
#pragma unroll
    for (int v = 0; v < Vv; v++) acc[v] = 0.f;
    for (int t = threadIdx.x; t < Tt; t += 128) {
        const float* row = xp + t * Vv;
#pragma unroll
        for (int v = 0; v < Vv; v++) acc[v] += row[v];
    }
    __shared__ float s[Vv][128];
#pragma unroll
    for (int v = 0; v < Vv; v++) s[v][threadIdx.x] = acc[v];
    __syncthreads();
    if (threadIdx.x < Vv) {
        float r = 0.f;
#pragma unroll 8
        for (int i = 0; i < 128; i++) r += s[threadIdx.x][i];
        g_xm[nc * Vv + threadIdx.x] = r * (1.f / Tt);
    }
}

// ---------------- K2: CTRGC relation -> A_at ---------------------------------
__global__ void k_rel(const float* __restrict__ spd, const float* __restrict__ A3,
                      const float* __restrict__ A6,
                      const float* __restrict__ alpha, const float* __restrict__ beta,
                      const float* __restrict__ gamma,
                      const float* __restrict__ c1w, const float* __restrict__ c1b,
                      const float* __restrict__ c2w, const float* __restrict__ c2b,
                      const float* __restrict__ c4w, const float* __restrict__ c4b) {
    int n = blockIdx.x / Ss, s = blockIdx.x % Ss;
    int tid = threadIdx.x;
    __shared__ float xm_s[Cc * Vv];
    __shared__ float x1s[RELr * Vv];
    __shared__ float x2s[RELr * Vv];
    __shared__ float Rs[RELr * Vv * Vv];
    __shared__ float base_s[Vv * Vv];

    for (int i = tid; i < Cc * Vv; i += 256) xm_s[i] = g_xm[n * Cc * Vv + i];
    __syncthreads();

    for (int i = tid; i < 2 * RELr * Vv; i += 256) {
        int which = i / (RELr * Vv);
        int rv = i % (RELr * Vv);
        int r = rv / Vv, v = rv % Vv;
        const float* w = (which ? c2w : c1w) + (s * RELr + r) * Cc;
        float acc = (which ? c2b : c1b)[s * RELr + r];
#pragma unroll 8
        for (int c = 0; c < Cc; c++) acc += w[c] * xm_s[c * Vv + v];
        (which ? x2s : x1s)[rv] = acc;
    }
    __syncthreads();

    float ga = __ldg(gamma);
    for (int i = tid; i < RELr * Vv * Vv; i += 256) {
        int r = i / (Vv * Vv);
        int uv = i % (Vv * Vv);
        int u = uv / Vv, v = uv % Vv;
        Rs[i] = tanhf(x1s[r * Vv + u] - x2s[r * Vv + v]);
    }
    for (int i = tid; i < Vv * Vv; i += 256)
        base_s[i] = __ldg(&A3[s * 625 + i]) + __ldg(&spd[i]) * ga;
    __syncthreads();

    float al = __ldg(alpha), be = __ldg(beta);
    float* Aout = g_A + (size_t)(n * Ss + s) * OUTo * 625;
    for (int o = 0; o < OUTo; o++) {
        float w4[RELr];
#pragma unroll
        for (int r = 0; r < RELr; r++) w4[r] = __ldg(&c4w[(s * OUTo + o) * RELr + r]);
        float b4 = __ldg(&c4b[s * OUTo + o]);
        const float* A6o = A6 + (o % 6) * 625;
        for (int i = tid; i < 625; i += 256) {
            float m = b4;
#pragma unroll
            for (int r = 0; r < RELr; r++) m += w4[r] * Rs[r * 625 + i];
            Aout[(size_t)o * 625 + i] = m * al + base_s[i] + __ldg(&A6o[i]) * be;
        }
    }
}

// ---------------- K3: x3 via wmma (HMMA) --------------------------------------
// Per block (ct, n): D[o=96][c=128] = W_s[96][96] @ X[96][128], 3 s-iterations.
// A = Wh [o][k] fp16 row-major (ld 96). B = Xs [c][k] fp16 (col-major view, ld 104).
#define XS_LD 104
__global__ void __launch_bounds__(256, 2)
k_gemm0_wmma(const float* __restrict__ x, const float* __restrict__ Wg,
             const float* __restrict__ bias) {
    extern __shared__ char smc[];
    __half* Xs = (__half*)smc;                               // 128*104*2 = 26624
    __half* Wh = (__half*)(smc + 128 * XS_LD * 2);           // 96*96*2  = 18432
    float*  Ds = (float*)(smc + 128 * XS_LD * 2 + 96*96*2);  // 96*128*4 = 49152

    int ct = blockIdx.x;      // 0..49
    int n  = blockIdx.z;
    int tid = threadIdx.x;
    int wid = tid >> 5;

    // stage X^T (fp32 -> fp16), coalesced gmem reads
    const float* X = x + (size_t)n * Cc * TV + (size_t)ct * 128;
    for (int i = tid; i < 96 * 128; i += 256) {
        int k = i >> 7, c = i & 127;
        Xs[c * XS_LD + k] = __float2half(X[(size_t)k * TV + c]);
    }

    for (int s = 0; s < Ss; s++) {
        __syncthreads();            // Wh/Ds reuse barrier (also covers Xs on s=0)
        const float* W = Wg + (size_t)s * 96 * 96;
        for (int i = tid; i < 96 * 96; i += 256)
            Wh[i] = __float2half(W[i]);
        __syncthreads();

        for (int t = wid; t < 48; t += 8) {
            int ot = t >> 3, c8 = t & 7;
            wmma::fragment<wmma::accumulator, 16, 16, 16, float> d;
            wmma::fill_fragment(d, 0.f);
#pragma unroll
            for (int k = 0; k < 6; k++) {
                wmma::fragment<wmma::matrix_a, 16, 16, 16, __half, wmma::row_major> a;
                wmma::fragment<wmma::matrix_b, 16, 16, 16, __half, wmma::col_major> b;
                wmma::load_matrix_sync(a, Wh + ot * 16 * 96 + k * 16, 96);
                wmma::load_matrix_sync(b, Xs + c8 * 16 * XS_LD + k * 16, XS_LD);
                wmma::mma_sync(d, a, b, d);
            }
            wmma::store_matrix_sync(Ds + ot * 16 * 128 + c8 * 16, d, 128,
                                    wmma::mem_row_major);
        }
        __syncthreads();

        // epilogue: bias + fp16, half2 stores
        __half* O = g_x3 + ((size_t)(n * Ss + s) * OUTo) * TV + (size_t)ct * 128;
        for (int i2 = tid; i2 < 96 * 64; i2 += 256) {
            int r = i2 >> 6, c2 = (i2 & 63) << 1;
            float bv = __ldg(&bias[s * 96 + r]);
            __half2 h = __floats2half2_rn(Ds[r * 128 + c2] + bv,
                                          Ds[r * 128 + c2 + 1] + bv);
            *(__half2*)&O[(size_t)r * TV + c2] = h;
        }
    }
}

// ---------------- K5: pointwise convs (scalar f32x2 GEMM) ---------------------
__global__ void __launch_bounds__(256, 1)
k_gemm_pw(const float* __restrict__ Wfull,
          const float* __restrict__ xglob,
          const float* __restrict__ bias,
          const float* __restrict__ bn_s, const float* __restrict__ bn_b,
          float* __restrict__ outbuf)
{
    extern __shared__ float sm[];
    float* Xs = sm;              // 96*256
    float* Ws = sm + 96 * 256;   // [kk*98 + r]

    int ct = blockIdx.x;
    int n  = blockIdx.z;
    int tid = threadIdx.x;
    int tx = tid & 31, ty = tid >> 5;

    const float* X = (const float*)g_y + (size_t)n * Cc * TV + (size_t)ct * 256;

    for (int i4 = tid; i4 < 96 * 64; i4 += 256) {
        int kk = i4 >> 6, c4 = (i4 & 63) << 2;
        *(float4*)&Xs[kk * 256 + c4] = *(const float4*)&X[(size_t)kk * TV + c4];
    }
    for (int i = tid; i < 96 * 96; i += 256) {
        int r = i / 96, kk = i - r * 96;
        Ws[kk * 98 + r] = Wfull[i];
    }
    __syncthreads();

    u64 acc2[6][8];
#pragma unroll
    for (int p = 0; p < 6; p++)
#pragma unroll
        for (int j = 0; j < 8; j++) acc2[p][j] = 0ull;

#pragma unroll 4
    for (int kk = 0; kk < 96; kk++) {
        u64 ap[6];
#pragma unroll
        for (int p = 0; p < 6; p++)
            ap[p] = *(const u64*)&Ws[kk * 98 + ty * 12 + 2 * p];
        float4 b0 = *(float4*)&Xs[kk * 256 + tx * 4];
        float4 b1 = *(float4*)&Xs[kk * 256 + 128 + tx * 4];
        u64 bs[8];
        bs[0] = splat2(b0.x); bs[1] = splat2(b0.y);
        bs[2] = splat2(b0.z); bs[3] = splat2(b0.w);
        bs[4] = splat2(b1.x); bs[5] = splat2(b1.y);
        bs[6] = splat2(b1.z); bs[7] = splat2(b1.w);
#pragma unroll
        for (int p = 0; p < 6; p++)
#pragma unroll
            for (int j = 0; j < 8; j++) ffma2(acc2[p][j], ap[p], bs[j]);
    }

#pragma unroll
    for (int p = 0; p < 6; p++) {
        float v0[8], v1[8];
#pragma unroll
        for (int j = 0; j < 8; j++) unpack2(v0[j], v1[j], acc2[p][j]);
#pragma unroll
        for (int e = 0; e < 2; e++) {
            int r = ty * 12 + 2 * p + e;
            int br = r / 24, bc = r % 24;
            float bv = __ldg(&bias[r]);
            float sc = __ldg(&bn_s[r]), sh = __ldg(&bn_b[r]);
            float* vv = e ? v1 : v0;
            float w[8];
#pragma unroll
            for (int j = 0; j < 8; j++) {
                float v = vv[j] + bv;
                v = v * sc + sh;
                if (br < 3) v = fmaxf(v, 0.f);
                w[j] = v;
            }
            int c0 = ct * 256 + tx * 4;
            int c1 = c0 + 128;
            if (br < 3) {
                size_t hbase = (size_t)(n * BCc + bc) * TV;
                float* dst = (br == 0) ? g_H0 : (br == 1) ? g_H1 : g_H2;
                float4 q0 = {w[0], w[1], w[2], w[3]};
                float4 q1 = {w[4], w[5], w[6], w[7]};
                *(float4*)&dst[hbase + c0] = q0;
                *(float4*)&dst[hbase + c1] = q1;
            } else {
                size_t ob = ((size_t)n * OUTo + 72 + bc) * TV;
                float4 r0 = *(const float4*)&xglob[ob + c0];
                float4 r1 = *(const float4*)&xglob[ob + c1];
                float4 q0 = {fmaxf(w[0] + r0.x, 0.f), fmaxf(w[1] + r0.y, 0.f),
                             fmaxf(w[2] + r0.z, 0.f), fmaxf(w[3] + r0.w, 0.f)};
                float4 q1 = {fmaxf(w[4] + r1.x, 0.f), fmaxf(w[5] + r1.y, 0.f),
                             fmaxf(w[6] + r1.z, 0.f), fmaxf(w[7] + r1.w, 0.f)};
                *(float4*)&outbuf[ob + c0] = q0;
                *(float4*)&outbuf[ob + c1] = q1;
            }
        }
    }
}

// ---------------- K4: y = relu(bn(sum_s A_s @ x3_s) + x) ----------------------
__global__ void k_y(const float* __restrict__ x, const float* __restrict__ gbn_s,
                    const float* __restrict__ gbn_b) {
    int no = blockIdx.x;
    int n = no / OUTo, o = no % OUTo;
    int tid = threadIdx.x;        // 128

    __shared__ __align__(16) float As[Ss * Vv * 28];
    __shared__ __align__(16) float Xs[Vv * 257 + 7];

    for (int i = tid; i < Ss * 625; i += 128) {
        int s = i / 625;
        int rem = i - s * 625;
        int u = rem / 25, v = rem - u * 25;
        As[(s * 25 + v) * 28 + u] =
            g_A[(((size_t)(n * Ss + s)) * OUTo + o) * 625 + rem];
    }
    for (int i = tid; i < Ss * Vv * 3; i += 128) {
        int sv = i / 3, pu = 25 + i % 3;
        As[sv * 28 + pu] = 0.f;
    }

    u64 acc2[13][2];
#pragma unroll
    for (int p = 0; p < 13; p++) { acc2[p][0] = 0ull; acc2[p][1] = 0ull; }

    int t0 = tid, t1 = tid + 128;
#pragma unroll
    for (int s = 0; s < Ss; s++) {
        __syncthreads();
        const __half* base = g_x3 + (((size_t)(n * Ss + s)) * OUTo + o) * TV;
        for (int l = tid * 8; l < TV; l += 1024) {
            uint4 w = *(const uint4*)&base[l];
            const __half2* hp = (const __half2*)&w;
            float2 f0 = __half22float2(hp[0]);
            float2 f1 = __half22float2(hp[1]);
            float2 f2 = __half22float2(hp[2]);
            float2 f3 = __half22float2(hp[3]);
            float4 q0 = {f0.x, f0.y, f1.x, f1.y};
            float4 q1 = {f2.x, f2.y, f3.x, f3.y};
            *(float4*)&Xs[l]     = q0;
            *(float4*)&Xs[l + 4] = q1;
        }
        __syncthreads();
        const float* A2 = As + s * Vv * 28;
#pragma unroll
        for (int v = 0; v < Vv; v++) {
            u64 xa = splat2(Xs[t0 * Vv + v]);
            u64 xb = splat2(Xs[t1 * Vv + v]);
            const float* ar = A2 + v * 28;
#pragma unroll
            for (int p = 0; p < 13; p++) {
                u64 ap = *(const u64*)&ar[2 * p];
                ffma2(acc2[p][0], ap, xa);
                ffma2(acc2[p][1], ap, xb);
            }
        }
    }

    float gs = __ldg(&gbn_s[o]), gb = __ldg(&gbn_b[o]);
    __syncthreads();
#pragma unroll
    for (int p = 0; p < 13; p++) {
        float lo0, hi0, lo1, hi1;
        unpack2(lo0, hi0, acc2[p][0]);
        unpack2(lo1, hi1, acc2[p][1]);
        int u = 2 * p;
        Xs[u * 257 + t0] = lo0 * gs + gb;
        Xs[u * 257 + t1] = lo1 * gs + gb;
        if (u + 1 < Vv) {
            Xs[(u + 1) * 257 + t0] = hi0 * gs + gb;
            Xs[(u + 1) * 257 + t1] = hi1 * gs + gb;
        }
    }
    __syncthreads();

    size_t obase = ((size_t)n * OUTo + o) * TV;
    const float* xo = x + obase;
    float* yo = g_y + obase;
    for (int l = tid * 4; l < TV; l += 512) {
        float4 r = *(const float4*)&xo[l];
        float rr[4] = {r.x, r.y, r.z, r.w};
        float w[4];
#pragma unroll
        for (int k = 0; k < 4; k++) {
            int idx = l + k;
            int tt = (int)(((unsigned)idx * 5243u) >> 17);
            int vv = idx - tt * 25;
            w[k] = fmaxf(Xs[vv * 257 + tt] + rr[k], 0.f);
        }
        float4 q = {w[0], w[1], w[2], w[3]};
        *(float4*)&yo[l] = q;
    }
}

// ---------------- K6: dilated temporal convs ----------------------------------
__global__ void k_tc2(const float* __restrict__ tcw, const float* __restrict__ tcb,
                      const float* __restrict__ tcbn_s, const float* __restrict__ tcbn_b,
                      const float* __restrict__ x, float* __restrict__ out) {
    extern __shared__ float sm[];
    float* Hs = sm;              // 24*600
    float* ws = sm + 14400;      // 2880

    int br = blockIdx.z;
    int n  = blockIdx.y;
    int t0 = blockIdx.x * 16;
    int tid = threadIdx.x;

    for (int i = tid; i < BCc * BCc * 5; i += 640)
        ws[i] = tcw[br * BCc * BCc * 5 + i];

    const float* H = (br == 0 ? g_H0 : g_H1) + (size_t)n * BCc * TV;
    int base = (t0 - 4) * 25;
    for (int i = tid; i < 24 * 600; i += 640) {
        int ic = i / 600;
        int rem = i - ic * 600;
        int tg25 = base + rem;
        float val = 0.f;
        if (tg25 >= 0 && tg25 < TV) val = H[(size_t)ic * TV + tg25];
        Hs[i] = val;
    }
    __syncthreads();
    if (tid >= BCc * Vv) return;
    int oc = tid / Vv, v = tid - oc * Vv;

    float bias = __ldg(&tcb[br * BCc + oc]);
    float sc = __ldg(&tcbn_s[br * BCc + oc]), sh = __ldg(&tcbn_b[br * BCc + oc]);

    float acc[16];
#pragma unroll
    for (int j = 0; j < 16; j++) acc[j] = bias;

    for (int ic = 0; ic < BCc; ic++) {
        float h[24];
        const float* hp = Hs + ic * 600 + v;
#pragma unroll
        for (int i = 0; i < 24; i++) h[i] = hp[i * 25];
        const float* wp = ws + (oc * BCc + ic) * 5;
        if (br == 0) {
#pragma unroll
            for (int k = 0; k < 5; k++) {
                float wv = wp[k];
#pragma unroll
                for (int j = 0; j < 16; j++) acc[j] += wv * h[j + k + 2];
            }
        } else {
#pragma unroll
            for (int k = 0; k < 5; k++) {
                float wv = wp[k];
#pragma unroll
                for (int j = 0; j < 16; j++) acc[j] += wv * h[j + 2 * k];
            }
        }
    }

#pragma unroll
    for (int j = 0; j < 16; j++) {
        int tg = t0 + j;
        size_t oi = ((size_t)n * OUTo + br * BCc + oc) * TV + (size_t)tg * Vv + v;
        out[oi] = fmaxf(acc[j] * sc + sh + __ldg(&x[oi]), 0.f);
    }
}

// ---------------- K7: maxpool branch -----------------------------------------
__global__ void k_mp(const float* __restrict__ mpbn_s, const float* __restrict__ mpbn_b,
                     const float* __restrict__ x, float* __restrict__ out) {
    int idx = blockIdx.x * 256 + threadIdx.x;
    if (idx >= Nn * BCc * TV) return;
    int v = idx % Vv;
    int t = (idx / Vv) % Tt;
    int bc = (idx / TV) % BCc;
    int n = idx / (TV * BCc);
    const float* H = g_H2 + (size_t)(n * BCc + bc) * TV;
    float m = H[t * Vv + v];
    if (t > 0)   m = fmaxf(m, H[(t - 1) * Vv + v]);
    if (t < 255) m = fmaxf(m, H[(t + 1) * Vv + v]);
    float val = m * __ldg(&mpbn_s[bc]) + __ldg(&mpbn_b[bc]);
    size_t oi = ((size_t)n * OUTo + 48 + bc) * TV + (size_t)t * Vv + v;
    out[oi] = fmaxf(val + __ldg(&x[oi]), 0.f);
}

// ---------------- driver ------------------------------------------------------
#define GEMM0_SMEM (128*XS_LD*2 + 96*96*2 + 96*128*4)    // 94208
#define GEMMPW_SMEM ((96*256 + 96*98) * 4)
#define TC_SMEM   ((24*600 + 24*24*5) * 4)

extern "C" void kernel_launch(void* const* d_in, const int* in_sizes, int n_in,
                              void* d_out, int out_size) {
    const float* x      = (const float*)d_in[0];
    const float* spd_A  = (const float*)d_in[1];
    const float* A3     = (const float*)d_in[2];
    const float* A6     = (const float*)d_in[3];
    const float* alpha  = (const float*)d_in[4];
    const float* beta   = (const float*)d_in[5];
    const float* gamma  = (const float*)d_in[6];
    const float* c1_w   = (const float*)d_in[7];
    const float* c1_b   = (const float*)d_in[8];
    const float* c2_w   = (const float*)d_in[9];
    const float* c2_b   = (const float*)d_in[10];
    const float* c4_w   = (const float*)d_in[11];
    const float* c4_b   = (const float*)d_in[12];
    const float* c3_w   = (const float*)d_in[13];
    const float* c3_b   = (const float*)d_in[14];
    const float* gbn_s  = (const float*)d_in[15];
    const float* gbn_b  = (const float*)d_in[16];
    const float* pw_w   = (const float*)d_in[17];
    const float* pw_b   = (const float*)d_in[18];
    const float* pwbn_s = (const float*)d_in[19];
    const float* pwbn_b = (const float*)d_in[20];
    const float* tc_w   = (const float*)d_in[21];
    const float* tc_b   = (const float*)d_in[22];
    const float* tcbn_s = (const float*)d_in[23];
    const float* tcbn_b = (const float*)d_in[24];
    const float* mpbn_s = (const float*)d_in[25];
    const float* mpbn_b = (const float*)d_in[26];
    float* out = (float*)d_out;

    cudaFuncSetAttribute(k_gemm0_wmma, cudaFuncAttributeMaxDynamicSharedMemorySize, GEMM0_SMEM);
    cudaFuncSetAttribute(k_gemm_pw,    cudaFuncAttributeMaxDynamicSharedMemorySize, GEMMPW_SMEM);
    cudaFuncSetAttribute(k_tc2,        cudaFuncAttributeMaxDynamicSharedMemorySize, TC_SMEM);

    k_xm<<<Nn * Cc / 2, 128>>>(x, 0);                               // 1
    k_xm<<<Nn * Cc / 2, 128>>>(x, Nn * Cc / 2);                     // 2
    k_rel<<<Nn * Ss, 256>>>(spd_A, A3, A6, alpha, beta, gamma,
                            c1_w, c1_b, c2_w, c2_b, c4_w, c4_b);    // 3
    k_gemm0_wmma<<<dim3(50, 1, Nn), 256, GEMM0_SMEM>>>(x, c3_w, c3_b);  // 4 <- profiled
    k_y<<<Nn * OUTo, 128>>>(x, gbn_s, gbn_b);                       // 5
    k_gemm_pw<<<dim3(25, 1, Nn), 256, GEMMPW_SMEM>>>(pw_w, x, pw_b, pwbn_s, pwbn_b, out);
    k_tc2<<<dim3(16, Nn, 2), 640, TC_SMEM>>>(tc_w, tc_b, tcbn_s, tcbn_b, x, out);
    k_mp<<<(Nn * BCc * TV + 255) / 256, 256>>>(mpbn_s, mpbn_b, x, out);
}

// round 10
// speedup vs baseline: 1.6365x; 1.1934x over previous
#include <cuda_runtime.h>
#include <cuda_fp16.h>
#include <math.h>
#include <stdint.h>
#include <mma.h>

using namespace nvcuda;

#define Nn 32
#define Cc 96
#define Tt 256
#define Vv 25
#define Ss 3
#define RELr 12
#define OUTo 96
#define BCc 24
#define TV (Tt*Vv)   // 6400

typedef unsigned long long u64;

__device__ __forceinline__ u64 splat2(float x) {
    u64 r;
    asm("mov.b64 %0, {%1, %1};" : "=l"(r) : "f"(x));
    return r;
}
__device__ __forceinline__ void ffma2(u64& d, u64 a, u64 b) {
    asm("fma.rn.f32x2 %0, %1, %2, %0;" : "+l"(d) : "l"(a), "l"(b));
}
__device__ __forceinline__ void unpack2(float& lo, float& hi, u64 v) {
    asm("mov.b64 {%0, %1}, %2;" : "=f"(lo), "=f"(hi) : "l"(v));
}

// ---------------- scratch ----------------------------------------------------
__device__ float  g_xm[Nn*Cc*Vv];
__device__ float  g_A [(size_t)Nn*Ss*OUTo*Vv*Vv];
__device__ __half g_x3[(size_t)Nn*Ss*OUTo*TV];
__device__ float  g_y [(size_t)Nn*OUTo*TV];
__device__ __half g_yh[(size_t)Nn*OUTo*TV];
__device__ __half g_xh[(size_t)Nn*Cc*TV];
__device__ __half g_c3h[Ss*96*96];
__device__ __half g_pwh[96*96];
__device__ float  g_H0[(size_t)Nn*BCc*TV];
__device__ float  g_H1[(size_t)Nn*BCc*TV];
__device__ float  g_H2[(size_t)Nn*BCc*TV];

// ---------------- P0: x -> fp16 ----------------------------------------------
__global__ void k_prep_xh(const float* __restrict__ x) {
    size_t i = ((size_t)blockIdx.x * 256 + threadIdx.x) * 8;
    if (i >= (size_t)Nn * Cc * TV) return;
    float4 a = *(const float4*)&x[i];
    float4 b = *(const float4*)&x[i + 4];
    __half2 h[4];
    h[0] = __floats2half2_rn(a.x, a.y);
    h[1] = __floats2half2_rn(a.z, a.w);
    h[2] = __floats2half2_rn(b.x, b.y);
    h[3] = __floats2half2_rn(b.z, b.w);
    *(uint4*)&g_xh[i] = *(uint4*)h;
}

// ---------------- P1: weights -> fp16 -----------------------------------------
__global__ void k_prep_wh(const float* __restrict__ c3w, const float* __restrict__ pww) {
    for (int i = threadIdx.x + blockIdx.x * 256; i < Ss * 96 * 96 + 96 * 96;
         i += gridDim.x * 256) {
        if (i < Ss * 96 * 96) g_c3h[i] = __float2half(c3w[i]);
        else                  g_pwh[i - Ss * 96 * 96] = __float2half(pww[i - Ss * 96 * 96]);
    }
}

// ---------------- K1: mean over T --------------------------------------------
__global__ void k_xm(const float* __restrict__ x) {
    int nc = blockIdx.x;
    const float* xp = x + (size_t)nc * TV;
    float acc[Vv];
#pragma unroll
    for (int v = 0; v < Vv; v++) acc[v] = 0.f;
    for (int t = threadIdx.x; t < Tt; t += 128) {
        const float* row = xp + t * Vv;
#pragma unroll
        for (int v = 0; v < Vv; v++) acc[v] += row[v];
    }
    __shared__ float s[Vv][128];
#pragma unroll
    for (int v = 0; v < Vv; v++) s[v][threadIdx.x] = acc[v];
    __syncthreads();
    if (threadIdx.x < Vv) {
        float r = 0.f;
#pragma unroll 8
        for (int i = 0; i < 128; i++) r += s[threadIdx.x][i];
        g_xm[nc * Vv + threadIdx.x] = r * (1.f / Tt);
    }
}

// ---------------- K2: CTRGC relation -> A_at ---------------------------------
__global__ void k_rel(const float* __restrict__ spd, const float* __restrict__ A3,
                      const float* __restrict__ A6,
                      const float* __restrict__ alpha, const float* __restrict__ beta,
                      const float* __restrict__ gamma,
                      const float* __restrict__ c1w, const float* __restrict__ c1b,
                      const float* __restrict__ c2w, const float* __restrict__ c2b,
                      const float* __restrict__ c4w, const float* __restrict__ c4b) {
    int n = blockIdx.x / Ss, s = blockIdx.x % Ss;
    int tid = threadIdx.x;
    __shared__ float xm_s[Cc * Vv];
    __shared__ float x1s[RELr * Vv];
    __shared__ float x2s[RELr * Vv];
    __shared__ float Rs[RELr * Vv * Vv];
    __shared__ float base_s[Vv * Vv];

    for (int i = tid; i < Cc * Vv; i += 256) xm_s[i] = g_xm[n * Cc * Vv + i];
    __syncthreads();

    for (int i = tid; i < 2 * RELr * Vv; i += 256) {
        int which = i / (RELr * Vv);
        int rv = i % (RELr * Vv);
        int r = rv / Vv, v = rv % Vv;
        const float* w = (which ? c2w : c1w) + (s * RELr + r) * Cc;
        float acc = (which ? c2b : c1b)[s * RELr + r];
#pragma unroll 8
        for (int c = 0; c < Cc; c++) acc += w[c] * xm_s[c * Vv + v];
        (which ? x2s : x1s)[rv] = acc;
    }
    __syncthreads();

    float ga = __ldg(gamma);
    for (int i = tid; i < RELr * Vv * Vv; i += 256) {
        int r = i / (Vv * Vv);
        int uv = i % (Vv * Vv);
        int u = uv / Vv, v = uv % Vv;
        Rs[i] = tanhf(x1s[r * Vv + u] - x2s[r * Vv + v]);
    }
    for (int i = tid; i < Vv * Vv; i += 256)
        base_s[i] = __ldg(&A3[s * 625 + i]) + __ldg(&spd[i]) * ga;
    __syncthreads();

    float al = __ldg(alpha), be = __ldg(beta);
    float* Aout = g_A + (size_t)(n * Ss + s) * OUTo * 625;
    for (int o = 0; o < OUTo; o++) {
        float w4[RELr];
#pragma unroll
        for (int r = 0; r < RELr; r++) w4[r] = __ldg(&c4w[(s * OUTo + o) * RELr + r]);
        float b4 = __ldg(&c4b[s * OUTo + o]);
        const float* A6o = A6 + (o % 6) * 625;
        for (int i = tid; i < 625; i += 256) {
            float m = b4;
#pragma unroll
            for (int r = 0; r < RELr; r++) m += w4[r] * Rs[r * 625 + i];
            Aout[(size_t)o * 625 + i] = m * al + base_s[i] + __ldg(&A6o[i]) * be;
        }
    }
}

// ---------------- K3: x3 via wmma, operands direct from global ----------------
// block (ct, n): D[96][128] = W_s[96][96] @ Xh[96][128]. warp wid owns col-tile.
__global__ void __launch_bounds__(256, 3)
k_gemm0_wmma(const float* __restrict__ bias) {
    __shared__ float Ds[96 * 128];     // 48KB
    int ct = blockIdx.x;      // 0..49
    int n  = blockIdx.z;
    int tid = threadIdx.x;
    int wid = tid >> 5;       // 0..7 -> col tile

    const __half* Xg = g_xh + (size_t)n * Cc * TV + (size_t)ct * 128 + wid * 16;

    wmma::fragment<wmma::matrix_b, 16, 16, 16, __half, wmma::row_major> b[6];
#pragma unroll
    for (int k = 0; k < 6; k++)
        wmma::load_matrix_sync(b[k], Xg + (size_t)k * 16 * TV, TV);

    for (int s = 0; s < Ss; s++) {
        const __half* Wg = g_c3h + s * 96 * 96;
#pragma unroll
        for (int ot = 0; ot < 6; ot++) {
            wmma::fragment<wmma::accumulator, 16, 16, 16, float> d;
            wmma::fill_fragment(d, 0.f);
#pragma unroll
            for (int k = 0; k < 6; k++) {
                wmma::fragment<wmma::matrix_a, 16, 16, 16, __half, wmma::row_major> a;
                wmma::load_matrix_sync(a, Wg + ot * 16 * 96 + k * 16, 96);
                wmma::mma_sync(d, a, b[k], d);
            }
            wmma::store_matrix_sync(Ds + ot * 16 * 128 + wid * 16, d, 128,
                                    wmma::mem_row_major);
        }
        __syncthreads();
        __half* O = g_x3 + ((size_t)(n * Ss + s) * OUTo) * TV + (size_t)ct * 128;
        for (int i2 = tid; i2 < 96 * 64; i2 += 256) {
            int r = i2 >> 6, c2 = (i2 & 63) << 1;
            float bv = __ldg(&bias[s * 96 + r]);
            __half2 h = __floats2half2_rn(Ds[r * 128 + c2] + bv,
                                          Ds[r * 128 + c2 + 1] + bv);
            *(__half2*)&O[(size_t)r * TV + c2] = h;
        }
        __syncthreads();
    }
}

// ---------------- K5: pointwise convs via wmma --------------------------------
__global__ void __launch_bounds__(256, 3)
k_pw_wmma(const float* __restrict__ xglob, const float* __restrict__ bias,
          const float* __restrict__ bn_s, const float* __restrict__ bn_b,
          float* __restrict__ outbuf) {
    __shared__ float Ds[96 * 128];     // 48KB
    int ct = blockIdx.x;      // 0..49
    int n  = blockIdx.z;
    int tid = threadIdx.x;
    int wid = tid >> 5;

    const __half* Yg = g_yh + (size_t)n * Cc * TV + (size_t)ct * 128 + wid * 16;

    wmma::fragment<wmma::matrix_b, 16, 16, 16, __half, wmma::row_major> b[6];
#pragma unroll
    for (int k = 0; k < 6; k++)
        wmma::load_matrix_sync(b[k], Yg + (size_t)k * 16 * TV, TV);

#pragma unroll
    for (int ot = 0; ot < 6; ot++) {
        wmma::fragment<wmma::accumulator, 16, 16, 16, float> d;
        wmma::fill_fragment(d, 0.f);
#pragma unroll
        for (int k = 0; k < 6; k++) {
            wmma::fragment<wmma::matrix_a, 16, 16, 16, __half, wmma::row_major> a;
            wmma::load_matrix_sync(a, g_pwh + ot * 16 * 96 + k * 16, 96);
            wmma::mma_sync(d, a, b[k], d);
        }
        wmma::store_matrix_sync(Ds + ot * 16 * 128 + wid * 16, d, 128,
                                wmma::mem_row_major);
    }
    __syncthreads();

    // epilogue: bias + BN (+relu / residual) to H0/H1/H2 and out
    for (int i2 = tid; i2 < 96 * 64; i2 += 256) {
        int r = i2 >> 6, c2 = (i2 & 63) << 1;
        int br = r / 24, bc = r % 24;
        float bv = __ldg(&bias[r]);
        float sc = __ldg(&bn_s[r]), sh = __ldg(&bn_b[r]);
        float v0 = (Ds[r * 128 + c2]     + bv) * sc + sh;
        float v1 = (Ds[r * 128 + c2 + 1] + bv) * sc + sh;
        int colg = ct * 128 + c2;
        if (br < 3) {
            v0 = fmaxf(v0, 0.f); v1 = fmaxf(v1, 0.f);
            float* dst = (br == 0) ? g_H0 : (br == 1) ? g_H1 : g_H2;
            float2 q = {v0, v1};
            *(float2*)&dst[(size_t)(n * BCc + bc) * TV + colg] = q;
        } else {
            size_t oi = ((size_t)n * OUTo + 72 + bc) * TV + colg;
            float2 rx = *(const float2*)&xglob[oi];
            float2 q = {fmaxf(v0 + rx.x, 0.f), fmaxf(v1 + rx.y, 0.f)};
            *(float2*)&outbuf[oi] = q;
        }
    }
}

// ---------------- K4: y = relu(bn(sum_s A_s @ x3_s) + x) ----------------------
__global__ void k_y(const float* __restrict__ x, const float* __restrict__ gbn_s,
                    const float* __restrict__ gbn_b) {
    int no = blockIdx.x;
    int n = no / OUTo, o = no % OUTo;
    int tid = threadIdx.x;        // 128

    __shared__ __align__(16) float As[Ss * Vv * 28];
    __shared__ __align__(16) float Xs[Vv * 257 + 7];

    for (int i = tid; i < Ss * 625; i += 128) {
        int s = i / 625;
        int rem = i - s * 625;
        int u = rem / 25, v = rem - u * 25;
        As[(s * 25 + v) * 28 + u] =
            g_A[(((size_t)(n * Ss + s)) * OUTo + o) * 625 + rem];
    }
    for (int i = tid; i < Ss * Vv * 3; i += 128) {
        int sv = i / 3, pu = 25 + i % 3;
        As[sv * 28 + pu] = 0.f;
    }

    u64 acc2[13][2];
#pragma unroll
    for (int p = 0; p < 13; p++) { acc2[p][0] = 0ull; acc2[p][1] = 0ull; }

    int t0 = tid, t1 = tid + 128;
#pragma unroll
    for (int s = 0; s < Ss; s++) {
        __syncthreads();
        const __half* base = g_x3 + (((size_t)(n * Ss + s)) * OUTo + o) * TV;
        for (int l = tid * 8; l < TV; l += 1024) {
            uint4 w = *(const uint4*)&base[l];
            const __half2* hp = (const __half2*)&w;
            float2 f0 = __half22float2(hp[0]);
            float2 f1 = __half22float2(hp[1]);
            float2 f2 = __half22float2(hp[2]);
            float2 f3 = __half22float2(hp[3]);
            float4 q0 = {f0.x, f0.y, f1.x, f1.y};
            float4 q1 = {f2.x, f2.y, f3.x, f3.y};
            *(float4*)&Xs[l]     = q0;
            *(float4*)&Xs[l + 4] = q1;
        }
        __syncthreads();
        const float* A2 = As + s * Vv * 28;
#pragma unroll
        for (int v = 0; v < Vv; v++) {
            u64 xa = splat2(Xs[t0 * Vv + v]);
            u64 xb = splat2(Xs[t1 * Vv + v]);
            const float* ar = A2 + v * 28;
#pragma unroll
            for (int p = 0; p < 13; p++) {
                u64 ap = *(const u64*)&ar[2 * p];
                ffma2(acc2[p][0], ap, xa);
                ffma2(acc2[p][1], ap, xb);
            }
        }
    }

    float gs = __ldg(&gbn_s[o]), gb = __ldg(&gbn_b[o]);
    __syncthreads();
#pragma unroll
    for (int p = 0; p < 13; p++) {
        float lo0, hi0, lo1, hi1;
        unpack2(lo0, hi0, acc2[p][0]);
        unpack2(lo1, hi1, acc2[p][1]);
        int u = 2 * p;
        Xs[u * 257 + t0] = lo0 * gs + gb;
        Xs[u * 257 + t1] = lo1 * gs + gb;
        if (u + 1 < Vv) {
            Xs[(u + 1) * 257 + t0] = hi0 * gs + gb;
            Xs[(u + 1) * 257 + t1] = hi1 * gs + gb;
        }
    }
    __syncthreads();

    size_t obase = ((size_t)n * OUTo + o) * TV;
    const float* xo = x + obase;
    float* yo = g_y + obase;
    __half* yh = g_yh + obase;
    for (int l = tid * 4; l < TV; l += 512) {
        float4 r = *(const float4*)&xo[l];
        float rr[4] = {r.x, r.y, r.z, r.w};
        float w[4];
#pragma unroll
        for (int k = 0; k < 4; k++) {
            int idx = l + k;
            int tt = (int)(((unsigned)idx * 5243u) >> 17);
            int vv = idx - tt * 25;
            w[k] = fmaxf(Xs[vv * 257 + tt] + rr[k], 0.f);
        }
        float4 q = {w[0], w[1], w[2], w[3]};
        *(float4*)&yo[l] = q;
        __half2 h[2];
        h[0] = __floats2half2_rn(w[0], w[1]);
        h[1] = __floats2half2_rn(w[2], w[3]);
        *(uint2*)&yh[l] = *(uint2*)h;
    }
}

// ---------------- K6: dilated temporal convs ----------------------------------
__global__ void k_tc2(const float* __restrict__ tcw, const float* __restrict__ tcb,
                      const float* __restrict__ tcbn_s, const float* __restrict__ tcbn_b,
                      const float* __restrict__ x, float* __restrict__ out) {
    extern __shared__ float sm[];
    float* Hs = sm;              // 24*600
    float* ws = sm + 14400;      // 2880

    int br = blockIdx.z;
    int n  = blockIdx.y;
    int t0 = blockIdx.x * 16;
    int tid = threadIdx.x;

    for (int i = tid; i < BCc * BCc * 5; i += 640)
        ws[i] = tcw[br * BCc * BCc * 5 + i];

    const float* H = (br == 0 ? g_H0 : g_H1) + (size_t)n * BCc * TV;
    int base = (t0 - 4) * 25;
    for (int i = tid; i < 24 * 600; i += 640) {
        int ic = i / 600;
        int rem = i - ic * 600;
        int tg25 = base + rem;
        float val = 0.f;
        if (tg25 >= 0 && tg25 < TV) val = H[(size_t)ic * TV + tg25];
        Hs[i] = val;
    }
    __syncthreads();
    if (tid >= BCc * Vv) return;
    int oc = tid / Vv, v = tid - oc * Vv;

    float bias = __ldg(&tcb[br * BCc + oc]);
    float sc = __ldg(&tcbn_s[br * BCc + oc]), sh = __ldg(&tcbn_b[br * BCc + oc]);

    float acc[16];
#pragma unroll
    for (int j = 0; j < 16; j++) acc[j] = bias;

    for (int ic = 0; ic < BCc; ic++) {
        float h[24];
        const float* hp = Hs + ic * 600 + v;
#pragma unroll
        for (int i = 0; i < 24; i++) h[i] = hp[i * 25];
        const float* wp = ws + (oc * BCc + ic) * 5;
        if (br == 0) {
#pragma unroll
            for (int k = 0; k < 5; k++) {
                float wv = wp[k];
#pragma unroll
                for (int j = 0; j < 16; j++) acc[j] += wv * h[j + k + 2];
            }
        } else {
#pragma unroll
            for (int k = 0; k < 5; k++) {
                float wv = wp[k];
#pragma unroll
                for (int j = 0; j < 16; j++) acc[j] += wv * h[j + 2 * k];
            }
        }
    }

#pragma unroll
    for (int j = 0; j < 16; j++) {
        int tg = t0 + j;
        size_t oi = ((size_t)n * OUTo + br * BCc + oc) * TV + (size_t)tg * Vv + v;
        out[oi] = fmaxf(acc[j] * sc + sh + __ldg(&x[oi]), 0.f);
    }
}

// ---------------- K7: maxpool branch -----------------------------------------
__global__ void k_mp(const float* __restrict__ mpbn_s, const float* __restrict__ mpbn_b,
                     const float* __restrict__ x, float* __restrict__ out) {
    int idx = blockIdx.x * 256 + threadIdx.x;
    if (idx >= Nn * BCc * TV) return;
    int v = idx % Vv;
    int t = (idx / Vv) % Tt;
    int bc = (idx / TV) % BCc;
    int n = idx / (TV * BCc);
    const float* H = g_H2 + (size_t)(n * BCc + bc) * TV;
    float m = H[t * Vv + v];
    if (t > 0)   m = fmaxf(m, H[(t - 1) * Vv + v]);
    if (t < 255) m = fmaxf(m, H[(t + 1) * Vv + v]);
    float val = m * __ldg(&mpbn_s[bc]) + __ldg(&mpbn_b[bc]);
    size_t oi = ((size_t)n * OUTo + 48 + bc) * TV + (size_t)t * Vv + v;
    out[oi] = fmaxf(val + __ldg(&x[oi]), 0.f);
}

// ---------------- driver ------------------------------------------------------
#define TC_SMEM   ((24*600 + 24*24*5) * 4)

extern "C" void kernel_launch(void* const* d_in, const int* in_sizes, int n_in,
                              void* d_out, int out_size) {
    const float* x      = (const float*)d_in[0];
    const float* spd_A  = (const float*)d_in[1];
    const float* A3     = (const float*)d_in[2];
    const float* A6     = (const float*)d_in[3];
    const float* alpha  = (const float*)d_in[4];
    const float* beta   = (const float*)d_in[5];
    const float* gamma  = (const float*)d_in[6];
    const float* c1_w   = (const float*)d_in[7];
    const float* c1_b   = (const float*)d_in[8];
    const float* c2_w   = (const float*)d_in[9];
    const float* c2_b   = (const float*)d_in[10];
    const float* c4_w   = (const float*)d_in[11];
    const float* c4_b   = (const float*)d_in[12];
    const float* c3_w   = (const float*)d_in[13];
    const float* c3_b   = (const float*)d_in[14];
    const float* gbn_s  = (const float*)d_in[15];
    const float* gbn_b  = (const float*)d_in[16];
    const float* pw_w   = (const float*)d_in[17];
    const float* pw_b   = (const float*)d_in[18];
    const float* pwbn_s = (const float*)d_in[19];
    const float* pwbn_b = (const float*)d_in[20];
    const float* tc_w   = (const float*)d_in[21];
    const float* tc_b   = (const float*)d_in[22];
    const float* tcbn_s = (const float*)d_in[23];
    const float* tcbn_b = (const float*)d_in[24];
    const float* mpbn_s = (const float*)d_in[25];
    const float* mpbn_b = (const float*)d_in[26];
    float* out = (float*)d_out;

    cudaFuncSetAttribute(k_tc2, cudaFuncAttributeMaxDynamicSharedMemorySize, TC_SMEM);

    size_t xtot = (size_t)Nn * Cc * TV;
    k_prep_xh<<<(int)((xtot / 8 + 255) / 256), 256>>>(x);           // 1
    k_prep_wh<<<16, 256>>>(c3_w, pw_w);                             // 2
    k_xm<<<Nn * Cc, 128>>>(x);                                      // 3
    k_gemm0_wmma<<<dim3(50, 1, Nn), 256>>>(c3_b);                   // 4 <- profiled
    k_rel<<<Nn * Ss, 256>>>(spd_A, A3, A6, alpha, beta, gamma,
                            c1_w, c1_b, c2_w, c2_b, c4_w, c4_b);    // 5
    k_y<<<Nn * OUTo, 128>>>(x, gbn_s, gbn_b);                       // 6
    k_pw_wmma<<<dim3(50, 1, Nn), 256>>>(x, pw_b, pwbn_s, pwbn_b, out);
    k_tc2<<<dim3(16, Nn, 2), 640, TC_SMEM>>>(tc_w, tc_b, tcbn_s, tcbn_b, x, out);
    k_mp<<<(Nn * BCc * TV + 255) / 256, 256>>>(mpbn_s, mpbn_b, x, out);
}

// round 11
// speedup vs baseline: 1.6617x; 1.0154x over previous
#include <cuda_runtime.h>
#include <cuda_fp16.h>
#include <math.h>
#include <stdint.h>
#include <mma.h>

using namespace nvcuda;

#define Nn 32
#define Cc 96
#define Tt 256
#define Vv 25
#define Ss 3
#define RELr 12
#define OUTo 96
#define BCc 24
#define TV (Tt*Vv)   // 6400

typedef unsigned long long u64;

__device__ __forceinline__ u64 splat2(float x) {
    u64 r;
    asm("mov.b64 %0, {%1, %1};" : "=l"(r) : "f"(x));
    return r;
}
__device__ __forceinline__ void ffma2(u64& d, u64 a, u64 b) {
    asm("fma.rn.f32x2 %0, %1, %2, %0;" : "+l"(d) : "l"(a), "l"(b));
}
__device__ __forceinline__ void unpack2(float& lo, float& hi, u64 v) {
    asm("mov.b64 {%0, %1}, %2;" : "=f"(lo), "=f"(hi) : "l"(v));
}

// ---------------- scratch ----------------------------------------------------
__device__ float  g_xm[Nn*Cc*Vv];
__device__ float  g_A [(size_t)Nn*Ss*OUTo*Vv*Vv];
__device__ __half g_x3[(size_t)Nn*Ss*OUTo*TV];
__device__ __half g_yh[(size_t)Nn*OUTo*TV];
__device__ __half g_xh[(size_t)Nn*Cc*TV];
__device__ __half g_c3h[Ss*96*96];
__device__ __half g_pwh[96*96];
__device__ float  g_H0[(size_t)Nn*BCc*TV];
__device__ float  g_H1[(size_t)Nn*BCc*TV];
__device__ float  g_H2[(size_t)Nn*BCc*TV];

// ---------------- P0: x -> fp16 ----------------------------------------------
__global__ void k_prep_xh(const float* __restrict__ x) {
    size_t i = ((size_t)blockIdx.x * 256 + threadIdx.x) * 8;
    if (i >= (size_t)Nn * Cc * TV) return;
    float4 a = *(const float4*)&x[i];
    float4 b = *(const float4*)&x[i + 4];
    __half2 h[4];
    h[0] = __floats2half2_rn(a.x, a.y);
    h[1] = __floats2half2_rn(a.z, a.w);
    h[2] = __floats2half2_rn(b.x, b.y);
    h[3] = __floats2half2_rn(b.z, b.w);
    *(uint4*)&g_xh[i] = *(uint4*)h;
}

// ---------------- P1: weights -> fp16 -----------------------------------------
__global__ void k_prep_wh(const float* __restrict__ c3w, const float* __restrict__ pww) {
    for (int i = threadIdx.x + blockIdx.x * 256; i < Ss * 96 * 96 + 96 * 96;
         i += gridDim.x * 256) {
        if (i < Ss * 96 * 96) g_c3h[i] = __float2half(c3w[i]);
        else                  g_pwh[i - Ss * 96 * 96] = __float2half(pww[i - Ss * 96 * 96]);
    }
}

// ---------------- K1: mean over T --------------------------------------------
__global__ void k_xm(const float* __restrict__ x) {
    int nc = blockIdx.x;
    const float* xp = x + (size_t)nc * TV;
    float acc[Vv];
#pragma unroll
    for (int v = 0; v < Vv; v++) acc[v] = 0.f;
    for (int t = threadIdx.x; t < Tt; t += 128) {
        const float* row = xp + t * Vv;
#pragma unroll
        for (int v = 0; v < Vv; v++) acc[v] += row[v];
    }
    __shared__ float s[Vv][128];
#pragma unroll
    for (int v = 0; v < Vv; v++) s[v][threadIdx.x] = acc[v];
    __syncthreads();
    if (threadIdx.x < Vv) {
        float r = 0.f;
#pragma unroll 8
        for (int i = 0; i < 128; i++) r += s[threadIdx.x][i];
        g_xm[nc * Vv + threadIdx.x] = r * (1.f / Tt);
    }
}

// ---------------- K2: CTRGC relation -> A_at ---------------------------------
__global__ void k_rel(const float* __restrict__ spd, const float* __restrict__ A3,
                      const float* __restrict__ A6,
                      const float* __restrict__ alpha, const float* __restrict__ beta,
                      const float* __restrict__ gamma,
                      const float* __restrict__ c1w, const float* __restrict__ c1b,
                      const float* __restrict__ c2w, const float* __restrict__ c2b,
                      const float* __restrict__ c4w, const float* __restrict__ c4b) {
    int n = blockIdx.x / Ss, s = blockIdx.x % Ss;
    int tid = threadIdx.x;
    __shared__ float xm_s[Cc * Vv];
    __shared__ float x1s[RELr * Vv];
    __shared__ float x2s[RELr * Vv];
    __shared__ float Rs[RELr * Vv * Vv];
    __shared__ float base_s[Vv * Vv];

    for (int i = tid; i < Cc * Vv; i += 256) xm_s[i] = g_xm[n * Cc * Vv + i];
    __syncthreads();

    for (int i = tid; i < 2 * RELr * Vv; i += 256) {
        int which = i / (RELr * Vv);
        int rv = i % (RELr * Vv);
        int r = rv / Vv, v = rv % Vv;
        const float* w = (which ? c2w : c1w) + (s * RELr + r) * Cc;
        float acc = (which ? c2b : c1b)[s * RELr + r];
#pragma unroll 8
        for (int c = 0; c < Cc; c++) acc += w[c] * xm_s[c * Vv + v];
        (which ? x2s : x1s)[rv] = acc;
    }
    __syncthreads();

    float ga = __ldg(gamma);
    for (int i = tid; i < RELr * Vv * Vv; i += 256) {
        int r = i / (Vv * Vv);
        int uv = i % (Vv * Vv);
        int u = uv / Vv, v = uv % Vv;
        Rs[i] = tanhf(x1s[r * Vv + u] - x2s[r * Vv + v]);
    }
    for (int i = tid; i < Vv * Vv; i += 256)
        base_s[i] = __ldg(&A3[s * 625 + i]) + __ldg(&spd[i]) * ga;
    __syncthreads();

    float al = __ldg(alpha), be = __ldg(beta);
    float* Aout = g_A + (size_t)(n * Ss + s) * OUTo * 625;
    for (int o = 0; o < OUTo; o++) {
        float w4[RELr];
#pragma unroll
        for (int r = 0; r < RELr; r++) w4[r] = __ldg(&c4w[(s * OUTo + o) * RELr + r]);
        float b4 = __ldg(&c4b[s * OUTo + o]);
        const float* A6o = A6 + (o % 6) * 625;
        for (int i = tid; i < 625; i += 256) {
            float m = b4;
#pragma unroll
            for (int r = 0; r < RELr; r++) m += w4[r] * Rs[r * 625 + i];
            Aout[(size_t)o * 625 + i] = m * al + base_s[i] + __ldg(&A6o[i]) * be;
        }
    }
}

// ---------------- K3: x3 via wmma, warp-private epilogue ----------------------
#define BLD 28     // per-warp buffer row stride (floats)
__global__ void __launch_bounds__(256, 4)
k_gemm0_wmma(const float* __restrict__ bias) {
    __shared__ float buf[8][16 * BLD];     // 14KB
    int ct = blockIdx.x;      // 0..49
    int n  = blockIdx.z;
    int tid = threadIdx.x;
    int wid = tid >> 5, lane = tid & 31;

    const __half* Xg = g_xh + (size_t)n * Cc * TV + (size_t)ct * 128 + wid * 16;

    wmma::fragment<wmma::matrix_b, 16, 16, 16, __half, wmma::row_major> b[6];
#pragma unroll
    for (int k = 0; k < 6; k++)
        wmma::load_matrix_sync(b[k], Xg + (size_t)k * 16 * TV, TV);

    int r = lane >> 1, c0 = (lane & 1) * 8;

    for (int s = 0; s < Ss; s++) {
        const __half* Wg = g_c3h + s * 96 * 96;
        __half* Obase = g_x3 + ((size_t)(n * Ss + s) * OUTo) * TV
                        + (size_t)ct * 128 + wid * 16 + c0;
#pragma unroll
        for (int ot = 0; ot < 6; ot++) {
            wmma::fragment<wmma::accumulator, 16, 16, 16, float> d;
            wmma::fill_fragment(d, 0.f);
#pragma unroll
            for (int k = 0; k < 6; k++) {
                wmma::fragment<wmma::matrix_a, 16, 16, 16, __half, wmma::row_major> a;
                wmma::load_matrix_sync(a, Wg + ot * 16 * 96 + k * 16, 96);
                wmma::mma_sync(d, a, b[k], d);
            }
            wmma::store_matrix_sync(buf[wid], d, BLD, wmma::mem_row_major);
            __syncwarp();
            float bv = __ldg(&bias[s * 96 + ot * 16 + r]);
            const float* bp = &buf[wid][r * BLD + c0];
            __half2 h[4];
#pragma unroll
            for (int q = 0; q < 4; q++)
                h[q] = __floats2half2_rn(bp[2 * q] + bv, bp[2 * q + 1] + bv);
            *(uint4*)&Obase[(size_t)(ot * 16 + r) * TV] = *(uint4*)h;
            __syncwarp();
        }
    }
}

// ---------------- K5: pointwise convs via wmma, warp-private epilogue ---------
__global__ void __launch_bounds__(256, 4)
k_pw_wmma(const float* __restrict__ xglob, const float* __restrict__ bias,
          const float* __restrict__ bn_s, const float* __restrict__ bn_b,
          float* __restrict__ outbuf) {
    __shared__ float buf[8][16 * BLD];
    int ct = blockIdx.x;      // 0..49
    int n  = blockIdx.z;
    int tid = threadIdx.x;
    int wid = tid >> 5, lane = tid & 31;

    const __half* Yg = g_yh + (size_t)n * Cc * TV + (size_t)ct * 128 + wid * 16;

    wmma::fragment<wmma::matrix_b, 16, 16, 16, __half, wmma::row_major> b[6];
#pragma unroll
    for (int k = 0; k < 6; k++)
        wmma::load_matrix_sync(b[k], Yg + (size_t)k * 16 * TV, TV);

    int r = lane >> 1, c0 = (lane & 1) * 8;
    int colg = ct * 128 + wid * 16 + c0;

#pragma unroll
    for (int ot = 0; ot < 6; ot++) {
        wmma::fragment<wmma::accumulator, 16, 16, 16, float> d;
        wmma::fill_fragment(d, 0.f);
#pragma unroll
        for (int k = 0; k < 6; k++) {
            wmma::fragment<wmma::matrix_a, 16, 16, 16, __half, wmma::row_major> a;
            wmma::load_matrix_sync(a, g_pwh + ot * 16 * 96 + k * 16, 96);
            wmma::mma_sync(d, a, b[k], d);
        }
        wmma::store_matrix_sync(buf[wid], d, BLD, wmma::mem_row_major);
        __syncwarp();

        int rg = ot * 16 + r;
        int br = rg / 24, bc = rg % 24;
        float bv = __ldg(&bias[rg]);
        float sc = __ldg(&bn_s[rg]), sh = __ldg(&bn_b[rg]);
        const float* bp = &buf[wid][r * BLD + c0];
        float w[8];
#pragma unroll
        for (int j = 0; j < 8; j++) {
            float v = (bp[j] + bv) * sc + sh;
            w[j] = v;
        }
        if (br < 3) {
            float* dst = (br == 0) ? g_H0 : (br == 1) ? g_H1 : g_H2;
            size_t hi = (size_t)(n * BCc + bc) * TV + colg;
            float4 q0 = {fmaxf(w[0],0.f), fmaxf(w[1],0.f), fmaxf(w[2],0.f), fmaxf(w[3],0.f)};
            float4 q1 = {fmaxf(w[4],0.f), fmaxf(w[5],0.f), fmaxf(w[6],0.f), fmaxf(w[7],0.f)};
            *(float4*)&dst[hi]     = q0;
            *(float4*)&dst[hi + 4] = q1;
        } else {
            size_t oi = ((size_t)n * OUTo + 72 + bc) * TV + colg;
            float4 r0 = *(const float4*)&xglob[oi];
            float4 r1 = *(const float4*)&xglob[oi + 4];
            float4 q0 = {fmaxf(w[0]+r0.x,0.f), fmaxf(w[1]+r0.y,0.f),
                         fmaxf(w[2]+r0.z,0.f), fmaxf(w[3]+r0.w,0.f)};
            float4 q1 = {fmaxf(w[4]+r1.x,0.f), fmaxf(w[5]+r1.y,0.f),
                         fmaxf(w[6]+r1.z,0.f), fmaxf(w[7]+r1.w,0.f)};
            *(float4*)&outbuf[oi]     = q0;
            *(float4*)&outbuf[oi + 4] = q1;
        }
        __syncwarp();
    }
}

// ---------------- K4: y(fp16) = relu(bn(sum_s A_s @ x3_s) + x) -----------------
__global__ void k_y(const float* __restrict__ x, const float* __restrict__ gbn_s,
                    const float* __restrict__ gbn_b) {
    int no = blockIdx.x;
    int n = no / OUTo, o = no % OUTo;
    int tid = threadIdx.x;        // 128

    __shared__ __align__(16) float As[Ss * Vv * 28];
    __shared__ __align__(16) float Xs[Vv * 257 + 7];

    for (int i = tid; i < Ss * 625; i += 128) {
        int s = i / 625;
        int rem = i - s * 625;
        int u = rem / 25, v = rem - u * 25;
        As[(s * 25 + v) * 28 + u] =
            g_A[(((size_t)(n * Ss + s)) * OUTo + o) * 625 + rem];
    }
    for (int i = tid; i < Ss * Vv * 3; i += 128) {
        int sv = i / 3, pu = 25 + i % 3;
        As[sv * 28 + pu] = 0.f;
    }

    u64 acc2[13][2];
#pragma unroll
    for (int p = 0; p < 13; p++) { acc2[p][0] = 0ull; acc2[p][1] = 0ull; }

    int t0 = tid, t1 = tid + 128;
#pragma unroll
    for (int s = 0; s < Ss; s++) {
        __syncthreads();
        const __half* base = g_x3 + (((size_t)(n * Ss + s)) * OUTo + o) * TV;
        for (int l = tid * 8; l < TV; l += 1024) {
            uint4 w = *(const uint4*)&base[l];
            const __half2* hp = (const __half2*)&w;
            float2 f0 = __half22float2(hp[0]);
            float2 f1 = __half22float2(hp[1]);
            float2 f2 = __half22float2(hp[2]);
            float2 f3 = __half22float2(hp[3]);
            float4 q0 = {f0.x, f0.y, f1.x, f1.y};
            float4 q1 = {f2.x, f2.y, f3.x, f3.y};
            *(float4*)&Xs[l]     = q0;
            *(float4*)&Xs[l + 4] = q1;
        }
        __syncthreads();
        const float* A2 = As + s * Vv * 28;
#pragma unroll
        for (int v = 0; v < Vv; v++) {
            u64 xa = splat2(Xs[t0 * Vv + v]);
            u64 xb = splat2(Xs[t1 * Vv + v]);
            const float* ar = A2 + v * 28;
#pragma unroll
            for (int p = 0; p < 13; p++) {
                u64 ap = *(const u64*)&ar[2 * p];
                ffma2(acc2[p][0], ap, xa);
                ffma2(acc2[p][1], ap, xb);
            }
        }
    }

    float gs = __ldg(&gbn_s[o]), gb = __ldg(&gbn_b[o]);
    __syncthreads();
#pragma unroll
    for (int p = 0; p < 13; p++) {
        float lo0, hi0, lo1, hi1;
        unpack2(lo0, hi0, acc2[p][0]);
        unpack2(lo1, hi1, acc2[p][1]);
        int u = 2 * p;
        Xs[u * 257 + t0] = lo0 * gs + gb;
        Xs[u * 257 + t1] = lo1 * gs + gb;
        if (u + 1 < Vv) {
            Xs[(u + 1) * 257 + t0] = hi0 * gs + gb;
            Xs[(u + 1) * 257 + t1] = hi1 * gs + gb;
        }
    }
    __syncthreads();

    size_t obase = ((size_t)n * OUTo + o) * TV;
    const float* xo = x + obase;
    __half* yh = g_yh + obase;
    for (int l = tid * 4; l < TV; l += 512) {
        float4 r = *(const float4*)&xo[l];
        float rr[4] = {r.x, r.y, r.z, r.w};
        float w[4];
#pragma unroll
        for (int k = 0; k < 4; k++) {
            int idx = l + k;
            int tt = (int)(((unsigned)idx * 5243u) >> 17);
            int vv = idx - tt * 25;
            w[k] = fmaxf(Xs[vv * 257 + tt] + rr[k], 0.f);
        }
        __half2 h[2];
        h[0] = __floats2half2_rn(w[0], w[1]);
        h[1] = __floats2half2_rn(w[2], w[3]);
        *(uint2*)&yh[l] = *(uint2*)h;
    }
}

// ---------------- K6: dilated temporal convs ----------------------------------
__global__ void k_tc2(const float* __restrict__ tcw, const float* __restrict__ tcb,
                      const float* __restrict__ tcbn_s, const float* __restrict__ tcbn_b,
                      const float* __restrict__ x, float* __restrict__ out) {
    extern __shared__ float sm[];
    float* Hs = sm;              // 24*600
    float* ws = sm + 14400;      // 2880

    int br = blockIdx.z;
    int n  = blockIdx.y;
    int t0 = blockIdx.x * 16;
    int tid = threadIdx.x;

    for (int i = tid; i < BCc * BCc * 5; i += 640)
        ws[i] = tcw[br * BCc * BCc * 5 + i];

    const float* H = (br == 0 ? g_H0 : g_H1) + (size_t)n * BCc * TV;
    int base = (t0 - 4) * 25;
    for (int i = tid; i < 24 * 600; i += 640) {
        int ic = i / 600;
        int rem = i - ic * 600;
        int tg25 = base + rem;
        float val = 0.f;
        if (tg25 >= 0 && tg25 < TV) val = H[(size_t)ic * TV + tg25];
        Hs[i] = val;
    }
    __syncthreads();
    if (tid >= BCc * Vv) return;
    int oc = tid / Vv, v = tid - oc * Vv;

    float bias = __ldg(&tcb[br * BCc + oc]);
    float sc = __ldg(&tcbn_s[br * BCc + oc]), sh = __ldg(&tcbn_b[br * BCc + oc]);

    float acc[16];
#pragma unroll
    for (int j = 0; j < 16; j++) acc[j] = bias;

    for (int ic = 0; ic < BCc; ic++) {
        float h[24];
        const float* hp = Hs + ic * 600 + v;
#pragma unroll
        for (int i = 0; i < 24; i++) h[i] = hp[i * 25];
        const float* wp = ws + (oc * BCc + ic) * 5;
        if (br == 0) {
#pragma unroll
            for (int k = 0; k < 5; k++) {
                float wv = wp[k];
#pragma unroll
                for (int j = 0; j < 16; j++) acc[j] += wv * h[j + k + 2];
            }
        } else {
#pragma unroll
            for (int k = 0; k < 5; k++) {
                float wv = wp[k];
#pragma unroll
                for (int j = 0; j < 16; j++) acc[j] += wv * h[j + 2 * k];
            }
        }
    }

#pragma unroll
    for (int j = 0; j < 16; j++) {
        int tg = t0 + j;
        size_t oi = ((size_t)n * OUTo + br * BCc + oc) * TV + (size_t)tg * Vv + v;
        out[oi] = fmaxf(acc[j] * sc + sh + __ldg(&x[oi]), 0.f);
    }
}

// ---------------- K7: maxpool branch -----------------------------------------
__global__ void k_mp(const float* __restrict__ mpbn_s, const float* __restrict__ mpbn_b,
                     const float* __restrict__ x, float* __restrict__ out) {
    int idx = blockIdx.x * 256 + threadIdx.x;
    if (idx >= Nn * BCc * TV) return;
    int v = idx % Vv;
    int t = (idx / Vv) % Tt;
    int bc = (idx / TV) % BCc;
    int n = idx / (TV * BCc);
    const float* H = g_H2 + (size_t)(n * BCc + bc) * TV;
    float m = H[t * Vv + v];
    if (t > 0)   m = fmaxf(m, H[(t - 1) * Vv + v]);
    if (t < 255) m = fmaxf(m, H[(t + 1) * Vv + v]);
    float val = m * __ldg(&mpbn_s[bc]) + __ldg(&mpbn_b[bc]);
    size_t oi = ((size_t)n * OUTo + 48 + bc) * TV + (size_t)t * Vv + v;
    out[oi] = fmaxf(val + __ldg(&x[oi]), 0.f);
}

// ---------------- driver ------------------------------------------------------
#define TC_SMEM   ((24*600 + 24*24*5) * 4)

extern "C" void kernel_launch(void* const* d_in, const int* in_sizes, int n_in,
                              void* d_out, int out_size) {
    const float* x      = (const float*)d_in[0];
    const float* spd_A  = (const float*)d_in[1];
    const float* A3     = (const float*)d_in[2];
    const float* A6     = (const float*)d_in[3];
    const float* alpha  = (const float*)d_in[4];
    const float* beta   = (const float*)d_in[5];
    const float* gamma  = (const float*)d_in[6];
    const float* c1_w   = (const float*)d_in[7];
    const float* c1_b   = (const float*)d_in[8];
    const float* c2_w   = (const float*)d_in[9];
    const float* c2_b   = (const float*)d_in[10];
    const float* c4_w   = (const float*)d_in[11];
    const float* c4_b   = (const float*)d_in[12];
    const float* c3_w   = (const float*)d_in[13];
    const float* c3_b   = (const float*)d_in[14];
    const float* gbn_s  = (const float*)d_in[15];
    const float* gbn_b  = (const float*)d_in[16];
    const float* pw_w   = (const float*)d_in[17];
    const float* pw_b   = (const float*)d_in[18];
    const float* pwbn_s = (const float*)d_in[19];
    const float* pwbn_b = (const float*)d_in[20];
    const float* tc_w   = (const float*)d_in[21];
    const float* tc_b   = (const float*)d_in[22];
    const float* tcbn_s = (const float*)d_in[23];
    const float* tcbn_b = (const float*)d_in[24];
    const float* mpbn_s = (const float*)d_in[25];
    const float* mpbn_b = (const float*)d_in[26];
    float* out = (float*)d_out;

    cudaFuncSetAttribute(k_tc2, cudaFuncAttributeMaxDynamicSharedMemorySize, TC_SMEM);

    size_t xtot = (size_t)Nn * Cc * TV;
    k_prep_xh<<<(int)((xtot / 8 + 255) / 256), 256>>>(x);           // 1
    k_prep_wh<<<16, 256>>>(c3_w, pw_w);                             // 2
    k_xm<<<Nn * Cc, 128>>>(x);                                      // 3
    k_gemm0_wmma<<<dim3(50, 1, Nn), 256>>>(c3_b);                   // 4 <- profiled
    k_rel<<<Nn * Ss, 256>>>(spd_A, A3, A6, alpha, beta, gamma,
                            c1_w, c1_b, c2_w, c2_b, c4_w, c4_b);    // 5
    k_y<<<Nn * OUTo, 128>>>(x, gbn_s, gbn_b);                       // 6
    k_pw_wmma<<<dim3(50, 1, Nn), 256>>>(x, pw_b, pwbn_s, pwbn_b, out);
    k_tc2<<<dim3(16, Nn, 2), 640, TC_SMEM>>>(tc_w, tc_b, tcbn_s, tcbn_b, x, out);
    k_mp<<<(Nn * BCc * TV + 255) / 256, 256>>>(mpbn_s, mpbn_b, x, out);
}

// round 12
// speedup vs baseline: 1.7332x; 1.0430x over previous
#include <cuda_runtime.h>
#include <cuda_fp16.h>
#include <math.h>
#include <stdint.h>
#include <mma.h>

using namespace nvcuda;

#define Nn 32
#define Cc 96
#define Tt 256
#define Vv 25
#define Ss 3
#define RELr 12
#define OUTo 96
#define BCc 24
#define TV (Tt*Vv)   // 6400

typedef unsigned long long u64;

__device__ __forceinline__ u64 splat2(float x) {
    u64 r;
    asm("mov.b64 %0, {%1, %1};" : "=l"(r) : "f"(x));
    return r;
}
__device__ __forceinline__ void ffma2(u64& d, u64 a, u64 b) {
    asm("fma.rn.f32x2 %0, %1, %2, %0;" : "+l"(d) : "l"(a), "l"(b));
}
__device__ __forceinline__ void unpack2(float& lo, float& hi, u64 v) {
    asm("mov.b64 {%0, %1}, %2;" : "=f"(lo), "=f"(hi) : "l"(v));
}

// ---------------- scratch ----------------------------------------------------
__device__ float  g_xm[Nn*Cc*Vv];
__device__ float  g_A [(size_t)Nn*Ss*OUTo*Vv*Vv];
__device__ __half g_x3[(size_t)Nn*Ss*OUTo*TV];
__device__ __half g_yh[(size_t)Nn*OUTo*TV];
__device__ __half g_xh[(size_t)Nn*Cc*TV];
__device__ __half g_c3h[Ss*96*96];
__device__ __half g_pwh[96*96];
__device__ float  g_H0[(size_t)Nn*BCc*TV];
__device__ float  g_H1[(size_t)Nn*BCc*TV];
__device__ float  g_H2[(size_t)Nn*BCc*TV];

// ---------------- P0: x -> fp16 ----------------------------------------------
__global__ void k_prep_xh(const float* __restrict__ x) {
    size_t i = ((size_t)blockIdx.x * 256 + threadIdx.x) * 8;
    if (i >= (size_t)Nn * Cc * TV) return;
    float4 a = *(const float4*)&x[i];
    float4 b = *(const float4*)&x[i + 4];
    __half2 h[4];
    h[0] = __floats2half2_rn(a.x, a.y);
    h[1] = __floats2half2_rn(a.z, a.w);
    h[2] = __floats2half2_rn(b.x, b.y);
    h[3] = __floats2half2_rn(b.z, b.w);
    *(uint4*)&g_xh[i] = *(uint4*)h;
}

// ---------------- P1: weights -> fp16 -----------------------------------------
__global__ void k_prep_wh(const float* __restrict__ c3w, const float* __restrict__ pww) {
    for (int i = threadIdx.x + blockIdx.x * 256; i < Ss * 96 * 96 + 96 * 96;
         i += gridDim.x * 256) {
        if (i < Ss * 96 * 96) g_c3h[i] = __float2half(c3w[i]);
        else                  g_pwh[i - Ss * 96 * 96] = __float2half(pww[i - Ss * 96 * 96]);
    }
}

// ---------------- K1: mean over T --------------------------------------------
__global__ void k_xm(const float* __restrict__ x) {
    int nc = blockIdx.x;
    const float* xp = x + (size_t)nc * TV;
    float acc[Vv];
#pragma unroll
    for (int v = 0; v < Vv; v++) acc[v] = 0.f;
    for (int t = threadIdx.x; t < Tt; t += 128) {
        const float* row = xp + t * Vv;
#pragma unroll
        for (int v = 0; v < Vv; v++) acc[v] += row[v];
    }
    __shared__ float s[Vv][128];
#pragma unroll
    for (int v = 0; v < Vv; v++) s[v][threadIdx.x] = acc[v];
    __syncthreads();
    if (threadIdx.x < Vv) {
        float r = 0.f;
#pragma unroll 8
        for (int i = 0; i < 128; i++) r += s[threadIdx.x][i];
        g_xm[nc * Vv + threadIdx.x] = r * (1.f / Tt);
    }
}

// ---------------- K2: CTRGC relation -> A_at ---------------------------------
__global__ void k_rel(const float* __restrict__ spd, const float* __restrict__ A3,
                      const float* __restrict__ A6,
                      const float* __restrict__ alpha, const float* __restrict__ beta,
                      const float* __restrict__ gamma,
                      const float* __restrict__ c1w, const float* __restrict__ c1b,
                      const float* __restrict__ c2w, const float* __restrict__ c2b,
                      const float* __restrict__ c4w, const float* __restrict__ c4b) {
    int n = blockIdx.x / Ss, s = blockIdx.x % Ss;
    int tid = threadIdx.x;
    __shared__ float xm_s[Cc * Vv];
    __shared__ float x1s[RELr * Vv];
    __shared__ float x2s[RELr * Vv];
    __shared__ float Rs[RELr * Vv * Vv];
    __shared__ float base_s[Vv * Vv];

    for (int i = tid; i < Cc * Vv; i += 256) xm_s[i] = g_xm[n * Cc * Vv + i];
    __syncthreads();

    for (int i = tid; i < 2 * RELr * Vv; i += 256) {
        int which = i / (RELr * Vv);
        int rv = i % (RELr * Vv);
        int r = rv / Vv, v = rv % Vv;
        const float* w = (which ? c2w : c1w) + (s * RELr + r) * Cc;
        float acc = (which ? c2b : c1b)[s * RELr + r];
#pragma unroll 8
        for (int c = 0; c < Cc; c++) acc += w[c] * xm_s[c * Vv + v];
        (which ? x2s : x1s)[rv] = acc;
    }
    __syncthreads();

    float ga = __ldg(gamma);
    for (int i = tid; i < RELr * Vv * Vv; i += 256) {
        int r = i / (Vv * Vv);
        int uv = i % (Vv * Vv);
        int u = uv / Vv, v = uv % Vv;
        Rs[i] = tanhf(x1s[r * Vv + u] - x2s[r * Vv + v]);
    }
    for (int i = tid; i < Vv * Vv; i += 256)
        base_s[i] = __ldg(&A3[s * 625 + i]) + __ldg(&spd[i]) * ga;
    __syncthreads();

    float al = __ldg(alpha), be = __ldg(beta);
    float* Aout = g_A + (size_t)(n * Ss + s) * OUTo * 625;
    for (int o = 0; o < OUTo; o++) {
        float w4[RELr];
#pragma unroll
        for (int r = 0; r < RELr; r++) w4[r] = __ldg(&c4w[(s * OUTo + o) * RELr + r]);
        float b4 = __ldg(&c4b[s * OUTo + o]);
        const float* A6o = A6 + (o % 6) * 625;
        for (int i = tid; i < 625; i += 256) {
            float m = b4;
#pragma unroll
            for (int r = 0; r < RELr; r++) m += w4[r] * Rs[r * 625 + i];
            Aout[(size_t)o * 625 + i] = m * al + base_s[i] + __ldg(&A6o[i]) * be;
        }
    }
}

// ---------------- K3: x3 via wmma; W in smem, B frags in regs -----------------
#define BLD 28
__global__ void __launch_bounds__(256, 3)
k_gemm0_wmma(const float* __restrict__ bias) {
    extern __shared__ char smc[];
    __half* Wsm = (__half*)smc;                         // 3*96*96 = 55296 B
    float*  buf = (float*)(smc + Ss * 96 * 96 * 2);     // 8*16*BLD = 14336 B

    int ct = blockIdx.x;      // 0..49
    int n  = blockIdx.z;
    int tid = threadIdx.x;
    int wid = tid >> 5, lane = tid & 31;
    float* wbuf = buf + wid * 16 * BLD;

    // stage all 3 W matrices (coalesced uint4)
    for (int i = tid; i < Ss * 96 * 96 / 8; i += 256)
        *(uint4*)&Wsm[i * 8] = *(const uint4*)&g_c3h[i * 8];

    const __half* Xg = g_xh + (size_t)n * Cc * TV + (size_t)ct * 128 + wid * 16;
    wmma::fragment<wmma::matrix_b, 16, 16, 16, __half, wmma::row_major> b[6];
#pragma unroll
    for (int k = 0; k < 6; k++)
        wmma::load_matrix_sync(b[k], Xg + (size_t)k * 16 * TV, TV);
    __syncthreads();

    int r = lane >> 1, c0 = (lane & 1) * 8;

    for (int s = 0; s < Ss; s++) {
        const __half* Wg = Wsm + s * 96 * 96;
        __half* Obase = g_x3 + ((size_t)(n * Ss + s) * OUTo) * TV
                        + (size_t)ct * 128 + wid * 16 + c0;
#pragma unroll
        for (int ot = 0; ot < 6; ot++) {
            wmma::fragment<wmma::accumulator, 16, 16, 16, float> d;
            wmma::fill_fragment(d, 0.f);
#pragma unroll
            for (int k = 0; k < 6; k++) {
                wmma::fragment<wmma::matrix_a, 16, 16, 16, __half, wmma::row_major> a;
                wmma::load_matrix_sync(a, Wg + ot * 16 * 96 + k * 16, 96);
                wmma::mma_sync(d, a, b[k], d);
            }
            wmma::store_matrix_sync(wbuf, d, BLD, wmma::mem_row_major);
            __syncwarp();
            float bv = __ldg(&bias[s * 96 + ot * 16 + r]);
            const float* bp = &wbuf[r * BLD + c0];
            __half2 h[4];
#pragma unroll
            for (int q = 0; q < 4; q++)
                h[q] = __floats2half2_rn(bp[2 * q] + bv, bp[2 * q + 1] + bv);
            *(uint4*)&Obase[(size_t)(ot * 16 + r) * TV] = *(uint4*)h;
            __syncwarp();
        }
    }
}

// ---------------- K5: pointwise convs via wmma; W in smem ---------------------
__global__ void __launch_bounds__(256, 4)
k_pw_wmma(const float* __restrict__ xglob, const float* __restrict__ bias,
          const float* __restrict__ bn_s, const float* __restrict__ bn_b,
          float* __restrict__ outbuf) {
    extern __shared__ char smc[];
    __half* Wsm = (__half*)smc;                         // 96*96*2 = 18432 B
    float*  buf = (float*)(smc + 96 * 96 * 2);          // 14336 B

    int ct = blockIdx.x;      // 0..49
    int n  = blockIdx.z;
    int tid = threadIdx.x;
    int wid = tid >> 5, lane = tid & 31;
    float* wbuf = buf + wid * 16 * BLD;

    for (int i = tid; i < 96 * 96 / 8; i += 256)
        *(uint4*)&Wsm[i * 8] = *(const uint4*)&g_pwh[i * 8];

    const __half* Yg = g_yh + (size_t)n * Cc * TV + (size_t)ct * 128 + wid * 16;
    wmma::fragment<wmma::matrix_b, 16, 16, 16, __half, wmma::row_major> b[6];
#pragma unroll
    for (int k = 0; k < 6; k++)
        wmma::load_matrix_sync(b[k], Yg + (size_t)k * 16 * TV, TV);
    __syncthreads();

    int r = lane >> 1, c0 = (lane & 1) * 8;
    int colg = ct * 128 + wid * 16 + c0;

#pragma unroll
    for (int ot = 0; ot < 6; ot++) {
        wmma::fragment<wmma::accumulator, 16, 16, 16, float> d;
        wmma::fill_fragment(d, 0.f);
#pragma unroll
        for (int k = 0; k < 6; k++) {
            wmma::fragment<wmma::matrix_a, 16, 16, 16, __half, wmma::row_major> a;
            wmma::load_matrix_sync(a, Wsm + ot * 16 * 96 + k * 16, 96);
            wmma::mma_sync(d, a, b[k], d);
        }
        wmma::store_matrix_sync(wbuf, d, BLD, wmma::mem_row_major);
        __syncwarp();

        int rg = ot * 16 + r;
        int br = rg / 24, bc = rg % 24;
        float bv = __ldg(&bias[rg]);
        float sc = __ldg(&bn_s[rg]), sh = __ldg(&bn_b[rg]);
        const float* bp = &wbuf[r * BLD + c0];
        float w[8];
#pragma unroll
        for (int j = 0; j < 8; j++) w[j] = (bp[j] + bv) * sc + sh;
        if (br < 3) {
            float* dst = (br == 0) ? g_H0 : (br == 1) ? g_H1 : g_H2;
            size_t hi = (size_t)(n * BCc + bc) * TV + colg;
            float4 q0 = {fmaxf(w[0],0.f), fmaxf(w[1],0.f), fmaxf(w[2],0.f), fmaxf(w[3],0.f)};
            float4 q1 = {fmaxf(w[4],0.f), fmaxf(w[5],0.f), fmaxf(w[6],0.f), fmaxf(w[7],0.f)};
            *(float4*)&dst[hi]     = q0;
            *(float4*)&dst[hi + 4] = q1;
        } else {
            size_t oi = ((size_t)n * OUTo + 72 + bc) * TV + colg;
            float4 r0 = *(const float4*)&xglob[oi];
            float4 r1 = *(const float4*)&xglob[oi + 4];
            float4 q0 = {fmaxf(w[0]+r0.x,0.f), fmaxf(w[1]+r0.y,0.f),
                         fmaxf(w[2]+r0.z,0.f), fmaxf(w[3]+r0.w,0.f)};
            float4 q1 = {fmaxf(w[4]+r1.x,0.f), fmaxf(w[5]+r1.y,0.f),
                         fmaxf(w[6]+r1.z,0.f), fmaxf(w[7]+r1.w,0.f)};
            *(float4*)&outbuf[oi]     = q0;
            *(float4*)&outbuf[oi + 4] = q1;
        }
        __syncwarp();
    }
}

// ---------------- K4: y(fp16) = relu(bn(sum_s A_s @ x3_s) + x) -----------------
__global__ void k_y(const float* __restrict__ x, const float* __restrict__ gbn_s,
                    const float* __restrict__ gbn_b) {
    int no = blockIdx.x;
    int n = no / OUTo, o = no % OUTo;
    int tid = threadIdx.x;        // 128

    __shared__ __align__(16) float As[Ss * Vv * 28];
    __shared__ __align__(16) float Xs[Vv * 257 + 7];

    for (int i = tid; i < Ss * 625; i += 128) {
        int s = i / 625;
        int rem = i - s * 625;
        int u = rem / 25, v = rem - u * 25;
        As[(s * 25 + v) * 28 + u] =
            g_A[(((size_t)(n * Ss + s)) * OUTo + o) * 625 + rem];
    }
    for (int i = tid; i < Ss * Vv * 3; i += 128) {
        int sv = i / 3, pu = 25 + i % 3;
        As[sv * 28 + pu] = 0.f;
    }

    u64 acc2[13][2];
#pragma unroll
    for (int p = 0; p < 13; p++) { acc2[p][0] = 0ull; acc2[p][1] = 0ull; }

    int t0 = tid, t1 = tid + 128;
#pragma unroll
    for (int s = 0; s < Ss; s++) {
        __syncthreads();
        const __half* base = g_x3 + (((size_t)(n * Ss + s)) * OUTo + o) * TV;
        for (int l = tid * 8; l < TV; l += 1024) {
            uint4 w = *(const uint4*)&base[l];
            const __half2* hp = (const __half2*)&w;
            float2 f0 = __half22float2(hp[0]);
            float2 f1 = __half22float2(hp[1]);
            float2 f2 = __half22float2(hp[2]);
            float2 f3 = __half22float2(hp[3]);
            float4 q0 = {f0.x, f0.y, f1.x, f1.y};
            float4 q1 = {f2.x, f2.y, f3.x, f3.y};
            *(float4*)&Xs[l]     = q0;
            *(float4*)&Xs[l + 4] = q1;
        }
        __syncthreads();
        const float* A2 = As + s * Vv * 28;
#pragma unroll
        for (int v = 0; v < Vv; v++) {
            u64 xa = splat2(Xs[t0 * Vv + v]);
            u64 xb = splat2(Xs[t1 * Vv + v]);
            const float* ar = A2 + v * 28;
#pragma unroll
            for (int p = 0; p < 13; p++) {
                u64 ap = *(const u64*)&ar[2 * p];
                ffma2(acc2[p][0], ap, xa);
                ffma2(acc2[p][1], ap, xb);
            }
        }
    }

    float gs = __ldg(&gbn_s[o]), gb = __ldg(&gbn_b[o]);
    __syncthreads();
#pragma unroll
    for (int p = 0; p < 13; p++) {
        float lo0, hi0, lo1, hi1;
        unpack2(lo0, hi0, acc2[p][0]);
        unpack2(lo1, hi1, acc2[p][1]);
        int u = 2 * p;
        Xs[u * 257 + t0] = lo0 * gs + gb;
        Xs[u * 257 + t1] = lo1 * gs + gb;
        if (u + 1 < Vv) {
            Xs[(u + 1) * 257 + t0] = hi0 * gs + gb;
            Xs[(u + 1) * 257 + t1] = hi1 * gs + gb;
        }
    }
    __syncthreads();

    size_t obase = ((size_t)n * OUTo + o) * TV;
    const float* xo = x + obase;
    __half* yh = g_yh + obase;
    for (int l = tid * 4; l < TV; l += 512) {
        float4 r = *(const float4*)&xo[l];
        float rr[4] = {r.x, r.y, r.z, r.w};
        float w[4];
#pragma unroll
        for (int k = 0; k < 4; k++) {
            int idx = l + k;
            int tt = (int)(((unsigned)idx * 5243u) >> 17);
            int vv = idx - tt * 25;
            w[k] = fmaxf(Xs[vv * 257 + tt] + rr[k], 0.f);
        }
        __half2 h[2];
        h[0] = __floats2half2_rn(w[0], w[1]);
        h[1] = __floats2half2_rn(w[2], w[3]);
        *(uint2*)&yh[l] = *(uint2*)h;
    }
}

// ---------------- K6: dilated temporal convs ----------------------------------
__global__ void k_tc2(const float* __restrict__ tcw, const float* __restrict__ tcb,
                      const float* __restrict__ tcbn_s, const float* __restrict__ tcbn_b,
                      const float* __restrict__ x, float* __restrict__ out) {
    extern __shared__ float sm[];
    float* Hs = sm;              // 24*600
    float* ws = sm + 14400;      // 2880

    int br = blockIdx.z;
    int n  = blockIdx.y;
    int t0 = blockIdx.x * 16;
    int tid = threadIdx.x;

    for (int i = tid; i < BCc * BCc * 5; i += 640)
        ws[i] = tcw[br * BCc * BCc * 5 + i];

    const float* H = (br == 0 ? g_H0 : g_H1) + (size_t)n * BCc * TV;
    int base = (t0 - 4) * 25;
    for (int i = tid; i < 24 * 600; i += 640) {
        int ic = i / 600;
        int rem = i - ic * 600;
        int tg25 = base + rem;
        float val = 0.f;
        if (tg25 >= 0 && tg25 < TV) val = H[(size_t)ic * TV + tg25];
        Hs[i] = val;
    }
    __syncthreads();
    if (tid >= BCc * Vv) return;
    int oc = tid / Vv, v = tid - oc * Vv;

    float bias = __ldg(&tcb[br * BCc + oc]);
    float sc = __ldg(&tcbn_s[br * BCc + oc]), sh = __ldg(&tcbn_b[br * BCc + oc]);

    float acc[16];
#pragma unroll
    for (int j = 0; j < 16; j++) acc[j] = bias;

    for (int ic = 0; ic < BCc; ic++) {
        float h[24];
        const float* hp = Hs + ic * 600 + v;
#pragma unroll
        for (int i = 0; i < 24; i++) h[i] = hp[i * 25];
        const float* wp = ws + (oc * BCc + ic) * 5;
        if (br == 0) {
#pragma unroll
            for (int k = 0; k < 5; k++) {
                float wv = wp[k];
#pragma unroll
                for (int j = 0; j < 16; j++) acc[j] += wv * h[j + k + 2];
            }
        } else {
#pragma unroll
            for (int k = 0; k < 5; k++) {
                float wv = wp[k];
#pragma unroll
                for (int j = 0; j < 16; j++) acc[j] += wv * h[j + 2 * k];
            }
        }
    }

#pragma unroll
    for (int j = 0; j < 16; j++) {
        int tg = t0 + j;
        size_t oi = ((size_t)n * OUTo + br * BCc + oc) * TV + (size_t)tg * Vv + v;
        out[oi] = fmaxf(acc[j] * sc + sh + __ldg(&x[oi]), 0.f);
    }
}

// ---------------- K7: maxpool branch -----------------------------------------
__global__ void k_mp(const float* __restrict__ mpbn_s, const float* __restrict__ mpbn_b,
                     const float* __restrict__ x, float* __restrict__ out) {
    int idx = blockIdx.x * 256 + threadIdx.x;
    if (idx >= Nn * BCc * TV) return;
    int v = idx % Vv;
    int t = (idx / Vv) % Tt;
    int bc = (idx / TV) % BCc;
    int n = idx / (TV * BCc);
    const float* H = g_H2 + (size_t)(n * BCc + bc) * TV;
    float m = H[t * Vv + v];
    if (t > 0)   m = fmaxf(m, H[(t - 1) * Vv + v]);
    if (t < 255) m = fmaxf(m, H[(t + 1) * Vv + v]);
    float val = m * __ldg(&mpbn_s[bc]) + __ldg(&mpbn_b[bc]);
    size_t oi = ((size_t)n * OUTo + 48 + bc) * TV + (size_t)t * Vv + v;
    out[oi] = fmaxf(val + __ldg(&x[oi]), 0.f);
}

// ---------------- driver ------------------------------------------------------
#define GEMM0_SMEM (Ss*96*96*2 + 8*16*BLD*4)    // 55296 + 14336 = 69632
#define PW_SMEM    (96*96*2 + 8*16*BLD*4)       // 18432 + 14336 = 32768
#define TC_SMEM    ((24*600 + 24*24*5) * 4)

extern "C" void kernel_launch(void* const* d_in, const int* in_sizes, int n_in,
                              void* d_out, int out_size) {
    const float* x      = (const float*)d_in[0];
    const float* spd_A  = (const float*)d_in[1];
    const float* A3     = (const float*)d_in[2];
    const float* A6     = (const float*)d_in[3];
    const float* alpha  = (const float*)d_in[4];
    const float* beta   = (const float*)d_in[5];
    const float* gamma  = (const float*)d_in[6];
    const float* c1_w   = (const float*)d_in[7];
    const float* c1_b   = (const float*)d_in[8];
    const float* c2_w   = (const float*)d_in[9];
    const float* c2_b   = (const float*)d_in[10];
    const float* c4_w   = (const float*)d_in[11];
    const float* c4_b   = (const float*)d_in[12];
    const float* c3_w   = (const float*)d_in[13];
    const float* c3_b   = (const float*)d_in[14];
    const float* gbn_s  = (const float*)d_in[15];
    const float* gbn_b  = (const float*)d_in[16];
    const float* pw_w   = (const float*)d_in[17];
    const float* pw_b   = (const float*)d_in[18];
    const float* pwbn_s = (const float*)d_in[19];
    const float* pwbn_b = (const float*)d_in[20];
    const float* tc_w   = (const float*)d_in[21];
    const float* tc_b   = (const float*)d_in[22];
    const float* tcbn_s = (const float*)d_in[23];
    const float* tcbn_b = (const float*)d_in[24];
    const float* mpbn_s = (const float*)d_in[25];
    const float* mpbn_b = (const float*)d_in[26];
    float* out = (float*)d_out;

    cudaFuncSetAttribute(k_gemm0_wmma, cudaFuncAttributeMaxDynamicSharedMemorySize, GEMM0_SMEM);
    cudaFuncSetAttribute(k_pw_wmma,    cudaFuncAttributeMaxDynamicSharedMemorySize, PW_SMEM);
    cudaFuncSetAttribute(k_tc2,        cudaFuncAttributeMaxDynamicSharedMemorySize, TC_SMEM);

    size_t xtot = (size_t)Nn * Cc * TV;
    k_prep_xh<<<(int)((xtot / 8 + 255) / 256), 256>>>(x);           // 1
    k_prep_wh<<<16, 256>>>(c3_w, pw_w);                             // 2
    k_xm<<<Nn * Cc, 128>>>(x);                                      // 3
    k_gemm0_wmma<<<dim3(50, 1, Nn), 256, GEMM0_SMEM>>>(c3_b);       // 4 <- profiled
    k_rel<<<Nn * Ss, 256>>>(spd_A, A3, A6, alpha, beta, gamma,
                            c1_w, c1_b, c2_w, c2_b, c4_w, c4_b);    // 5
    k_y<<<Nn * OUTo, 128>>>(x, gbn_s, gbn_b);                       // 6
    k_pw_wmma<<<dim3(50, 1, Nn), 256, PW_SMEM>>>(x, pw_b, pwbn_s, pwbn_b, out);
    k_tc2<<<dim3(16, Nn, 2), 640, TC_SMEM>>>(tc_w, tc_b, tcbn_s, tcbn_b, x, out);
    k_mp<<<(Nn * BCc * TV + 255) / 256, 256>>>(mpbn_s, mpbn_b, x, out);
}

// round 15
// speedup vs baseline: 1.7354x; 1.0013x over previous
#include <cuda_runtime.h>
#include <cuda_fp16.h>
#include <math.h>
#include <stdint.h>
#include <mma.h>

using namespace nvcuda;

#define Nn 32
#define Cc 96
#define Tt 256
#define Vv 25
#define Ss 3
#define RELr 12
#define OUTo 96
#define BCc 24
#define TV (Tt*Vv)   // 6400

typedef unsigned long long u64;

__device__ __forceinline__ u64 splat2(float x) {
    u64 r;
    asm("mov.b64 %0, {%1, %1};" : "=l"(r) : "f"(x));
    return r;
}
__device__ __forceinline__ void ffma2(u64& d, u64 a, u64 b) {
    asm("fma.rn.f32x2 %0, %1, %2, %0;" : "+l"(d) : "l"(a), "l"(b));
}
__device__ __forceinline__ void unpack2(float& lo, float& hi, u64 v) {
    asm("mov.b64 {%0, %1}, %2;" : "=f"(lo), "=f"(hi) : "l"(v));
}

// ---------------- scratch ----------------------------------------------------
__device__ float  g_xm[Nn*Cc*Vv];
__device__ float  g_A [(size_t)Nn*Ss*OUTo*Vv*Vv];
__device__ __half g_x3[(size_t)Nn*Ss*OUTo*TV];
__device__ __half g_yh[(size_t)Nn*OUTo*TV];
__device__ __half g_xh[(size_t)Nn*Cc*TV];
__device__ __half g_c3h[Ss*96*96];
__device__ __half g_pwh[96*96];
__device__ float  g_H0[(size_t)Nn*BCc*TV];
__device__ float  g_H1[(size_t)Nn*BCc*TV];
__device__ float  g_H2[(size_t)Nn*BCc*TV];

// ---------------- P1: weights -> fp16 -----------------------------------------
__global__ void k_prep_wh(const float* __restrict__ c3w, const float* __restrict__ pww) {
    for (int i = threadIdx.x + blockIdx.x * 256; i < Ss * 96 * 96 + 96 * 96;
         i += gridDim.x * 256) {
        if (i < Ss * 96 * 96) g_c3h[i] = __float2half(c3w[i]);
        else                  g_pwh[i - Ss * 96 * 96] = __float2half(pww[i - Ss * 96 * 96]);
    }
}

// ---------------- K1: x -> fp16 + mean over T (fused) -------------------------
__global__ void k_xm(const float* __restrict__ x, int nc0) {
    int nc = nc0 + blockIdx.x;
    const float* xp = x + (size_t)nc * TV;
    __half* xh = g_xh + (size_t)nc * TV;

    for (int l = threadIdx.x * 8; l < TV; l += 128 * 8) {
        float4 a = *(const float4*)&xp[l];
        float4 b = *(const float4*)&xp[l + 4];
        __half2 h[4];
        h[0] = __floats2half2_rn(a.x, a.y);
        h[1] = __floats2half2_rn(a.z, a.w);
        h[2] = __floats2half2_rn(b.x, b.y);
        h[3] = __floats2half2_rn(b.z, b.w);
        *(uint4*)&xh[l] = *(uint4*)h;
    }

    float acc[Vv];
#pragma unroll
    for (int v = 0; v < Vv; v++) acc[v] = 0.f;
    for (int t = threadIdx.x; t < Tt; t += 128) {
        const float* row = xp + t * Vv;
#pragma unroll
        for (int v = 0; v < Vv; v++) acc[v] += row[v];
    }
    __shared__ float s[Vv][128];
#pragma unroll
    for (int v = 0; v < Vv; v++) s[v][threadIdx.x] = acc[v];
    __syncthreads();
    if (threadIdx.x < Vv) {
        float r = 0.f;
#pragma unroll 8
        for (int i = 0; i < 128; i++) r += s[threadIdx.x][i];
        g_xm[nc * Vv + threadIdx.x] = r * (1.f / Tt);
    }
}

// ---------------- K2: CTRGC relation -> A_at ---------------------------------
__global__ void k_rel(const float* __restrict__ spd, const float* __restrict__ A3,
                      const float* __restrict__ A6,
                      const float* __restrict__ alpha, const float* __restrict__ beta,
                      const float* __restrict__ gamma,
                      const float* __restrict__ c1w, const float* __restrict__ c1b,
                      const float* __restrict__ c2w, const float* __restrict__ c2b,
                      const float* __restrict__ c4w, const float* __restrict__ c4b) {
    int n = blockIdx.x / Ss, s = blockIdx.x % Ss;
    int tid = threadIdx.x;
    __shared__ float xm_s[Cc * Vv];
    __shared__ float x1s[RELr * Vv];
    __shared__ float x2s[RELr * Vv];
    __shared__ float Rs[RELr * Vv * Vv];
    __shared__ float base_s[Vv * Vv];

    for (int i = tid; i < Cc * Vv; i += 256) xm_s[i] = g_xm[n * Cc * Vv + i];
    __syncthreads();

    for (int i = tid; i < 2 * RELr * Vv; i += 256) {
        int which = i / (RELr * Vv);
        int rv = i % (RELr * Vv);
        int r = rv / Vv, v = rv % Vv;
        const float* w = (which ? c2w : c1w) + (s * RELr + r) * Cc;
        float acc = (which ? c2b : c1b)[s * RELr + r];
#pragma unroll 8
        for (int c = 0; c < Cc; c++) acc += w[c] * xm_s[c * Vv + v];
        (which ? x2s : x1s)[rv] = acc;
    }
    __syncthreads();

    float ga = __ldg(gamma);
    for (int i = tid; i < RELr * Vv * Vv; i += 256) {
        int r = i / (Vv * Vv);
        int uv = i % (Vv * Vv);
        int u = uv / Vv, v = uv % Vv;
        Rs[i] = tanhf(x1s[r * Vv + u] - x2s[r * Vv + v]);
    }
    for (int i = tid; i < Vv * Vv; i += 256)
        base_s[i] = __ldg(&A3[s * 625 + i]) + __ldg(&spd[i]) * ga;
    __syncthreads();

    float al = __ldg(alpha), be = __ldg(beta);
    float* Aout = g_A + (size_t)(n * Ss + s) * OUTo * 625;
    for (int o = 0; o < OUTo; o++) {
        float w4[RELr];
#pragma unroll
        for (int r = 0; r < RELr; r++) w4[r] = __ldg(&c4w[(s * OUTo + o) * RELr + r]);
        float b4 = __ldg(&c4b[s * OUTo + o]);
        const float* A6o = A6 + (o % 6) * 625;
        for (int i = tid; i < 625; i += 256) {
            float m = b4;
#pragma unroll
            for (int r = 0; r < RELr; r++) m += w4[r] * Rs[r * 625 + i];
            Aout[(size_t)o * 625 + i] = m * al + base_s[i] + __ldg(&A6o[i]) * be;
        }
    }
}

// ---------------- K3: x3 via wmma; dual-accumulator ot pairs ------------------
#define BLD 28
__global__ void __launch_bounds__(256)
k_gemm0_wmma(const float* __restrict__ bias) {
    extern __shared__ char smc[];
    __half* Wsm = (__half*)smc;                         // 55296 B
    float*  buf = (float*)(smc + Ss * 96 * 96 * 2);     // 14336 B

    int ct = blockIdx.x;      // 0..49
    int n  = blockIdx.z;
    int tid = threadIdx.x;
    int wid = tid >> 5, lane = tid & 31;
    float* wbuf = buf + wid * 16 * BLD;

    for (int i = tid; i < Ss * 96 * 96 / 8; i += 256)
        *(uint4*)&Wsm[i * 8] = *(const uint4*)&g_c3h[i * 8];

    const __half* Xg = g_xh + (size_t)n * Cc * TV + (size_t)ct * 128 + wid * 16;
    wmma::fragment<wmma::matrix_b, 16, 16, 16, __half, wmma::row_major> b[6];
#pragma unroll
    for (int k = 0; k < 6; k++)
        wmma::load_matrix_sync(b[k], Xg + (size_t)k * 16 * TV, TV);
    __syncthreads();

    int r = lane >> 1, c0 = (lane & 1) * 8;

    for (int s = 0; s < Ss; s++) {
        const __half* Wg = Wsm + s * 96 * 96;
        __half* Obase = g_x3 + ((size_t)(n * Ss + s) * OUTo) * TV
                        + (size_t)ct * 128 + wid * 16 + c0;
#pragma unroll
        for (int op = 0; op < 3; op++) {
            wmma::fragment<wmma::accumulator, 16, 16, 16, float> d0, d1;
            wmma::fill_fragment(d0, 0.f);
            wmma::fill_fragment(d1, 0.f);
#pragma unroll
            for (int k = 0; k < 6; k++) {
                wmma::fragment<wmma::matrix_a, 16, 16, 16, __half, wmma::row_major> a0, a1;
                wmma::load_matrix_sync(a0, Wg + (2 * op) * 16 * 96 + k * 16, 96);
                wmma::load_matrix_sync(a1, Wg + (2 * op + 1) * 16 * 96 + k * 16, 96);
                wmma::mma_sync(d0, a0, b[k], d0);
                wmma::mma_sync(d1, a1, b[k], d1);
            }
#pragma unroll
            for (int e = 0; e < 2; e++) {
                wmma::store_matrix_sync(wbuf, e ? d1 : d0, BLD, wmma::mem_row_major);
                __syncwarp();
                int ot = 2 * op + e;
                float bv = __ldg(&bias[s * 96 + ot * 16 + r]);
                const float* bp = &wbuf[r * BLD + c0];
                __half2 h[4];
#pragma unroll
                for (int q = 0; q < 4; q++)
                    h[q] = __floats2half2_rn(bp[2 * q] + bv, bp[2 * q + 1] + bv);
                *(uint4*)&Obase[(size_t)(ot * 16 + r) * TV] = *(uint4*)h;
                __syncwarp();
            }
        }
    }
}

// ---------------- K5: pointwise convs via wmma; dual accumulators -------------
__global__ void __launch_bounds__(256)
k_pw_wmma(const float* __restrict__ xglob, const float* __restrict__ bias,
          const float* __restrict__ bn_s, const float* __restrict__ bn_b,
          float* __restrict__ outbuf) {
    extern __shared__ char smc[];
    __half* Wsm = (__half*)smc;                         // 18432 B
    float*  buf = (float*)(smc + 96 * 96 * 2);          // 14336 B

    int ct = blockIdx.x;
    int n  = blockIdx.z;
    int tid = threadIdx.x;
    int wid = tid >> 5, lane = tid & 31;
    float* wbuf = buf + wid * 16 * BLD;

    for (int i = tid; i < 96 * 96 / 8; i += 256)
        *(uint4*)&Wsm[i * 8] = *(const uint4*)&g_pwh[i * 8];

    const __half* Yg = g_yh + (size_t)n * Cc * TV + (size_t)ct * 128 + wid * 16;
    wmma::fragment<wmma::matrix_b, 16, 16, 16, __half, wmma::row_major> b[6];
#pragma unroll
    for (int k = 0; k < 6; k++)
        wmma::load_matrix_sync(b[k], Yg + (size_t)k * 16 * TV, TV);
    __syncthreads();

    int r = lane >> 1, c0 = (lane & 1) * 8;
    int colg = ct * 128 + wid * 16 + c0;

#pragma unroll
    for (int op = 0; op < 3; op++) {
        wmma::fragment<wmma::accumulator, 16, 16, 16, float> d0, d1;
        wmma::fill_fragment(d0, 0.f);
        wmma::fill_fragment(d1, 0.f);
#pragma unroll
        for (int k = 0; k < 6; k++) {
            wmma::fragment<wmma::matrix_a, 16, 16, 16, __half, wmma::row_major> a0, a1;
            wmma::load_matrix_sync(a0, Wsm + (2 * op) * 16 * 96 + k * 16, 96);
            wmma::load_matrix_sync(a1, Wsm + (2 * op + 1) * 16 * 96 + k * 16, 96);
            wmma::mma_sync(d0, a0, b[k], d0);
            wmma::mma_sync(d1, a1, b[k], d1);
        }
#pragma unroll
        for (int e = 0; e < 2; e++) {
            wmma::store_matrix_sync(wbuf, e ? d1 : d0, BLD, wmma::mem_row_major);
            __syncwarp();
            int ot = 2 * op + e;
            int rg = ot * 16 + r;
            int br = rg / 24, bc = rg % 24;
            float bv = __ldg(&bias[rg]);
            float sc = __ldg(&bn_s[rg]), sh = __ldg(&bn_b[rg]);
            const float* bp = &wbuf[r * BLD + c0];
            float w[8];
#pragma unroll
            for (int j = 0; j < 8; j++) w[j] = (bp[j] + bv) * sc + sh;
            if (br < 3) {
                float* dst = (br == 0) ? g_H0 : (br == 1) ? g_H1 : g_H2;
                size_t hi = (size_t)(n * BCc + bc) * TV + colg;
                float4 q0 = {fmaxf(w[0],0.f), fmaxf(w[1],0.f), fmaxf(w[2],0.f), fmaxf(w[3],0.f)};
                float4 q1 = {fmaxf(w[4],0.f), fmaxf(w[5],0.f), fmaxf(w[6],0.f), fmaxf(w[7],0.f)};
                *(float4*)&dst[hi]     = q0;
                *(float4*)&dst[hi + 4] = q1;
            } else {
                size_t oi = ((size_t)n * OUTo + 72 + bc) * TV + colg;
                float4 r0 = *(const float4*)&xglob[oi];
                float4 r1 = *(const float4*)&xglob[oi + 4];
                float4 q0 = {fmaxf(w[0]+r0.x,0.f), fmaxf(w[1]+r0.y,0.f),
                             fmaxf(w[2]+r0.z,0.f), fmaxf(w[3]+r0.w,0.f)};
                float4 q1 = {fmaxf(w[4]+r1.x,0.f), fmaxf(w[5]+r1.y,0.f),
                             fmaxf(w[6]+r1.z,0.f), fmaxf(w[7]+r1.w,0.f)};
                *(float4*)&outbuf[oi]     = q0;
                *(float4*)&outbuf[oi + 4] = q1;
            }
            __syncwarp();
        }
    }
}

// ---------------- K4: y(fp16) = relu(bn(sum_s A_s @ x3_s) + x) -----------------
__global__ void k_y(const float* __restrict__ x, const float* __restrict__ gbn_s,
                    const float* __restrict__ gbn_b) {
    int no = blockIdx.x;
    int n = no / OUTo, o = no % OUTo;
    int tid = threadIdx.x;        // 128

    __shared__ __align__(16) float As[Ss * Vv * 28];
    __shared__ __align__(16) float Xs[Vv * 257 + 7];

    for (int i = tid; i < Ss * 625; i += 128) {
        int s = i / 625;
        int rem = i - s * 625;
        int u = rem / 25, v = rem - u * 25;
        As[(s * 25 + v) * 28 + u] =
            g_A[(((size_t)(n * Ss + s)) * OUTo + o) * 625 + rem];
    }
    for (int i = tid; i < Ss * Vv * 3; i += 128) {
        int sv = i / 3, pu = 25 + i % 3;
        As[sv * 28 + pu] = 0.f;
    }

    u64 acc2[13][2];
#pragma unroll
    for (int p = 0; p < 13; p++) { acc2[p][0] = 0ull; acc2[p][1] = 0ull; }

    int t0 = tid, t1 = tid + 128;
#pragma unroll
    for (int s = 0; s < Ss; s++) {
        __syncthreads();
        const __half* base = g_x3 + (((size_t)(n * Ss + s)) * OUTo + o) * TV;
        for (int l = tid * 8; l < TV; l += 1024) {
            uint4 w = *(const uint4*)&base[l];
            const __half2* hp = (const __half2*)&w;
            float2 f0 = __half22float2(hp[0]);
            float2 f1 = __half22float2(hp[1]);
            float2 f2 = __half22float2(hp[2]);
            float2 f3 = __half22float2(hp[3]);
            float4 q0 = {f0.x, f0.y, f1.x, f1.y};
            float4 q1 = {f2.x, f2.y, f3.x, f3.y};
            *(float4*)&Xs[l]     = q0;
            *(float4*)&Xs[l + 4] = q1;
        }
        __syncthreads();
        const float* A2 = As + s * Vv * 28;
#pragma unroll
        for (int v = 0; v < Vv; v++) {
            u64 xa = splat2(Xs[t0 * Vv + v]);
            u64 xb = splat2(Xs[t1 * Vv + v]);
            const float* ar = A2 + v * 28;
#pragma unroll
            for (int p = 0; p < 13; p++) {
                u64 ap = *(const u64*)&ar[2 * p];
                ffma2(acc2[p][0], ap, xa);
                ffma2(acc2[p][1], ap, xb);
            }
        }
    }

    float gs = __ldg(&gbn_s[o]), gb = __ldg(&gbn_b[o]);
    __syncthreads();
#pragma unroll
    for (int p = 0; p < 13; p++) {
        float lo0, hi0, lo1, hi1;
        unpack2(lo0, hi0, acc2[p][0]);
        unpack2(lo1, hi1, acc2[p][1]);
        int u = 2 * p;
        Xs[u * 257 + t0] = lo0 * gs + gb;
        Xs[u * 257 + t1] = lo1 * gs + gb;
        if (u + 1 < Vv) {
            Xs[(u + 1) * 257 + t0] = hi0 * gs + gb;
            Xs[(u + 1) * 257 + t1] = hi1 * gs + gb;
        }
    }
    __syncthreads();

    size_t obase = ((size_t)n * OUTo + o) * TV;
    const float* xo = x + obase;
    __half* yh = g_yh + obase;
    for (int l = tid * 4; l < TV; l += 512) {
        float4 r = *(const float4*)&xo[l];
        float rr[4] = {r.x, r.y, r.z, r.w};
        float w[4];
#pragma unroll
        for (int k = 0; k < 4; k++) {
            int idx = l + k;
            int tt = (int)(((unsigned)idx * 5243u) >> 17);
            int vv = idx - tt * 25;
            w[k] = fmaxf(Xs[vv * 257 + tt] + rr[k], 0.f);
        }
        __half2 h[2];
        h[0] = __floats2half2_rn(w[0], w[1]);
        h[1] = __floats2half2_rn(w[2], w[3]);
        *(uint2*)&yh[l] = *(uint2*)h;
    }
}

// ---------------- K6: dilated temporal convs ----------------------------------
__global__ void k_tc2(const float* __restrict__ tcw, const float* __restrict__ tcb,
                      const float* __restrict__ tcbn_s, const float* __restrict__ tcbn_b,
                      const float* __restrict__ x, float* __restrict__ out) {
    extern __shared__ float sm[];
    float* Hs = sm;              // 24*600
    float* ws = sm + 14400;      // 2880

    int br = blockIdx.z;
    int n  = blockIdx.y;
    int t0 = blockIdx.x * 16;
    int tid = threadIdx.x;

    for (int i = tid; i < BCc * BCc * 5; i += 640)
        ws[i] = tcw[br * BCc * BCc * 5 + i];

    const float* H = (br == 0 ? g_H0 : g_H1) + (size_t)n * BCc * TV;
    int base = (t0 - 4) * 25;
    for (int i = tid; i < 24 * 600; i += 640) {
        int ic = i / 600;
        int rem = i - ic * 600;
        int tg25 = base + rem;
        float val = 0.f;
        if (tg25 >= 0 && tg25 < TV) val = H[(size_t)ic * TV + tg25];
        Hs[i] = val;
    }
    __syncthreads();
    if (tid >= BCc * Vv) return;
    int oc = tid / Vv, v = tid - oc * Vv;

    float bias = __ldg(&tcb[br * BCc + oc]);
    float sc = __ldg(&tcbn_s[br * BCc + oc]), sh = __ldg(&tcbn_b[br * BCc + oc]);

    float acc[16];
#pragma unroll
    for (int j = 0; j < 16; j++) acc[j] = bias;

    for (int ic = 0; ic < BCc; ic++) {
        float h[24];
        const float* hp = Hs + ic * 600 + v;
#pragma unroll
        for (int i = 0; i < 24; i++) h[i] = hp[i * 25];
        const float* wp = ws + (oc * BCc + ic) * 5;
        if (br == 0) {
#pragma unroll
            for (int k = 0; k < 5; k++) {
                float wv = wp[k];
#pragma unroll
                for (int j = 0; j < 16; j++) acc[j] += wv * h[j + k + 2];
            }
        } else {
#pragma unroll
            for (int k = 0; k < 5; k++) {
                float wv = wp[k];
#pragma unroll
                for (int j = 0; j < 16; j++) acc[j] += wv * h[j + 2 * k];
            }
        }
    }

#pragma unroll
    for (int j = 0; j < 16; j++) {
        int tg = t0 + j;
        size_t oi = ((size_t)n * OUTo + br * BCc + oc) * TV + (size_t)tg * Vv + v;
        out[oi] = fmaxf(acc[j] * sc + sh + __ldg(&x[oi]), 0.f);
    }
}

// ---------------- K7: maxpool branch -----------------------------------------
__global__ void k_mp(const float* __restrict__ mpbn_s, const float* __restrict__ mpbn_b,
                     const float* __restrict__ x, float* __restrict__ out) {
    int idx = blockIdx.x * 256 + threadIdx.x;
    if (idx >= Nn * BCc * TV) return;
    int v = idx % Vv;
    int t = (idx / Vv) % Tt;
    int bc = (idx / TV) % BCc;
    int n = idx / (TV * BCc);
    const float* H = g_H2 + (size_t)(n * BCc + bc) * TV;
    float m = H[t * Vv + v];
    if (t > 0)   m = fmaxf(m, H[(t - 1) * Vv + v]);
    if (t < 255) m = fmaxf(m, H[(t + 1) * Vv + v]);
    float val = m * __ldg(&mpbn_s[bc]) + __ldg(&mpbn_b[bc]);
    size_t oi = ((size_t)n * OUTo + 48 + bc) * TV + (size_t)t * Vv + v;
    out[oi] = fmaxf(val + __ldg(&x[oi]), 0.f);
}

// ---------------- driver ------------------------------------------------------
#define GEMM0_SMEM (Ss*96*96*2 + 8*16*BLD*4)    // 69632
#define PW_SMEM    (96*96*2 + 8*16*BLD*4)       // 32768
#define TC_SMEM    ((24*600 + 24*24*5) * 4)

extern "C" void kernel_launch(void* const* d_in, const int* in_sizes, int n_in,
                              void* d_out, int out_size) {
    const float* x      = (const float*)d_in[0];
    const float* spd_A  = (const float*)d_in[1];
    const float* A3     = (const float*)d_in[2];
    const float* A6     = (const float*)d_in[3];
    const float* alpha  = (const float*)d_in[4];
    const float* beta   = (const float*)d_in[5];
    const float* gamma  = (const float*)d_in[6];
    const float* c1_w   = (const float*)d_in[7];
    const float* c1_b   = (const float*)d_in[8];
    const float* c2_w   = (const float*)d_in[9];
    const float* c2_b   = (const float*)d_in[10];
    const float* c4_w   = (const float*)d_in[11];
    const float* c4_b   = (const float*)d_in[12];
    const float* c3_w   = (const float*)d_in[13];
    const float* c3_b   = (const float*)d_in[14];
    const float* gbn_s  = (const float*)d_in[15];
    const float* gbn_b  = (const float*)d_in[16];
    const float* pw_w   = (const float*)d_in[17];
    const float* pw_b   = (const float*)d_in[18];
    const float* pwbn_s = (const float*)d_in[19];
    const float* pwbn_b = (const float*)d_in[20];
    const float* tc_w   = (const float*)d_in[21];
    const float* tc_b   = (const float*)d_in[22];
    const float* tcbn_s = (const float*)d_in[23];
    const float* tcbn_b = (const float*)d_in[24];
    const float* mpbn_s = (const float*)d_in[25];
    const float* mpbn_b = (const float*)d_in[26];
    float* out = (float*)d_out;

    cudaFuncSetAttribute(k_gemm0_wmma, cudaFuncAttributeMaxDynamicSharedMemorySize, GEMM0_SMEM);
    cudaFuncSetAttribute(k_pw_wmma,    cudaFuncAttributeMaxDynamicSharedMemorySize, PW_SMEM);
    cudaFuncSetAttribute(k_tc2,        cudaFuncAttributeMaxDynamicSharedMemorySize, TC_SMEM);

    k_prep_wh<<<16, 256>>>(c3_w, pw_w);                             // 1
    k_xm<<<Nn * Cc / 2, 128>>>(x, 0);                               // 2
    k_xm<<<Nn * Cc / 2, 128>>>(x, Nn * Cc / 2);                     // 3
    k_gemm0_wmma<<<dim3(50, 1, Nn), 256, GEMM0_SMEM>>>(c3_b);       // 4 <- profiled
    k_rel<<<Nn * Ss, 256>>>(spd_A, A3, A6, alpha, beta, gamma,
                            c1_w, c1_b, c2_w, c2_b, c4_w, c4_b);    // 5
    k_y<<<Nn * OUTo, 128>>>(x, gbn_s, gbn_b);                       // 6
    k_pw_wmma<<<dim3(50, 1, Nn), 256, PW_SMEM>>>(x, pw_b, pwbn_s, pwbn_b, out);
    k_tc2<<<dim3(16, Nn, 2), 640, TC_SMEM>>>(tc_w, tc_b, tcbn_s, tcbn_b, x, out);
    k_mp<<<(Nn * BCc * TV + 255) / 256, 256>>>(mpbn_s, mpbn_b, x, out);
}

// round 16
// speedup vs baseline: 1.7575x; 1.0127x over previous
#include <cuda_runtime.h>
#include <cuda_fp16.h>
#include <math.h>
#include <stdint.h>
#include <mma.h>

using namespace nvcuda;

#define Nn 32
#define Cc 96
#define Tt 256
#define Vv 25
#define Ss 3
#define RELr 12
#define OUTo 96
#define BCc 24
#define TV (Tt*Vv)   // 6400

typedef unsigned long long u64;

__device__ __forceinline__ u64 splat2(float x) {
    u64 r;
    asm("mov.b64 %0, {%1, %1};" : "=l"(r) : "f"(x));
    return r;
}
__device__ __forceinline__ void ffma2(u64& d, u64 a, u64 b) {
    asm("fma.rn.f32x2 %0, %1, %2, %0;" : "+l"(d) : "l"(a), "l"(b));
}
__device__ __forceinline__ void unpack2(float& lo, float& hi, u64 v) {
    asm("mov.b64 {%0, %1}, %2;" : "=f"(lo), "=f"(hi) : "l"(v));
}

// ---------------- scratch ----------------------------------------------------
__device__ float  g_xm[Nn*Cc*Vv];
__device__ float  g_A [(size_t)Nn*Ss*OUTo*Vv*Vv];
__device__ __half g_x3[(size_t)Nn*Ss*OUTo*TV];
__device__ __half g_yh[(size_t)Nn*OUTo*TV];
__device__ __half g_xh[(size_t)Nn*Cc*TV];
__device__ __half g_c3h[Ss*96*96];
__device__ __half g_pwh[96*96];
__device__ float  g_H0[(size_t)Nn*BCc*TV];
__device__ float  g_H1[(size_t)Nn*BCc*TV];
__device__ float  g_H2[(size_t)Nn*BCc*TV];

// ---------------- P1: weights -> fp16 -----------------------------------------
__global__ void k_prep_wh(const float* __restrict__ c3w, const float* __restrict__ pww) {
    for (int i = threadIdx.x + blockIdx.x * 256; i < Ss * 96 * 96 + 96 * 96;
         i += gridDim.x * 256) {
        if (i < Ss * 96 * 96) g_c3h[i] = __float2half(c3w[i]);
        else                  g_pwh[i - Ss * 96 * 96] = __float2half(pww[i - Ss * 96 * 96]);
    }
}

// ---------------- K1: x -> fp16 + mean over T (fused) -------------------------
__global__ void k_xm(const float* __restrict__ x, int nc0) {
    int nc = nc0 + blockIdx.x;
    const float* xp = x + (size_t)nc * TV;
    __half* xh = g_xh + (size_t)nc * TV;

    for (int l = threadIdx.x * 8; l < TV; l += 128 * 8) {
        float4 a = *(const float4*)&xp[l];
        float4 b = *(const float4*)&xp[l + 4];
        __half2 h[4];
        h[0] = __floats2half2_rn(a.x, a.y);
        h[1] = __floats2half2_rn(a.z, a.w);
        h[2] = __floats2half2_rn(b.x, b.y);
        h[3] = __floats2half2_rn(b.z, b.w);
        *(uint4*)&xh[l] = *(uint4*)h;
    }

    float acc[Vv];
#pragma unroll
    for (int v = 0; v < Vv; v++) acc[v] = 0.f;
    for (int t = threadIdx.x; t < Tt; t += 128) {
        const float* row = xp + t * Vv;
#pragma unroll
        for (int v = 0; v < Vv; v++) acc[v] += row[v];
    }
    __shared__ float s[Vv][128];
#pragma unroll
    for (int v = 0; v < Vv; v++) s[v][threadIdx.x] = acc[v];
    __syncthreads();
    if (threadIdx.x < Vv) {
        float r = 0.f;
#pragma unroll 8
        for (int i = 0; i < 128; i++) r += s[threadIdx.x][i];
        g_xm[nc * Vv + threadIdx.x] = r * (1.f / Tt);
    }
}

// ---------------- K2: CTRGC relation -> A_at ---------------------------------
__global__ void k_rel(const float* __restrict__ spd, const float* __restrict__ A3,
                      const float* __restrict__ A6,
                      const float* __restrict__ alpha, const float* __restrict__ beta,
                      const float* __restrict__ gamma,
                      const float* __restrict__ c1w, const float* __restrict__ c1b,
                      const float* __restrict__ c2w, const float* __restrict__ c2b,
                      const float* __restrict__ c4w, const float* __restrict__ c4b) {
    int n = blockIdx.x / Ss, s = blockIdx.x % Ss;
    int tid = threadIdx.x;
    __shared__ float xm_s[Cc * Vv];
    __shared__ float x1s[RELr * Vv];
    __shared__ float x2s[RELr * Vv];
    __shared__ float Rs[RELr * Vv * Vv];
    __shared__ float base_s[Vv * Vv];

    for (int i = tid; i < Cc * Vv; i += 256) xm_s[i] = g_xm[n * Cc * Vv + i];
    __syncthreads();

    for (int i = tid; i < 2 * RELr * Vv; i += 256) {
        int which = i / (RELr * Vv);
        int rv = i % (RELr * Vv);
        int r = rv / Vv, v = rv % Vv;
        const float* w = (which ? c2w : c1w) + (s * RELr + r) * Cc;
        float acc = (which ? c2b : c1b)[s * RELr + r];
#pragma unroll 8
        for (int c = 0; c < Cc; c++) acc += w[c] * xm_s[c * Vv + v];
        (which ? x2s : x1s)[rv] = acc;
    }
    __syncthreads();

    float ga = __ldg(gamma);
    for (int i = tid; i < RELr * Vv * Vv; i += 256) {
        int r = i / (Vv * Vv);
        int uv = i % (Vv * Vv);
        int u = uv / Vv, v = uv % Vv;
        Rs[i] = tanhf(x1s[r * Vv + u] - x2s[r * Vv + v]);
    }
    for (int i = tid; i < Vv * Vv; i += 256)
        base_s[i] = __ldg(&A3[s * 625 + i]) + __ldg(&spd[i]) * ga;
    __syncthreads();

    float al = __ldg(alpha), be = __ldg(beta);
    float* Aout = g_A + (size_t)(n * Ss + s) * OUTo * 625;
    for (int o = 0; o < OUTo; o++) {
        float w4[RELr];
#pragma unroll
        for (int r = 0; r < RELr; r++) w4[r] = __ldg(&c4w[(s * OUTo + o) * RELr + r]);
        float b4 = __ldg(&c4b[s * OUTo + o]);
        const float* A6o = A6 + (o % 6) * 625;
        for (int i = tid; i < 625; i += 256) {
            float m = b4;
#pragma unroll
            for (int r = 0; r < RELr; r++) m += w4[r] * Rs[r * 625 + i];
            Aout[(size_t)o * 625 + i] = m * al + base_s[i] + __ldg(&A6o[i]) * be;
        }
    }
}

// ---------------- K3: x3 via wmma; one W_s staged at a time (32.8KB smem) -----
#define BLD 28
__global__ void __launch_bounds__(256)
k_gemm0_wmma(const float* __restrict__ bias) {
    extern __shared__ char smc[];
    __half* Wsm = (__half*)smc;                         // 96*96*2 = 18432 B
    float*  buf = (float*)(smc + 96 * 96 * 2);          // 14336 B

    int ct = blockIdx.x;      // 0..49
    int n  = blockIdx.z;
    int tid = threadIdx.x;
    int wid = tid >> 5, lane = tid & 31;
    float* wbuf = buf + wid * 16 * BLD;

    const __half* Xg = g_xh + (size_t)n * Cc * TV + (size_t)ct * 128 + wid * 16;
    wmma::fragment<wmma::matrix_b, 16, 16, 16, __half, wmma::row_major> b[6];
#pragma unroll
    for (int k = 0; k < 6; k++)
        wmma::load_matrix_sync(b[k], Xg + (size_t)k * 16 * TV, TV);

    int r = lane >> 1, c0 = (lane & 1) * 8;

    for (int s = 0; s < Ss; s++) {
        __syncthreads();    // wbuf/Wsm safe to overwrite
        for (int i = tid; i < 96 * 96 / 8; i += 256)
            *(uint4*)&Wsm[i * 8] = *(const uint4*)&g_c3h[s * 96 * 96 + i * 8];
        __syncthreads();

        __half* Obase = g_x3 + ((size_t)(n * Ss + s) * OUTo) * TV
                        + (size_t)ct * 128 + wid * 16 + c0;
#pragma unroll
        for (int op = 0; op < 3; op++) {
            wmma::fragment<wmma::accumulator, 16, 16, 16, float> d0, d1;
            wmma::fill_fragment(d0, 0.f);
            wmma::fill_fragment(d1, 0.f);
#pragma unroll
            for (int k = 0; k < 6; k++) {
                wmma::fragment<wmma::matrix_a, 16, 16, 16, __half, wmma::row_major> a0, a1;
                wmma::load_matrix_sync(a0, Wsm + (2 * op) * 16 * 96 + k * 16, 96);
                wmma::load_matrix_sync(a1, Wsm + (2 * op + 1) * 16 * 96 + k * 16, 96);
                wmma::mma_sync(d0, a0, b[k], d0);
                wmma::mma_sync(d1, a1, b[k], d1);
            }
#pragma unroll
            for (int e = 0; e < 2; e++) {
                wmma::store_matrix_sync(wbuf, e ? d1 : d0, BLD, wmma::mem_row_major);
                __syncwarp();
                int ot = 2 * op + e;
                float bv = __ldg(&bias[s * 96 + ot * 16 + r]);
                const float* bp = &wbuf[r * BLD + c0];
                __half2 h[4];
#pragma unroll
                for (int q = 0; q < 4; q++)
                    h[q] = __floats2half2_rn(bp[2 * q] + bv, bp[2 * q + 1] + bv);
                *(uint4*)&Obase[(size_t)(ot * 16 + r) * TV] = *(uint4*)h;
                __syncwarp();
            }
        }
    }
}

// ---------------- K5: pointwise convs via wmma --------------------------------
__global__ void __launch_bounds__(256)
k_pw_wmma(const float* __restrict__ xglob, const float* __restrict__ bias,
          const float* __restrict__ bn_s, const float* __restrict__ bn_b,
          float* __restrict__ outbuf) {
    extern __shared__ char smc[];
    __half* Wsm = (__half*)smc;                         // 18432 B
    float*  buf = (float*)(smc + 96 * 96 * 2);          // 14336 B

    int ct = blockIdx.x;
    int n  = blockIdx.z;
    int tid = threadIdx.x;
    int wid = tid >> 5, lane = tid & 31;
    float* wbuf = buf + wid * 16 * BLD;

    for (int i = tid; i < 96 * 96 / 8; i += 256)
        *(uint4*)&Wsm[i * 8] = *(const uint4*)&g_pwh[i * 8];

    const __half* Yg = g_yh + (size_t)n * Cc * TV + (size_t)ct * 128 + wid * 16;
    wmma::fragment<wmma::matrix_b, 16, 16, 16, __half, wmma::row_major> b[6];
#pragma unroll
    for (int k = 0; k < 6; k++)
        wmma::load_matrix_sync(b[k], Yg + (size_t)k * 16 * TV, TV);
    __syncthreads();

    int r = lane >> 1, c0 = (lane & 1) * 8;
    int colg = ct * 128 + wid * 16 + c0;

#pragma unroll
    for (int op = 0; op < 3; op++) {
        wmma::fragment<wmma::accumulator, 16, 16, 16, float> d0, d1;
        wmma::fill_fragment(d0, 0.f);
        wmma::fill_fragment(d1, 0.f);
#pragma unroll
        for (int k = 0; k < 6; k++) {
            wmma::fragment<wmma::matrix_a, 16, 16, 16, __half, wmma::row_major> a0, a1;
            wmma::load_matrix_sync(a0, Wsm + (2 * op) * 16 * 96 + k * 16, 96);
            wmma::load_matrix_sync(a1, Wsm + (2 * op + 1) * 16 * 96 + k * 16, 96);
            wmma::mma_sync(d0, a0, b[k], d0);
            wmma::mma_sync(d1, a1, b[k], d1);
        }
#pragma unroll
        for (int e = 0; e < 2; e++) {
            wmma::store_matrix_sync(wbuf, e ? d1 : d0, BLD, wmma::mem_row_major);
            __syncwarp();
            int ot = 2 * op + e;
            int rg = ot * 16 + r;
            int br = rg / 24, bc = rg % 24;
            float bv = __ldg(&bias[rg]);
            float sc = __ldg(&bn_s[rg]), sh = __ldg(&bn_b[rg]);
            const float* bp = &wbuf[r * BLD + c0];
            float w[8];
#pragma unroll
            for (int j = 0; j < 8; j++) w[j] = (bp[j] + bv) * sc + sh;
            if (br < 3) {
                float* dst = (br == 0) ? g_H0 : (br == 1) ? g_H1 : g_H2;
                size_t hi = (size_t)(n * BCc + bc) * TV + colg;
                float4 q0 = {fmaxf(w[0],0.f), fmaxf(w[1],0.f), fmaxf(w[2],0.f), fmaxf(w[3],0.f)};
                float4 q1 = {fmaxf(w[4],0.f), fmaxf(w[5],0.f), fmaxf(w[6],0.f), fmaxf(w[7],0.f)};
                *(float4*)&dst[hi]     = q0;
                *(float4*)&dst[hi + 4] = q1;
            } else {
                size_t oi = ((size_t)n * OUTo + 72 + bc) * TV + colg;
                float4 r0 = *(const float4*)&xglob[oi];
                float4 r1 = *(const float4*)&xglob[oi + 4];
                float4 q0 = {fmaxf(w[0]+r0.x,0.f), fmaxf(w[1]+r0.y,0.f),
                             fmaxf(w[2]+r0.z,0.f), fmaxf(w[3]+r0.w,0.f)};
                float4 q1 = {fmaxf(w[4]+r1.x,0.f), fmaxf(w[5]+r1.y,0.f),
                             fmaxf(w[6]+r1.z,0.f), fmaxf(w[7]+r1.w,0.f)};
                *(float4*)&outbuf[oi]     = q0;
                *(float4*)&outbuf[oi + 4] = q1;
            }
            __syncwarp();
        }
    }
}

// ---------------- K4: y(fp16) = relu(bn(sum_s A_s @ x3_s) + x) -----------------
__global__ void k_y(const float* __restrict__ x, const float* __restrict__ gbn_s,
                    const float* __restrict__ gbn_b) {
    int no = blockIdx.x;
    int n = no / OUTo, o = no % OUTo;
    int tid = threadIdx.x;        // 128

    __shared__ __align__(16) float As[Ss * Vv * 28];
    __shared__ __align__(16) float Xs[Vv * 257 + 7];

    for (int i = tid; i < Ss * 625; i += 128) {
        int s = i / 625;
        int rem = i - s * 625;
        int u = rem / 25, v = rem - u * 25;
        As[(s * 25 + v) * 28 + u] =
            g_A[(((size_t)(n * Ss + s)) * OUTo + o) * 625 + rem];
    }
    for (int i = tid; i < Ss * Vv * 3; i += 128) {
        int sv = i / 3, pu = 25 + i % 3;
        As[sv * 28 + pu] = 0.f;
    }

    u64 acc2[13][2];
#pragma unroll
    for (int p = 0; p < 13; p++) { acc2[p][0] = 0ull; acc2[p][1] = 0ull; }

    int t0 = tid, t1 = tid + 128;
#pragma unroll
    for (int s = 0; s < Ss; s++) {
        __syncthreads();
        const __half* base = g_x3 + (((size_t)(n * Ss + s)) * OUTo + o) * TV;
        for (int l = tid * 8; l < TV; l += 1024) {
            uint4 w = *(const uint4*)&base[l];
            const __half2* hp = (const __half2*)&w;
            float2 f0 = __half22float2(hp[0]);
            float2 f1 = __half22float2(hp[1]);
            float2 f2 = __half22float2(hp[2]);
            float2 f3 = __half22float2(hp[3]);
            float4 q0 = {f0.x, f0.y, f1.x, f1.y};
            float4 q1 = {f2.x, f2.y, f3.x, f3.y};
            *(float4*)&Xs[l]     = q0;
            *(float4*)&Xs[l + 4] = q1;
        }
        __syncthreads();
        const float* A2 = As + s * Vv * 28;
#pragma unroll
        for (int v = 0; v < Vv; v++) {
            u64 xa = splat2(Xs[t0 * Vv + v]);
            u64 xb = splat2(Xs[t1 * Vv + v]);
            const float* ar = A2 + v * 28;
#pragma unroll
            for (int p = 0; p < 13; p++) {
                u64 ap = *(const u64*)&ar[2 * p];
                ffma2(acc2[p][0], ap, xa);
                ffma2(acc2[p][1], ap, xb);
            }
        }
    }

    float gs = __ldg(&gbn_s[o]), gb = __ldg(&gbn_b[o]);
    __syncthreads();
#pragma unroll
    for (int p = 0; p < 13; p++) {
        float lo0, hi0, lo1, hi1;
        unpack2(lo0, hi0, acc2[p][0]);
        unpack2(lo1, hi1, acc2[p][1]);
        int u = 2 * p;
        Xs[u * 257 + t0] = lo0 * gs + gb;
        Xs[u * 257 + t1] = lo1 * gs + gb;
        if (u + 1 < Vv) {
            Xs[(u + 1) * 257 + t0] = hi0 * gs + gb;
            Xs[(u + 1) * 257 + t1] = hi1 * gs + gb;
        }
    }
    __syncthreads();

    size_t obase = ((size_t)n * OUTo + o) * TV;
    const float* xo = x + obase;
    __half* yh = g_yh + obase;
    for (int l = tid * 4; l < TV; l += 512) {
        float4 r = *(const float4*)&xo[l];
        float rr[4] = {r.x, r.y, r.z, r.w};
        float w[4];
#pragma unroll
        for (int k = 0; k < 4; k++) {
            int idx = l + k;
            int tt = (int)(((unsigned)idx * 5243u) >> 17);
            int vv = idx - tt * 25;
            w[k] = fmaxf(Xs[vv * 257 + tt] + rr[k], 0.f);
        }
        __half2 h[2];
        h[0] = __floats2half2_rn(w[0], w[1]);
        h[1] = __floats2half2_rn(w[2], w[3]);
        *(uint2*)&yh[l] = *(uint2*)h;
    }
}

// ---------------- K6: dilated temporal convs ----------------------------------
__global__ void k_tc2(const float* __restrict__ tcw, const float* __restrict__ tcb,
                      const float* __restrict__ tcbn_s, const float* __restrict__ tcbn_b,
                      const float* __restrict__ x, float* __restrict__ out) {
    extern __shared__ float sm[];
    float* Hs = sm;              // 24*600
    float* ws = sm + 14400;      // 2880

    int br = blockIdx.z;
    int n  = blockIdx.y;
    int t0 = blockIdx.x * 16;
    int tid = threadIdx.x;

    for (int i = tid; i < BCc * BCc * 5; i += 640)
        ws[i] = tcw[br * BCc * BCc * 5 + i];

    const float* H = (br == 0 ? g_H0 : g_H1) + (size_t)n * BCc * TV;
    int base = (t0 - 4) * 25;
    for (int i = tid; i < 24 * 600; i += 640) {
        int ic = i / 600;
        int rem = i - ic * 600;
        int tg25 = base + rem;
        float val = 0.f;
        if (tg25 >= 0 && tg25 < TV) val = H[(size_t)ic * TV + tg25];
        Hs[i] = val;
    }
    __syncthreads();
    if (tid >= BCc * Vv) return;
    int oc = tid / Vv, v = tid - oc * Vv;

    float bias = __ldg(&tcb[br * BCc + oc]);
    float sc = __ldg(&tcbn_s[br * BCc + oc]), sh = __ldg(&tcbn_b[br * BCc + oc]);

    float acc[16];
#pragma unroll
    for (int j = 0; j < 16; j++) acc[j] = bias;

    for (int ic = 0; ic < BCc; ic++) {
        float h[24];
        const float* hp = Hs + ic * 600 + v;
#pragma unroll
        for (int i = 0; i < 24; i++) h[i] = hp[i * 25];
        const float* wp = ws + (oc * BCc + ic) * 5;
        if (br == 0) {
#pragma unroll
            for (int k = 0; k < 5; k++) {
                float wv = wp[k];
#pragma unroll
                for (int j = 0; j < 16; j++) acc[j] += wv * h[j + k + 2];
            }
        } else {
#pragma unroll
            for (int k = 0; k < 5; k++) {
                float wv = wp[k];
#pragma unroll
                for (int j = 0; j < 16; j++) acc[j] += wv * h[j + 2 * k];
            }
        }
    }

#pragma unroll
    for (int j = 0; j < 16; j++) {
        int tg = t0 + j;
        size_t oi = ((size_t)n * OUTo + br * BCc + oc) * TV + (size_t)tg * Vv + v;
        out[oi] = fmaxf(acc[j] * sc + sh + __ldg(&x[oi]), 0.f);
    }
}

// ---------------- K7: maxpool branch -----------------------------------------
__global__ void k_mp(const float* __restrict__ mpbn_s, const float* __restrict__ mpbn_b,
                     const float* __restrict__ x, float* __restrict__ out) {
    int idx = blockIdx.x * 256 + threadIdx.x;
    if (idx >= Nn * BCc * TV) return;
    int v = idx % Vv;
    int t = (idx / Vv) % Tt;
    int bc = (idx / TV) % BCc;
    int n = idx / (TV * BCc);
    const float* H = g_H2 + (size_t)(n * BCc + bc) * TV;
    float m = H[t * Vv + v];
    if (t > 0)   m = fmaxf(m, H[(t - 1) * Vv + v]);
    if (t < 255) m = fmaxf(m, H[(t + 1) * Vv + v]);
    float val = m * __ldg(&mpbn_s[bc]) + __ldg(&mpbn_b[bc]);
    size_t oi = ((size_t)n * OUTo + 48 + bc) * TV + (size_t)t * Vv + v;
    out[oi] = fmaxf(val + __ldg(&x[oi]), 0.f);
}

// ---------------- driver ------------------------------------------------------
#define GEMM0_SMEM (96*96*2 + 8*16*BLD*4)       // 18432 + 14336 = 32768
#define PW_SMEM    (96*96*2 + 8*16*BLD*4)       // 32768
#define TC_SMEM    ((24*600 + 24*24*5) * 4)

extern "C" void kernel_launch(void* const* d_in, const int* in_sizes, int n_in,
                              void* d_out, int out_size) {
    const float* x      = (const float*)d_in[0];
    const float* spd_A  = (const float*)d_in[1];
    const float* A3     = (const float*)d_in[2];
    const float* A6     = (const float*)d_in[3];
    const float* alpha  = (const float*)d_in[4];
    const float* beta   = (const float*)d_in[5];
    const float* gamma  = (const float*)d_in[6];
    const float* c1_w   = (const float*)d_in[7];
    const float* c1_b   = (const float*)d_in[8];
    const float* c2_w   = (const float*)d_in[9];
    const float* c2_b   = (const float*)d_in[10];
    const float* c4_w   = (const float*)d_in[11];
    const float* c4_b   = (const float*)d_in[12];
    const float* c3_w   = (const float*)d_in[13];
    const float* c3_b   = (const float*)d_in[14];
    const float* gbn_s  = (const float*)d_in[15];
    const float* gbn_b  = (const float*)d_in[16];
    const float* pw_w   = (const float*)d_in[17];
    const float* pw_b   = (const float*)d_in[18];
    const float* pwbn_s = (const float*)d_in[19];
    const float* pwbn_b = (const float*)d_in[20];
    const float* tc_w   = (const float*)d_in[21];
    const float* tc_b   = (const float*)d_in[22];
    const float* tcbn_s = (const float*)d_in[23];
    const float* tcbn_b = (const float*)d_in[24];
    const float* mpbn_s = (const float*)d_in[25];
    const float* mpbn_b = (const float*)d_in[26];
    float* out = (float*)d_out;

    cudaFuncSetAttribute(k_gemm0_wmma, cudaFuncAttributeMaxDynamicSharedMemorySize, GEMM0_SMEM);
    cudaFuncSetAttribute(k_pw_wmma,    cudaFuncAttributeMaxDynamicSharedMemorySize, PW_SMEM);
    cudaFuncSetAttribute(k_tc2,        cudaFuncAttributeMaxDynamicSharedMemorySize, TC_SMEM);

    k_prep_wh<<<16, 256>>>(c3_w, pw_w);                             // 1
    k_xm<<<Nn * Cc / 2, 128>>>(x, 0);                               // 2
    k_xm<<<Nn * Cc / 2, 128>>>(x, Nn * Cc / 2);                     // 3
    k_gemm0_wmma<<<dim3(50, 1, Nn), 256, GEMM0_SMEM>>>(c3_b);       // 4 <- profiled
    k_rel<<<Nn * Ss, 256>>>(spd_A, A3, A6, alpha, beta, gamma,
                            c1_w, c1_b, c2_w, c2_b, c4_w, c4_b);    // 5
    k_y<<<Nn * OUTo, 128>>>(x, gbn_s, gbn_b);                       // 6
    k_pw_wmma<<<dim3(50, 1, Nn), 256, PW_SMEM>>>(x, pw_b, pwbn_s, pwbn_b, out);
    k_tc2<<<dim3(16, Nn, 2), 640, TC_SMEM>>>(tc_w, tc_b, tcbn_s, tcbn_b, x, out);
    k_mp<<<(Nn * BCc * TV + 255) / 256, 256>>>(mpbn_s, mpbn_b, x, out);
}

// round 17
// speedup vs baseline: 1.9020x; 1.0822x over previous
#include <cuda_runtime.h>
#include <cuda_fp16.h>
#include <math.h>
#include <stdint.h>
#include <mma.h>

using namespace nvcuda;

#define Nn 32
#define Cc 96
#define Tt 256
#define Vv 25
#define Ss 3
#define RELr 12
#define OUTo 96
#define BCc 24
#define TV (Tt*Vv)   // 6400

typedef unsigned long long u64;

__device__ __forceinline__ u64 splat2(float x) {
    u64 r;
    asm("mov.b64 %0, {%1, %1};" : "=l"(r) : "f"(x));
    return r;
}
__device__ __forceinline__ void ffma2(u64& d, u64 a, u64 b) {
    asm("fma.rn.f32x2 %0, %1, %2, %0;" : "+l"(d) : "l"(a), "l"(b));
}
__device__ __forceinline__ void unpack2(float& lo, float& hi, u64 v) {
    asm("mov.b64 {%0, %1}, %2;" : "=f"(lo), "=f"(hi) : "l"(v));
}

// ---------------- scratch ----------------------------------------------------
__device__ float  g_xm[Nn*Cc*Vv];
__device__ float  g_A [(size_t)Nn*Ss*OUTo*Vv*Vv];
__device__ __half g_x3[(size_t)Nn*Ss*OUTo*TV];
__device__ __half g_yh[(size_t)Nn*OUTo*TV];
__device__ __half g_xh[(size_t)Nn*Cc*TV];
__device__ __half g_c3h[Ss*96*96];
__device__ __half g_pwh[96*96];
__device__ float  g_H0[(size_t)Nn*BCc*TV];
__device__ float  g_H1[(size_t)Nn*BCc*TV];
__device__ float  g_H2[(size_t)Nn*BCc*TV];

// ---------------- K1: x -> fp16 + mean over T, plus weight prep (tail blocks) --
__global__ void k_xm(const float* __restrict__ x,
                     const float* __restrict__ c3w, const float* __restrict__ pww) {
    int nc = blockIdx.x;
    if (nc >= Nn * Cc) {
        // weight conversion blocks
        int base = (nc - Nn * Cc) * 128 + threadIdx.x;
        for (int i = base; i < Ss * 96 * 96 + 96 * 96; i += 8 * 128) {
            if (i < Ss * 96 * 96) g_c3h[i] = __float2half(c3w[i]);
            else                  g_pwh[i - Ss * 96 * 96] = __float2half(pww[i - Ss * 96 * 96]);
        }
        return;
    }
    const float* xp = x + (size_t)nc * TV;
    __half* xh = g_xh + (size_t)nc * TV;

    for (int l = threadIdx.x * 8; l < TV; l += 128 * 8) {
        float4 a = *(const float4*)&xp[l];
        float4 b = *(const float4*)&xp[l + 4];
        __half2 h[4];
        h[0] = __floats2half2_rn(a.x, a.y);
        h[1] = __floats2half2_rn(a.z, a.w);
        h[2] = __floats2half2_rn(b.x, b.y);
        h[3] = __floats2half2_rn(b.z, b.w);
        *(uint4*)&xh[l] = *(uint4*)h;
    }

    float acc[Vv];
#pragma unroll
    for (int v = 0; v < Vv; v++) acc[v] = 0.f;
    for (int t = threadIdx.x; t < Tt; t += 128) {
        const float* row = xp + t * Vv;
#pragma unroll
        for (int v = 0; v < Vv; v++) acc[v] += row[v];
    }
    __shared__ float s[Vv][128];
#pragma unroll
    for (int v = 0; v < Vv; v++) s[v][threadIdx.x] = acc[v];
    __syncthreads();
    if (threadIdx.x < Vv) {
        float r = 0.f;
#pragma unroll 8
        for (int i = 0; i < 128; i++) r += s[threadIdx.x][i];
        g_xm[nc * Vv + threadIdx.x] = r * (1.f / Tt);
    }
}

// ---------------- K2: CTRGC relation -> A_at ---------------------------------
__global__ void k_rel(const float* __restrict__ spd, const float* __restrict__ A3,
                      const float* __restrict__ A6,
                      const float* __restrict__ alpha, const float* __restrict__ beta,
                      const float* __restrict__ gamma,
                      const float* __restrict__ c1w, const float* __restrict__ c1b,
                      const float* __restrict__ c2w, const float* __restrict__ c2b,
                      const float* __restrict__ c4w, const float* __restrict__ c4b) {
    int n = blockIdx.x / Ss, s = blockIdx.x % Ss;
    int tid = threadIdx.x;
    __shared__ float xm_s[Cc * Vv];
    __shared__ float x1s[RELr * Vv];
    __shared__ float x2s[RELr * Vv];
    __shared__ float Rs[RELr * Vv * Vv];
    __shared__ float base_s[Vv * Vv];

    for (int i = tid; i < Cc * Vv; i += 256) xm_s[i] = g_xm[n * Cc * Vv + i];
    __syncthreads();

    for (int i = tid; i < 2 * RELr * Vv; i += 256) {
        int which = i / (RELr * Vv);
        int rv = i % (RELr * Vv);
        int r = rv / Vv, v = rv % Vv;
        const float* w = (which ? c2w : c1w) + (s * RELr + r) * Cc;
        float acc = (which ? c2b : c1b)[s * RELr + r];
#pragma unroll 8
        for (int c = 0; c < Cc; c++) acc += w[c] * xm_s[c * Vv + v];
        (which ? x2s : x1s)[rv] = acc;
    }
    __syncthreads();

    float ga = __ldg(gamma);
    for (int i = tid; i < RELr * Vv * Vv; i += 256) {
        int r = i / (Vv * Vv);
        int uv = i % (Vv * Vv);
        int u = uv / Vv, v = uv % Vv;
        Rs[i] = tanhf(x1s[r * Vv + u] - x2s[r * Vv + v]);
    }
    for (int i = tid; i < Vv * Vv; i += 256)
        base_s[i] = __ldg(&A3[s * 625 + i]) + __ldg(&spd[i]) * ga;
    __syncthreads();

    float al = __ldg(alpha), be = __ldg(beta);
    float* Aout = g_A + (size_t)(n * Ss + s) * OUTo * 625;
    for (int o = 0; o < OUTo; o++) {
        float w4[RELr];
#pragma unroll
        for (int r = 0; r < RELr; r++) w4[r] = __ldg(&c4w[(s * OUTo + o) * RELr + r]);
        float b4 = __ldg(&c4b[s * OUTo + o]);
        const float* A6o = A6 + (o % 6) * 625;
        for (int i = tid; i < 625; i += 256) {
            float m = b4;
#pragma unroll
            for (int r = 0; r < RELr; r++) m += w4[r] * Rs[r * 625 + i];
            Aout[(size_t)o * 625 + i] = m * al + base_s[i] + __ldg(&A6o[i]) * be;
        }
    }
}

// ---------------- K3: x3 via wmma; A reused over 2 column tiles ---------------
#define BLD 28
__global__ void __launch_bounds__(256)
k_gemm0_wmma(const float* __restrict__ bias) {
    extern __shared__ char smc[];
    __half* Wsm = (__half*)smc;                         // 18432 B
    float*  buf = (float*)(smc + 96 * 96 * 2);          // 14336 B

    int ct = blockIdx.x;      // 0..24 (256-col tiles)
    int n  = blockIdx.z;
    int tid = threadIdx.x;
    int wid = tid >> 5, lane = tid & 31;
    float* wbuf = buf + wid * 16 * BLD;

    const __half* Xg = g_xh + (size_t)n * Cc * TV + (size_t)ct * 256 + wid * 16;
    wmma::fragment<wmma::matrix_b, 16, 16, 16, __half, wmma::row_major> b0[6], b1[6];
#pragma unroll
    for (int k = 0; k < 6; k++) {
        wmma::load_matrix_sync(b0[k], Xg + (size_t)k * 16 * TV, TV);
        wmma::load_matrix_sync(b1[k], Xg + 128 + (size_t)k * 16 * TV, TV);
    }

    int r = lane >> 1, c0 = (lane & 1) * 8;

    for (int s = 0; s < Ss; s++) {
        __syncthreads();
        for (int i = tid; i < 96 * 96 / 8; i += 256)
            *(uint4*)&Wsm[i * 8] = *(const uint4*)&g_c3h[s * 96 * 96 + i * 8];
        __syncthreads();

        __half* Ob0 = g_x3 + ((size_t)(n * Ss + s) * OUTo) * TV
                      + (size_t)ct * 256 + wid * 16 + c0;
        __half* Ob1 = Ob0 + 128;
#pragma unroll
        for (int op = 0; op < 3; op++) {
            wmma::fragment<wmma::accumulator, 16, 16, 16, float> d00, d01, d10, d11;
            wmma::fill_fragment(d00, 0.f);
            wmma::fill_fragment(d01, 0.f);
            wmma::fill_fragment(d10, 0.f);
            wmma::fill_fragment(d11, 0.f);
#pragma unroll
            for (int k = 0; k < 6; k++) {
                wmma::fragment<wmma::matrix_a, 16, 16, 16, __half, wmma::row_major> a0, a1;
                wmma::load_matrix_sync(a0, Wsm + (2 * op) * 16 * 96 + k * 16, 96);
                wmma::load_matrix_sync(a1, Wsm + (2 * op + 1) * 16 * 96 + k * 16, 96);
                wmma::mma_sync(d00, a0, b0[k], d00);
                wmma::mma_sync(d10, a0, b1[k], d10);
                wmma::mma_sync(d01, a1, b0[k], d01);
                wmma::mma_sync(d11, a1, b1[k], d11);
            }
#pragma unroll
            for (int e = 0; e < 4; e++) {
                // e: {ot-sub, tile}: 0=(0,t0) 1=(0,t1) 2=(1,t0) 3=(1,t1)
                wmma::fragment<wmma::accumulator, 16, 16, 16, float>& d =
                    (e == 0) ? d00 : (e == 1) ? d10 : (e == 2) ? d01 : d11;
                int ot = 2 * op + (e >> 1);
                __half* Ob = (e & 1) ? Ob1 : Ob0;
                wmma::store_matrix_sync(wbuf, d, BLD, wmma::mem_row_major);
                __syncwarp();
                float bv = __ldg(&bias[s * 96 + ot * 16 + r]);
                const float* bp = &wbuf[r * BLD + c0];
                __half2 h[4];
#pragma unroll
                for (int q = 0; q < 4; q++)
                    h[q] = __floats2half2_rn(bp[2 * q] + bv, bp[2 * q + 1] + bv);
                *(uint4*)&Ob[(size_t)(ot * 16 + r) * TV] = *(uint4*)h;
                __syncwarp();
            }
        }
    }
}

// ---------------- K5: pointwise convs via wmma; 2 column tiles ----------------
__global__ void __launch_bounds__(256)
k_pw_wmma(const float* __restrict__ xglob, const float* __restrict__ bias,
          const float* __restrict__ bn_s, const float* __restrict__ bn_b,
          float* __restrict__ outbuf) {
    extern __shared__ char smc[];
    __half* Wsm = (__half*)smc;                         // 18432 B
    float*  buf = (float*)(smc + 96 * 96 * 2);          // 14336 B

    int ct = blockIdx.x;      // 0..24
    int n  = blockIdx.z;
    int tid = threadIdx.x;
    int wid = tid >> 5, lane = tid & 31;
    float* wbuf = buf + wid * 16 * BLD;

    for (int i = tid; i < 96 * 96 / 8; i += 256)
        *(uint4*)&Wsm[i * 8] = *(const uint4*)&g_pwh[i * 8];

    const __half* Yg = g_yh + (size_t)n * Cc * TV + (size_t)ct * 256 + wid * 16;
    wmma::fragment<wmma::matrix_b, 16, 16, 16, __half, wmma::row_major> b0[6], b1[6];
#pragma unroll
    for (int k = 0; k < 6; k++) {
        wmma::load_matrix_sync(b0[k], Yg + (size_t)k * 16 * TV, TV);
        wmma::load_matrix_sync(b1[k], Yg + 128 + (size_t)k * 16 * TV, TV);
    }
    __syncthreads();

    int r = lane >> 1, c0 = (lane & 1) * 8;
    int colg0 = ct * 256 + wid * 16 + c0;

#pragma unroll
    for (int op = 0; op < 3; op++) {
        wmma::fragment<wmma::accumulator, 16, 16, 16, float> d00, d01, d10, d11;
        wmma::fill_fragment(d00, 0.f);
        wmma::fill_fragment(d01, 0.f);
        wmma::fill_fragment(d10, 0.f);
        wmma::fill_fragment(d11, 0.f);
#pragma unroll
        for (int k = 0; k < 6; k++) {
            wmma::fragment<wmma::matrix_a, 16, 16, 16, __half, wmma::row_major> a0, a1;
            wmma::load_matrix_sync(a0, Wsm + (2 * op) * 16 * 96 + k * 16, 96);
            wmma::load_matrix_sync(a1, Wsm + (2 * op + 1) * 16 * 96 + k * 16, 96);
            wmma::mma_sync(d00, a0, b0[k], d00);
            wmma::mma_sync(d10, a0, b1[k], d10);
            wmma::mma_sync(d01, a1, b0[k], d01);
            wmma::mma_sync(d11, a1, b1[k], d11);
        }
#pragma unroll
        for (int e = 0; e < 4; e++) {
            wmma::fragment<wmma::accumulator, 16, 16, 16, float>& d =
                (e == 0) ? d00 : (e == 1) ? d10 : (e == 2) ? d01 : d11;
            int ot = 2 * op + (e >> 1);
            int colg = colg0 + (e & 1) * 128;
            wmma::store_matrix_sync(wbuf, d, BLD, wmma::mem_row_major);
            __syncwarp();
            int rg = ot * 16 + r;
            int br = rg / 24, bc = rg % 24;
            float bv = __ldg(&bias[rg]);
            float sc = __ldg(&bn_s[rg]), sh = __ldg(&bn_b[rg]);
            const float* bp = &wbuf[r * BLD + c0];
            float w[8];
#pragma unroll
            for (int j = 0; j < 8; j++) w[j] = (bp[j] + bv) * sc + sh;
            if (br < 3) {
                float* dst = (br == 0) ? g_H0 : (br == 1) ? g_H1 : g_H2;
                size_t hi = (size_t)(n * BCc + bc) * TV + colg;
                float4 q0 = {fmaxf(w[0],0.f), fmaxf(w[1],0.f), fmaxf(w[2],0.f), fmaxf(w[3],0.f)};
                float4 q1 = {fmaxf(w[4],0.f), fmaxf(w[5],0.f), fmaxf(w[6],0.f), fmaxf(w[7],0.f)};
                *(float4*)&dst[hi]     = q0;
                *(float4*)&dst[hi + 4] = q1;
            } else {
                size_t oi = ((size_t)n * OUTo + 72 + bc) * TV + colg;
                float4 r0 = *(const float4*)&xglob[oi];
                float4 r1 = *(const float4*)&xglob[oi + 4];
                float4 q0 = {fmaxf(w[0]+r0.x,0.f), fmaxf(w[1]+r0.y,0.f),
                             fmaxf(w[2]+r0.z,0.f), fmaxf(w[3]+r0.w,0.f)};
                float4 q1 = {fmaxf(w[4]+r1.x,0.f), fmaxf(w[5]+r1.y,0.f),
                             fmaxf(w[6]+r1.z,0.f), fmaxf(w[7]+r1.w,0.f)};
                *(float4*)&outbuf[oi]     = q0;
                *(float4*)&outbuf[oi + 4] = q1;
            }
            __syncwarp();
        }
    }
}

// ---------------- K4: y(fp16) = relu(bn(sum_s A_s @ x3_s) + x) -----------------
__global__ void k_y(const float* __restrict__ x, const float* __restrict__ gbn_s,
                    const float* __restrict__ gbn_b) {
    int no = blockIdx.x;
    int n = no / OUTo, o = no % OUTo;
    int tid = threadIdx.x;        // 128

    __shared__ __align__(16) float As[Ss * Vv * 28];
    __shared__ __align__(16) float Xs[Vv * 257 + 7];

    for (int i = tid; i < Ss * 625; i += 128) {
        int s = i / 625;
        int rem = i - s * 625;
        int u = rem / 25, v = rem - u * 25;
        As[(s * 25 + v) * 28 + u] =
            g_A[(((size_t)(n * Ss + s)) * OUTo + o) * 625 + rem];
    }
    for (int i = tid; i < Ss * Vv * 3; i += 128) {
        int sv = i / 3, pu = 25 + i % 3;
        As[sv * 28 + pu] = 0.f;
    }

    u64 acc2[13][2];
#pragma unroll
    for (int p = 0; p < 13; p++) { acc2[p][0] = 0ull; acc2[p][1] = 0ull; }

    int t0 = tid, t1 = tid + 128;
#pragma unroll
    for (int s = 0; s < Ss; s++) {
        __syncthreads();
        const __half* base = g_x3 + (((size_t)(n * Ss + s)) * OUTo + o) * TV;
        for (int l = tid * 8; l < TV; l += 1024) {
            uint4 w = *(const uint4*)&base[l];
            const __half2* hp = (const __half2*)&w;
            float2 f0 = __half22float2(hp[0]);
            float2 f1 = __half22float2(hp[1]);
            float2 f2 = __half22float2(hp[2]);
            float2 f3 = __half22float2(hp[3]);
            float4 q0 = {f0.x, f0.y, f1.x, f1.y};
            float4 q1 = {f2.x, f2.y, f3.x, f3.y};
            *(float4*)&Xs[l]     = q0;
            *(float4*)&Xs[l + 4] = q1;
        }
        __syncthreads();
        const float* A2 = As + s * Vv * 28;
#pragma unroll
        for (int v = 0; v < Vv; v++) {
            u64 xa = splat2(Xs[t0 * Vv + v]);
            u64 xb = splat2(Xs[t1 * Vv + v]);
            const float* ar = A2 + v * 28;
#pragma unroll
            for (int p = 0; p < 13; p++) {
                u64 ap = *(const u64*)&ar[2 * p];
                ffma2(acc2[p][0], ap, xa);
                ffma2(acc2[p][1], ap, xb);
            }
        }
    }

    float gs = __ldg(&gbn_s[o]), gb = __ldg(&gbn_b[o]);
    __syncthreads();
#pragma unroll
    for (int p = 0; p < 13; p++) {
        float lo0, hi0, lo1, hi1;
        unpack2(lo0, hi0, acc2[p][0]);
        unpack2(lo1, hi1, acc2[p][1]);
        int u = 2 * p;
        Xs[u * 257 + t0] = lo0 * gs + gb;
        Xs[u * 257 + t1] = lo1 * gs + gb;
        if (u + 1 < Vv) {
            Xs[(u + 1) * 257 + t0] = hi0 * gs + gb;
            Xs[(u + 1) * 257 + t1] = hi1 * gs + gb;
        }
    }
    __syncthreads();

    size_t obase = ((size_t)n * OUTo + o) * TV;
    const float* xo = x + obase;
    __half* yh = g_yh + obase;
    for (int l = tid * 4; l < TV; l += 512) {
        float4 r = *(const float4*)&xo[l];
        float rr[4] = {r.x, r.y, r.z, r.w};
        float w[4];
#pragma unroll
        for (int k = 0; k < 4; k++) {
            int idx = l + k;
            int tt = (int)(((unsigned)idx * 5243u) >> 17);
            int vv = idx - tt * 25;
            w[k] = fmaxf(Xs[vv * 257 + tt] + rr[k], 0.f);
        }
        __half2 h[2];
        h[0] = __floats2half2_rn(w[0], w[1]);
        h[1] = __floats2half2_rn(w[2], w[3]);
        *(uint2*)&yh[l] = *(uint2*)h;
    }
}

// ---------------- K6: dilated temporal convs ----------------------------------
__global__ void k_tc2(const float* __restrict__ tcw, const float* __restrict__ tcb,
                      const float* __restrict__ tcbn_s, const float* __restrict__ tcbn_b,
                      const float* __restrict__ x, float* __restrict__ out) {
    extern __shared__ float sm[];
    float* Hs = sm;              // 24*600
    float* ws = sm + 14400;      // 2880

    int br = blockIdx.z;
    int n  = blockIdx.y;
    int t0 = blockIdx.x * 16;
    int tid = threadIdx.x;

    for (int i = tid; i < BCc * BCc * 5; i += 640)
        ws[i] = tcw[br * BCc * BCc * 5 + i];

    const float* H = (br == 0 ? g_H0 : g_H1) + (size_t)n * BCc * TV;
    int base = (t0 - 4) * 25;
    for (int i = tid; i < 24 * 600; i += 640) {
        int ic = i / 600;
        int rem = i - ic * 600;
        int tg25 = base + rem;
        float val = 0.f;
        if (tg25 >= 0 && tg25 < TV) val = H[(size_t)ic * TV + tg25];
        Hs[i] = val;
    }
    __syncthreads();
    if (tid >= BCc * Vv) return;
    int oc = tid / Vv, v = tid - oc * Vv;

    float bias = __ldg(&tcb[br * BCc + oc]);
    float sc = __ldg(&tcbn_s[br * BCc + oc]), sh = __ldg(&tcbn_b[br * BCc + oc]);

    float acc[16];
#pragma unroll
    for (int j = 0; j < 16; j++) acc[j] = bias;

    for (int ic = 0; ic < BCc; ic++) {
        float h[24];
        const float* hp = Hs + ic * 600 + v;
#pragma unroll
        for (int i = 0; i < 24; i++) h[i] = hp[i * 25];
        const float* wp = ws + (oc * BCc + ic) * 5;
        if (br == 0) {
#pragma unroll
            for (int k = 0; k < 5; k++) {
                float wv = wp[k];
#pragma unroll
                for (int j = 0; j < 16; j++) acc[j] += wv * h[j + k + 2];
            }
        } else {
#pragma unroll
            for (int k = 0; k < 5; k++) {
                float wv = wp[k];
#pragma unroll
                for (int j = 0; j < 16; j++) acc[j] += wv * h[j + 2 * k];
            }
        }
    }

#pragma unroll
    for (int j = 0; j < 16; j++) {
        int tg = t0 + j;
        size_t oi = ((size_t)n * OUTo + br * BCc + oc) * TV + (size_t)tg * Vv + v;
        out[oi] = fmaxf(acc[j] * sc + sh + __ldg(&x[oi]), 0.f);
    }
}

// ---------------- K7: maxpool branch -----------------------------------------
__global__ void k_mp(const float* __restrict__ mpbn_s, const float* __restrict__ mpbn_b,
                     const float* __restrict__ x, float* __restrict__ out) {
    int idx = blockIdx.x * 256 + threadIdx.x;
    if (idx >= Nn * BCc * TV) return;
    int v = idx % Vv;
    int t = (idx / Vv) % Tt;
    int bc = (idx / TV) % BCc;
    int n = idx / (TV * BCc);
    const float* H = g_H2 + (size_t)(n * BCc + bc) * TV;
    float m = H[t * Vv + v];
    if (t > 0)   m = fmaxf(m, H[(t - 1) * Vv + v]);
    if (t < 255) m = fmaxf(m, H[(t + 1) * Vv + v]);
    float val = m * __ldg(&mpbn_s[bc]) + __ldg(&mpbn_b[bc]);
    size_t oi = ((size_t)n * OUTo + 48 + bc) * TV + (size_t)t * Vv + v;
    out[oi] = fmaxf(val + __ldg(&x[oi]), 0.f);
}

// ---------------- driver ------------------------------------------------------
#define GEMM0_SMEM (96*96*2 + 8*16*BLD*4)       // 32768
#define PW_SMEM    (96*96*2 + 8*16*BLD*4)       // 32768
#define TC_SMEM    ((24*600 + 24*24*5) * 4)

extern "C" void kernel_launch(void* const* d_in, const int* in_sizes, int n_in,
                              void* d_out, int out_size) {
    const float* x      = (const float*)d_in[0];
    const float* spd_A  = (const float*)d_in[1];
    const float* A3     = (const float*)d_in[2];
    const float* A6     = (const float*)d_in[3];
    const float* alpha  = (const float*)d_in[4];
    const float* beta   = (const float*)d_in[5];
    const float* gamma  = (const float*)d_in[6];
    const float* c1_w   = (const float*)d_in[7];
    const float* c1_b   = (const float*)d_in[8];
    const float* c2_w   = (const float*)d_in[9];
    const float* c2_b   = (const float*)d_in[10];
    const float* c4_w   = (const float*)d_in[11];
    const float* c4_b   = (const float*)d_in[12];
    const float* c3_w   = (const float*)d_in[13];
    const float* c3_b   = (const float*)d_in[14];
    const float* gbn_s  = (const float*)d_in[15];
    const float* gbn_b  = (const float*)d_in[16];
    const float* pw_w   = (const float*)d_in[17];
    const float* pw_b   = (const float*)d_in[18];
    const float* pwbn_s = (const float*)d_in[19];
    const float* pwbn_b = (const float*)d_in[20];
    const float* tc_w   = (const float*)d_in[21];
    const float* tc_b   = (const float*)d_in[22];
    const float* tcbn_s = (const float*)d_in[23];
    const float* tcbn_b = (const float*)d_in[24];
    const float* mpbn_s = (const float*)d_in[25];
    const float* mpbn_b = (const float*)d_in[26];
    float* out = (float*)d_out;

    cudaFuncSetAttribute(k_gemm0_wmma, cudaFuncAttributeMaxDynamicSharedMemorySize, GEMM0_SMEM);
    cudaFuncSetAttribute(k_pw_wmma,    cudaFuncAttributeMaxDynamicSharedMemorySize, PW_SMEM);
    cudaFuncSetAttribute(k_tc2,        cudaFuncAttributeMaxDynamicSharedMemorySize, TC_SMEM);

    k_xm<<<Nn * Cc + 8, 128>>>(x, c3_w, pw_w);                      // 1 (x prep + W prep)
    k_rel<<<Nn * Ss, 256>>>(spd_A, A3, A6, alpha, beta, gamma,
                            c1_w, c1_b, c2_w, c2_b, c4_w, c4_b);    // 2
    k_gemm0_wmma<<<dim3(25, 1, Nn), 256, GEMM0_SMEM>>>(c3_b);       // 3
    k_y<<<Nn * OUTo, 128>>>(x, gbn_s, gbn_b);                       // 4 <- profiled
    k_pw_wmma<<<dim3(25, 1, Nn), 256, PW_SMEM>>>(x, pw_b, pwbn_s, pwbn_b, out);
    k_tc2<<<dim3(16, Nn, 2), 640, TC_SMEM>>>(tc_w, tc_b, tcbn_s, tcbn_b, x, out);
    k_mp<<<(Nn * BCc * TV + 255) / 256, 256>>>(mpbn_s, mpbn_b, x, out);
}